// round 4
// baseline (speedup 1.0000x reference)
#include <cuda_runtime.h>

#define DIMV 768
#define NHEAD 16
#define PH 48
#define BATCH 4
#define TSEQ 2048
#define MTOT (BATCH * TSEQ)   // 8192
#define NQKV (3 * DIMV)       // 2304

typedef unsigned long long u64;

// Scratch (allocation-free rule: __device__ globals)
__device__ float g_qkv[MTOT * NQKV];   // (8192, 2304)
__device__ float g_att[MTOT * DIMV];   // (8192, 768)

// ---- packed f32x2 helpers (sm_100+ PTX; ptxas never auto-emits these) ----
__device__ __forceinline__ u64 pk2(float lo, float hi) {
    u64 r; asm("mov.b64 %0,{%1,%2};" : "=l"(r) : "f"(lo), "f"(hi)); return r;
}
__device__ __forceinline__ float2 upk2(u64 v) {
    float2 r; asm("mov.b64 {%0,%1},%2;" : "=f"(r.x), "=f"(r.y) : "l"(v)); return r;
}
__device__ __forceinline__ void fma2(u64& d, u64 a, u64 b) {
    asm("fma.rn.f32x2 %0,%1,%2,%0;" : "+l"(d) : "l"(a), "l"(b));
}
__device__ __forceinline__ void mul2(u64& d, u64 a, u64 b) {
    asm("mul.rn.f32x2 %0,%1,%2;" : "=l"(d) : "l"(a), "l"(b));
}

// ---------------------------------------------------------------------------
// Tiled fp32 GEMM with bias: C[M,N] = A[M,K] @ B[K,N] + bias[N]
// BM=BN=128, BK=16, 256 threads, 8x8 micro-tile, f32x2 packed math.
// ---------------------------------------------------------------------------
__global__ void __launch_bounds__(256) gemm_bias_kernel(
    const float* __restrict__ A, const float* __restrict__ B,
    const float* __restrict__ bias, float* __restrict__ C,
    int M, int N, int K)
{
    __shared__ float As[16][128];   // transposed A tile: As[k][m]
    __shared__ float Bs[16][128];   // Bs[k][n]

    const int tid = threadIdx.x;
    const int m0 = blockIdx.y * 128;
    const int n0 = blockIdx.x * 128;
    const int ty = tid >> 4;
    const int tx = tid & 15;

    const int arow = tid >> 1;
    const int ac  = (tid & 1) * 8;
    const int brow = tid >> 4;
    const int bc   = (tid & 15) * 8;

    const float* Aptr = A + (long)(m0 + arow) * K + ac;
    const float* Bptr = B + (long)brow * N + n0 + bc;

    u64 acc[8][4];
    #pragma unroll
    for (int i = 0; i < 8; i++)
        #pragma unroll
        for (int j = 0; j < 4; j++) acc[i][j] = 0ull;

    float4 a0 = *(const float4*)(Aptr + 0);
    float4 a1 = *(const float4*)(Aptr + 4);
    float4 b0 = *(const float4*)(Bptr + 0);
    float4 b1 = *(const float4*)(Bptr + 4);

    for (int k0 = 0; k0 < K; k0 += 16) {
        As[ac + 0][arow] = a0.x; As[ac + 1][arow] = a0.y;
        As[ac + 2][arow] = a0.z; As[ac + 3][arow] = a0.w;
        As[ac + 4][arow] = a1.x; As[ac + 5][arow] = a1.y;
        As[ac + 6][arow] = a1.z; As[ac + 7][arow] = a1.w;
        *(float4*)&Bs[brow][bc + 0] = b0;
        *(float4*)&Bs[brow][bc + 4] = b1;
        __syncthreads();

        if (k0 + 16 < K) {
            a0 = *(const float4*)(Aptr + (k0 + 16) + 0);
            a1 = *(const float4*)(Aptr + (k0 + 16) + 4);
            b0 = *(const float4*)(Bptr + (long)(k0 + 16) * N + 0);
            b1 = *(const float4*)(Bptr + (long)(k0 + 16) * N + 4);
        }

        #pragma unroll
        for (int k = 0; k < 16; k++) {
            ulonglong2 bv0 = *(const ulonglong2*)&Bs[k][tx * 8];
            ulonglong2 bv1 = *(const ulonglong2*)&Bs[k][tx * 8 + 4];
            u64 bb[4] = {bv0.x, bv0.y, bv1.x, bv1.y};
            float4 af0 = *(const float4*)&As[k][ty * 8];
            float4 af1 = *(const float4*)&As[k][ty * 8 + 4];
            float ar[8] = {af0.x, af0.y, af0.z, af0.w, af1.x, af1.y, af1.z, af1.w};
            #pragma unroll
            for (int i = 0; i < 8; i++) {
                u64 aa = pk2(ar[i], ar[i]);
                #pragma unroll
                for (int j = 0; j < 4; j++) fma2(acc[i][j], aa, bb[j]);
            }
        }
        __syncthreads();
    }

    const int col = n0 + tx * 8;
    float4 bbias0 = *(const float4*)&bias[col];
    float4 bbias1 = *(const float4*)&bias[col + 4];
    #pragma unroll
    for (int i = 0; i < 8; i++) {
        const int row = m0 + ty * 8 + i;
        float2 c0 = upk2(acc[i][0]);
        float2 c1 = upk2(acc[i][1]);
        float2 c2 = upk2(acc[i][2]);
        float2 c3 = upk2(acc[i][3]);
        float4 o0 = make_float4(c0.x + bbias0.x, c0.y + bbias0.y,
                                c1.x + bbias0.z, c1.y + bbias0.w);
        float4 o1 = make_float4(c2.x + bbias1.x, c2.y + bbias1.y,
                                c3.x + bbias1.z, c3.y + bbias1.w);
        *(float4*)&C[(long)row * N + col + 0] = o0;
        *(float4*)&C[(long)row * N + col + 4] = o1;
    }
}

// ---------------------------------------------------------------------------
// Flash attention: thread pair (t, t^1) splits headdim (24 dims each);
// each thread owns 2 queries. Block = 256 threads -> 256 queries.
// grid = (TSEQ/256, BATCH*NHEAD).
// ---------------------------------------------------------------------------
__global__ void __launch_bounds__(256) attn_kernel(
    const float* __restrict__ qkv, float* __restrict__ out)
{
    __shared__ float Ks[64][PH];
    __shared__ float Vs[64][PH];

    const int bh = blockIdx.y;
    const int b = bh / NHEAD;
    const int h = bh % NHEAD;
    const int tid = threadIdx.x;
    const int half = tid & 1;                    // d-half: 0 -> dims 0..23, 1 -> 24..47
    const int qslot = tid >> 1;                  // 0..127
    const int q0 = blockIdx.x * 256 + qslot * 2; // this thread: queries q0, q0+1
    const int dOff = half * 24;

    const float scale = 0.14433756729740643f;    // 1/sqrt(48)
    const long headCol = (long)h * (3 * PH);

    // q halves for 2 queries, pre-scaled, packed: 2 x 12 u64 (24 floats each)
    u64 q2[2][12];
    #pragma unroll
    for (int qi = 0; qi < 2; qi++) {
        const float* qptr = qkv + ((long)(b * TSEQ + q0 + qi)) * NQKV + headCol + dOff;
        #pragma unroll
        for (int c = 0; c < 6; c++) {
            float4 v = *(const float4*)&qptr[c * 4];
            q2[qi][2 * c + 0] = pk2(v.x * scale, v.y * scale);
            q2[qi][2 * c + 1] = pk2(v.z * scale, v.w * scale);
        }
    }

    u64 o2[2][12];
    #pragma unroll
    for (int qi = 0; qi < 2; qi++)
        #pragma unroll
        for (int c = 0; c < 12; c++) o2[qi][c] = 0ull;
    float m[2] = {-1e30f, -1e30f};
    float l[2] = {0.f, 0.f};

    for (int kb = 0; kb < TSEQ; kb += 64) {
        // cooperative K/V tile load: 64 rows x 12 float4 each, 256 threads
        for (int idx = tid; idx < 64 * 12; idx += 256) {
            const int r  = idx / 12;
            const int c4 = idx % 12;
            const float* src = qkv + ((long)(b * TSEQ + kb + r)) * NQKV + headCol;
            *(float4*)&Ks[r][c4 * 4] = *(const float4*)&src[PH + c4 * 4];
            *(float4*)&Vs[r][c4 * 4] = *(const float4*)&src[2 * PH + c4 * 4];
        }
        __syncthreads();

        #pragma unroll 1
        for (int j = 0; j < 64; j++) {
            // this thread's K half-row: 24 floats = 6 LDS.128 = 12 u64
            const ulonglong2* kr = (const ulonglong2*)&Ks[j][dOff];
            u64 kc[12];
            #pragma unroll
            for (int c = 0; c < 6; c++) {
                ulonglong2 t = kr[c];
                kc[2 * c + 0] = t.x;
                kc[2 * c + 1] = t.y;
            }

            float s[2];
            #pragma unroll
            for (int qi = 0; qi < 2; qi++) {
                u64 a0 = 0ull, a1 = 0ull;
                #pragma unroll
                for (int c = 0; c < 6; c++) {
                    fma2(a0, q2[qi][2 * c + 0], kc[2 * c + 0]);
                    fma2(a1, q2[qi][2 * c + 1], kc[2 * c + 1]);
                }
                float2 p0 = upk2(a0);
                float2 p1 = upk2(a1);
                s[qi] = (p0.x + p0.y) + (p1.x + p1.y);
            }
            // combine the two d-halves (partner lane = tid^1)
            s[0] += __shfl_xor_sync(0xffffffffu, s[0], 1);
            s[1] += __shfl_xor_sync(0xffffffffu, s[1], 1);

            // V half-row (reuse pattern)
            const ulonglong2* vr = (const ulonglong2*)&Vs[j][dOff];
            u64 vc[12];
            #pragma unroll
            for (int c = 0; c < 6; c++) {
                ulonglong2 t = vr[c];
                vc[2 * c + 0] = t.x;
                vc[2 * c + 1] = t.y;
            }

            #pragma unroll
            for (int qi = 0; qi < 2; qi++) {
                float sv = s[qi];
                if (sv > m[qi]) {                 // lazy rescale (rare)
                    float corr = __expf(m[qi] - sv);
                    m[qi] = sv;
                    l[qi] *= corr;
                    u64 corr2 = pk2(corr, corr);
                    #pragma unroll
                    for (int c = 0; c < 12; c++) mul2(o2[qi][c], o2[qi][c], corr2);
                }
                float p = __expf(sv - m[qi]);
                l[qi] += p;
                u64 p2 = pk2(p, p);
                #pragma unroll
                for (int c = 0; c < 12; c++) fma2(o2[qi][c], p2, vc[c]);
            }
        }
        __syncthreads();
    }

    // write both query halves: 24 floats each at (row, h*48 + dOff)
    #pragma unroll
    for (int qi = 0; qi < 2; qi++) {
        const float inv_l = 1.0f / l[qi];
        float* optr = out + ((long)(b * TSEQ + q0 + qi)) * DIMV + (long)h * PH + dOff;
        #pragma unroll
        for (int c = 0; c < 6; c++) {
            float2 lo = upk2(o2[qi][2 * c + 0]);
            float2 hi = upk2(o2[qi][2 * c + 1]);
            float4 v = make_float4(lo.x * inv_l, lo.y * inv_l,
                                   hi.x * inv_l, hi.y * inv_l);
            *(float4*)&optr[c * 4] = v;
        }
    }
}

// ---------------------------------------------------------------------------
extern "C" void kernel_launch(void* const* d_in, const int* in_sizes, int n_in,
                              void* d_out, int out_size)
{
    const float* x     = (const float*)d_in[0];
    const float* w_in  = (const float*)d_in[1];
    const float* b_in  = (const float*)d_in[2];
    const float* w_out = (const float*)d_in[3];
    const float* b_out = (const float*)d_in[4];
    float* out = (float*)d_out;

    float* qkv = nullptr;
    float* att = nullptr;
    cudaGetSymbolAddress((void**)&qkv, g_qkv);
    cudaGetSymbolAddress((void**)&att, g_att);

    // 1) QKV projection: (8192,768) @ (768,2304) + b_in
    {
        dim3 grid(NQKV / 128, MTOT / 128);
        gemm_bias_kernel<<<grid, 256>>>(x, w_in, b_in, qkv, MTOT, NQKV, DIMV);
    }

    // 2) Attention
    {
        dim3 grid(TSEQ / 256, BATCH * NHEAD);
        attn_kernel<<<grid, 256>>>(qkv, att);
    }

    // 3) Output projection: (8192,768) @ (768,768) + b_out
    {
        dim3 grid(DIMV / 128, MTOT / 128);
        gemm_bias_kernel<<<grid, 256>>>(att, w_out, b_out, out, MTOT, DIMV, DIMV);
    }
}

// round 5
// speedup vs baseline: 1.0972x; 1.0972x over previous
#include <cuda_runtime.h>

#define DIMV 768
#define NHEAD 16
#define PH 48
#define BATCH 4
#define TSEQ 2048
#define MTOT (BATCH * TSEQ)   // 8192
#define NQKV (3 * DIMV)       // 2304

typedef unsigned long long u64;

// Scratch (allocation-free rule: __device__ globals)
__device__ float g_qkv[MTOT * NQKV];   // (8192, 2304)
__device__ float g_att[MTOT * DIMV];   // (8192, 768)

// ---- packed f32x2 helpers (sm_100+ PTX; ptxas never auto-emits these) ----
__device__ __forceinline__ u64 pk2(float lo, float hi) {
    u64 r; asm("mov.b64 %0,{%1,%2};" : "=l"(r) : "f"(lo), "f"(hi)); return r;
}
__device__ __forceinline__ float2 upk2(u64 v) {
    float2 r; asm("mov.b64 {%0,%1},%2;" : "=f"(r.x), "=f"(r.y) : "l"(v)); return r;
}
__device__ __forceinline__ void fma2(u64& d, u64 a, u64 b) {
    asm("fma.rn.f32x2 %0,%1,%2,%0;" : "+l"(d) : "l"(a), "l"(b));
}
__device__ __forceinline__ void mul2(u64& d, u64 a, u64 b) {
    asm("mul.rn.f32x2 %0,%1,%2;" : "=l"(d) : "l"(a), "l"(b));
}

// ---------------------------------------------------------------------------
// Tiled fp32 GEMM with bias: C[M,N] = A[M,K] @ B[K,N] + bias[N]
// BM=BN=128, BK=16, 256 threads, 8x8 micro-tile, f32x2 packed math.
// ---------------------------------------------------------------------------
__global__ void __launch_bounds__(256, 2) gemm_bias_kernel(
    const float* __restrict__ A, const float* __restrict__ B,
    const float* __restrict__ bias, float* __restrict__ C,
    int M, int N, int K)
{
    __shared__ float As[16][128];   // transposed A tile: As[k][m]
    __shared__ float Bs[16][128];   // Bs[k][n]

    const int tid = threadIdx.x;
    const int m0 = blockIdx.y * 128;
    const int n0 = blockIdx.x * 128;
    const int ty = tid >> 4;
    const int tx = tid & 15;

    const int arow = tid >> 1;
    const int ac  = (tid & 1) * 8;
    const int brow = tid >> 4;
    const int bc   = (tid & 15) * 8;

    const float* Aptr = A + (long)(m0 + arow) * K + ac;
    const float* Bptr = B + (long)brow * N + n0 + bc;

    u64 acc[8][4];
    #pragma unroll
    for (int i = 0; i < 8; i++)
        #pragma unroll
        for (int j = 0; j < 4; j++) acc[i][j] = 0ull;

    float4 a0 = *(const float4*)(Aptr + 0);
    float4 a1 = *(const float4*)(Aptr + 4);
    float4 b0 = *(const float4*)(Bptr + 0);
    float4 b1 = *(const float4*)(Bptr + 4);

    for (int k0 = 0; k0 < K; k0 += 16) {
        As[ac + 0][arow] = a0.x; As[ac + 1][arow] = a0.y;
        As[ac + 2][arow] = a0.z; As[ac + 3][arow] = a0.w;
        As[ac + 4][arow] = a1.x; As[ac + 5][arow] = a1.y;
        As[ac + 6][arow] = a1.z; As[ac + 7][arow] = a1.w;
        *(float4*)&Bs[brow][bc + 0] = b0;
        *(float4*)&Bs[brow][bc + 4] = b1;
        __syncthreads();

        if (k0 + 16 < K) {
            a0 = *(const float4*)(Aptr + (k0 + 16) + 0);
            a1 = *(const float4*)(Aptr + (k0 + 16) + 4);
            b0 = *(const float4*)(Bptr + (long)(k0 + 16) * N + 0);
            b1 = *(const float4*)(Bptr + (long)(k0 + 16) * N + 4);
        }

        #pragma unroll
        for (int k = 0; k < 16; k++) {
            ulonglong2 bv0 = *(const ulonglong2*)&Bs[k][tx * 8];
            ulonglong2 bv1 = *(const ulonglong2*)&Bs[k][tx * 8 + 4];
            u64 bb[4] = {bv0.x, bv0.y, bv1.x, bv1.y};
            float4 af0 = *(const float4*)&As[k][ty * 8];
            float4 af1 = *(const float4*)&As[k][ty * 8 + 4];
            float ar[8] = {af0.x, af0.y, af0.z, af0.w, af1.x, af1.y, af1.z, af1.w};
            #pragma unroll
            for (int i = 0; i < 8; i++) {
                u64 aa = pk2(ar[i], ar[i]);
                #pragma unroll
                for (int j = 0; j < 4; j++) fma2(acc[i][j], aa, bb[j]);
            }
        }
        __syncthreads();
    }

    const int col = n0 + tx * 8;
    float4 bbias0 = *(const float4*)&bias[col];
    float4 bbias1 = *(const float4*)&bias[col + 4];
    #pragma unroll
    for (int i = 0; i < 8; i++) {
        const int row = m0 + ty * 8 + i;
        float2 c0 = upk2(acc[i][0]);
        float2 c1 = upk2(acc[i][1]);
        float2 c2 = upk2(acc[i][2]);
        float2 c3 = upk2(acc[i][3]);
        float4 o0 = make_float4(c0.x + bbias0.x, c0.y + bbias0.y,
                                c1.x + bbias0.z, c1.y + bbias0.w);
        float4 o1 = make_float4(c2.x + bbias1.x, c2.y + bbias1.y,
                                c3.x + bbias1.z, c3.y + bbias1.w);
        *(float4*)&C[(long)row * N + col + 0] = o0;
        *(float4*)&C[(long)row * N + col + 4] = o1;
    }
}

// ---------------------------------------------------------------------------
// Flash attention: lane pair (t, t^1) splits headdim (24 dims each);
// each thread owns 2 queries. Block = 128 threads -> 128 queries.
// K/V chunks are streamed straight from LDS into FMAs (no staging arrays).
// grid = (TSEQ/128, BATCH*NHEAD).
// ---------------------------------------------------------------------------
__global__ void __launch_bounds__(128, 3) attn_kernel(
    const float* __restrict__ qkv, float* __restrict__ out)
{
    __shared__ float Ks[64][PH];
    __shared__ float Vs[64][PH];

    const int bh = blockIdx.y;
    const int b = bh / NHEAD;
    const int h = bh % NHEAD;
    const int tid = threadIdx.x;
    const int half = tid & 1;                    // d-half: 0 -> dims 0..23, 1 -> 24..47
    const int qslot = tid >> 1;                  // 0..63
    const int q0 = blockIdx.x * 128 + qslot * 2; // this thread: queries q0, q0+1
    const int dOff = half * 24;

    const float scale = 0.14433756729740643f;    // 1/sqrt(48)
    const long headCol = (long)h * (3 * PH);

    // q halves for 2 queries, pre-scaled, packed: 2 x 12 u64 (24 floats each)
    u64 q2[2][12];
    #pragma unroll
    for (int qi = 0; qi < 2; qi++) {
        const float* qptr = qkv + ((long)(b * TSEQ + q0 + qi)) * NQKV + headCol + dOff;
        #pragma unroll
        for (int c = 0; c < 6; c++) {
            float4 v = *(const float4*)&qptr[c * 4];
            q2[qi][2 * c + 0] = pk2(v.x * scale, v.y * scale);
            q2[qi][2 * c + 1] = pk2(v.z * scale, v.w * scale);
        }
    }

    u64 o2[2][12];
    #pragma unroll
    for (int qi = 0; qi < 2; qi++)
        #pragma unroll
        for (int c = 0; c < 12; c++) o2[qi][c] = 0ull;
    float m0v = -1e30f, m1v = -1e30f;
    float l0 = 0.f, l1 = 0.f;

    for (int kb = 0; kb < TSEQ; kb += 64) {
        // cooperative K/V tile load: 64 rows x 12 float4 each, 128 threads
        for (int idx = tid; idx < 64 * 12; idx += 128) {
            const int r  = idx / 12;
            const int c4 = idx % 12;
            const float* src = qkv + ((long)(b * TSEQ + kb + r)) * NQKV + headCol;
            *(float4*)&Ks[r][c4 * 4] = *(const float4*)&src[PH + c4 * 4];
            *(float4*)&Vs[r][c4 * 4] = *(const float4*)&src[2 * PH + c4 * 4];
        }
        __syncthreads();

        #pragma unroll 1
        for (int j = 0; j < 64; j++) {
            // K half-row streamed: 6 LDS.128, each chunk feeds both queries
            const ulonglong2* kr = (const ulonglong2*)&Ks[j][dOff];
            u64 a00 = 0ull, a01 = 0ull, a10 = 0ull, a11 = 0ull;
            #pragma unroll
            for (int c = 0; c < 6; c++) {
                ulonglong2 t = kr[c];
                fma2(a00, q2[0][2 * c + 0], t.x);
                fma2(a01, q2[0][2 * c + 1], t.y);
                fma2(a10, q2[1][2 * c + 0], t.x);
                fma2(a11, q2[1][2 * c + 1], t.y);
            }
            float2 p00 = upk2(a00), p01 = upk2(a01);
            float2 p10 = upk2(a10), p11 = upk2(a11);
            float s0 = (p00.x + p00.y) + (p01.x + p01.y);
            float s1 = (p10.x + p10.y) + (p11.x + p11.y);
            // combine the two d-halves (partner lane = tid^1)
            s0 += __shfl_xor_sync(0xffffffffu, s0, 1);
            s1 += __shfl_xor_sync(0xffffffffu, s1, 1);

            if (s0 > m0v) {                       // lazy rescale (rare)
                float corr = __expf(m0v - s0);
                m0v = s0; l0 *= corr;
                u64 c2v = pk2(corr, corr);
                #pragma unroll
                for (int c = 0; c < 12; c++) mul2(o2[0][c], o2[0][c], c2v);
            }
            if (s1 > m1v) {
                float corr = __expf(m1v - s1);
                m1v = s1; l1 *= corr;
                u64 c2v = pk2(corr, corr);
                #pragma unroll
                for (int c = 0; c < 12; c++) mul2(o2[1][c], o2[1][c], c2v);
            }
            float pe0 = __expf(s0 - m0v);
            float pe1 = __expf(s1 - m1v);
            l0 += pe0; l1 += pe1;
            u64 pp0 = pk2(pe0, pe0);
            u64 pp1 = pk2(pe1, pe1);

            // V half-row streamed: 6 LDS.128, each chunk feeds both queries
            const ulonglong2* vr = (const ulonglong2*)&Vs[j][dOff];
            #pragma unroll
            for (int c = 0; c < 6; c++) {
                ulonglong2 t = vr[c];
                fma2(o2[0][2 * c + 0], pp0, t.x);
                fma2(o2[0][2 * c + 1], pp0, t.y);
                fma2(o2[1][2 * c + 0], pp1, t.x);
                fma2(o2[1][2 * c + 1], pp1, t.y);
            }
        }
        __syncthreads();
    }

    // write both query halves: 24 floats each at (row, h*48 + dOff)
    {
        const float inv_l0 = 1.0f / l0;
        float* optr = out + ((long)(b * TSEQ + q0)) * DIMV + (long)h * PH + dOff;
        #pragma unroll
        for (int c = 0; c < 6; c++) {
            float2 lo = upk2(o2[0][2 * c + 0]);
            float2 hi = upk2(o2[0][2 * c + 1]);
            *(float4*)&optr[c * 4] = make_float4(lo.x * inv_l0, lo.y * inv_l0,
                                                 hi.x * inv_l0, hi.y * inv_l0);
        }
    }
    {
        const float inv_l1 = 1.0f / l1;
        float* optr = out + ((long)(b * TSEQ + q0 + 1)) * DIMV + (long)h * PH + dOff;
        #pragma unroll
        for (int c = 0; c < 6; c++) {
            float2 lo = upk2(o2[1][2 * c + 0]);
            float2 hi = upk2(o2[1][2 * c + 1]);
            *(float4*)&optr[c * 4] = make_float4(lo.x * inv_l1, lo.y * inv_l1,
                                                 hi.x * inv_l1, hi.y * inv_l1);
        }
    }
}

// ---------------------------------------------------------------------------
extern "C" void kernel_launch(void* const* d_in, const int* in_sizes, int n_in,
                              void* d_out, int out_size)
{
    const float* x     = (const float*)d_in[0];
    const float* w_in  = (const float*)d_in[1];
    const float* b_in  = (const float*)d_in[2];
    const float* w_out = (const float*)d_in[3];
    const float* b_out = (const float*)d_in[4];
    float* out = (float*)d_out;

    float* qkv = nullptr;
    float* att = nullptr;
    cudaGetSymbolAddress((void**)&qkv, g_qkv);
    cudaGetSymbolAddress((void**)&att, g_att);

    // 1) QKV projection: (8192,768) @ (768,2304) + b_in
    {
        dim3 grid(NQKV / 128, MTOT / 128);
        gemm_bias_kernel<<<grid, 256>>>(x, w_in, b_in, qkv, MTOT, NQKV, DIMV);
    }

    // 2) Attention
    {
        dim3 grid(TSEQ / 128, BATCH * NHEAD);
        attn_kernel<<<grid, 128>>>(qkv, att);
    }

    // 3) Output projection: (8192,768) @ (768,768) + b_out
    {
        dim3 grid(DIMV / 128, MTOT / 128);
        gemm_bias_kernel<<<grid, 256>>>(att, w_out, b_out, out, MTOT, DIMV, DIMV);
    }
}

// round 6
// speedup vs baseline: 2.0353x; 1.8551x over previous
#include <cuda_runtime.h>
#include <cuda_bf16.h>
#include <cstdint>

#define DIMV 768
#define NHEAD 16
#define PH 48
#define BATCH 4
#define TSEQ 2048
#define MTOT (BATCH * TSEQ)   // 8192
#define NQKV (3 * DIMV)       // 2304
#define SCALE 0.14433756729740643f   // 1/sqrt(48)

typedef unsigned long long u64;

// Scratch (allocation-free rule: __device__ globals)
__device__ float g_qkv[MTOT * NQKV];            // (8192, 2304)
__device__ float g_att[MTOT * DIMV];            // (8192, 768)
__device__ __nv_bfloat16 g_Qh[MTOT * DIMV];     // q*scale hi
__device__ __nv_bfloat16 g_Ql[MTOT * DIMV];     // q*scale lo
__device__ __nv_bfloat16 g_Kh[MTOT * DIMV];
__device__ __nv_bfloat16 g_Kl[MTOT * DIMV];
__device__ __nv_bfloat16 g_Vth[64 * PH * TSEQ]; // V transposed: [bh][d][t]
__device__ __nv_bfloat16 g_Vtl[64 * PH * TSEQ];

// ---- packed f32x2 helpers ----
__device__ __forceinline__ u64 pk2(float lo, float hi) {
    u64 r; asm("mov.b64 %0,{%1,%2};" : "=l"(r) : "f"(lo), "f"(hi)); return r;
}
__device__ __forceinline__ float2 upk2(u64 v) {
    float2 r; asm("mov.b64 {%0,%1},%2;" : "=f"(r.x), "=f"(r.y) : "l"(v)); return r;
}
__device__ __forceinline__ void fma2(u64& d, u64 a, u64 b) {
    asm("fma.rn.f32x2 %0,%1,%2,%0;" : "+l"(d) : "l"(a), "l"(b));
}

// ---- bf16 pack/unpack ----
// cvt2: pack (lo,hi) floats -> bf16x2 reg with lo in low half
__device__ __forceinline__ uint32_t cvt2(float lo, float hi) {
    uint32_t r;
    asm("cvt.rn.bf16x2.f32 %0, %1, %2;" : "=r"(r) : "f"(hi), "f"(lo));
    return r;
}
__device__ __forceinline__ float lo16f(uint32_t v) { return __uint_as_float(v << 16); }
__device__ __forceinline__ float hi16f(uint32_t v) { return __uint_as_float(v & 0xffff0000u); }

// ---- bf16 m16n8k16 mma ----
__device__ __forceinline__ void mma16816(float* c, uint32_t a0, uint32_t a1,
                                         uint32_t a2, uint32_t a3,
                                         uint32_t b0, uint32_t b1) {
    asm volatile(
        "mma.sync.aligned.m16n8k16.row.col.f32.bf16.bf16.f32 "
        "{%0,%1,%2,%3},{%4,%5,%6,%7},{%8,%9},{%0,%1,%2,%3};"
        : "+f"(c[0]), "+f"(c[1]), "+f"(c[2]), "+f"(c[3])
        : "r"(a0), "r"(a1), "r"(a2), "r"(a3), "r"(b0), "r"(b1));
}

// ---------------------------------------------------------------------------
// Tiled fp32 GEMM with bias (unchanged from R3 best)
// ---------------------------------------------------------------------------
__global__ void __launch_bounds__(256, 2) gemm_bias_kernel(
    const float* __restrict__ A, const float* __restrict__ B,
    const float* __restrict__ bias, float* __restrict__ C,
    int M, int N, int K)
{
    __shared__ float As[16][128];
    __shared__ float Bs[16][128];

    const int tid = threadIdx.x;
    const int m0 = blockIdx.y * 128;
    const int n0 = blockIdx.x * 128;
    const int ty = tid >> 4;
    const int tx = tid & 15;

    const int arow = tid >> 1;
    const int ac  = (tid & 1) * 8;
    const int brow = tid >> 4;
    const int bc   = (tid & 15) * 8;

    const float* Aptr = A + (long)(m0 + arow) * K + ac;
    const float* Bptr = B + (long)brow * N + n0 + bc;

    u64 acc[8][4];
    #pragma unroll
    for (int i = 0; i < 8; i++)
        #pragma unroll
        for (int j = 0; j < 4; j++) acc[i][j] = 0ull;

    float4 a0 = *(const float4*)(Aptr + 0);
    float4 a1 = *(const float4*)(Aptr + 4);
    float4 b0 = *(const float4*)(Bptr + 0);
    float4 b1 = *(const float4*)(Bptr + 4);

    for (int k0 = 0; k0 < K; k0 += 16) {
        As[ac + 0][arow] = a0.x; As[ac + 1][arow] = a0.y;
        As[ac + 2][arow] = a0.z; As[ac + 3][arow] = a0.w;
        As[ac + 4][arow] = a1.x; As[ac + 5][arow] = a1.y;
        As[ac + 6][arow] = a1.z; As[ac + 7][arow] = a1.w;
        *(float4*)&Bs[brow][bc + 0] = b0;
        *(float4*)&Bs[brow][bc + 4] = b1;
        __syncthreads();

        if (k0 + 16 < K) {
            a0 = *(const float4*)(Aptr + (k0 + 16) + 0);
            a1 = *(const float4*)(Aptr + (k0 + 16) + 4);
            b0 = *(const float4*)(Bptr + (long)(k0 + 16) * N + 0);
            b1 = *(const float4*)(Bptr + (long)(k0 + 16) * N + 4);
        }

        #pragma unroll
        for (int k = 0; k < 16; k++) {
            ulonglong2 bv0 = *(const ulonglong2*)&Bs[k][tx * 8];
            ulonglong2 bv1 = *(const ulonglong2*)&Bs[k][tx * 8 + 4];
            u64 bb[4] = {bv0.x, bv0.y, bv1.x, bv1.y};
            float4 af0 = *(const float4*)&As[k][ty * 8];
            float4 af1 = *(const float4*)&As[k][ty * 8 + 4];
            float ar[8] = {af0.x, af0.y, af0.z, af0.w, af1.x, af1.y, af1.z, af1.w};
            #pragma unroll
            for (int i = 0; i < 8; i++) {
                u64 aa = pk2(ar[i], ar[i]);
                #pragma unroll
                for (int j = 0; j < 4; j++) fma2(acc[i][j], aa, bb[j]);
            }
        }
        __syncthreads();
    }

    const int col = n0 + tx * 8;
    float4 bbias0 = *(const float4*)&bias[col];
    float4 bbias1 = *(const float4*)&bias[col + 4];
    #pragma unroll
    for (int i = 0; i < 8; i++) {
        const int row = m0 + ty * 8 + i;
        float2 c0 = upk2(acc[i][0]);
        float2 c1 = upk2(acc[i][1]);
        float2 c2 = upk2(acc[i][2]);
        float2 c3 = upk2(acc[i][3]);
        float4 o0 = make_float4(c0.x + bbias0.x, c0.y + bbias0.y,
                                c1.x + bbias0.z, c1.y + bbias0.w);
        float4 o1 = make_float4(c2.x + bbias1.x, c2.y + bbias1.y,
                                c3.x + bbias1.z, c3.y + bbias1.w);
        *(float4*)&C[(long)row * N + col + 0] = o0;
        *(float4*)&C[(long)row * N + col + 4] = o1;
    }
}

// ---------------------------------------------------------------------------
// Convert A: split Q (pre-scaled) and K into bf16 hi/lo, layout [row][h*48+d]
// ---------------------------------------------------------------------------
__global__ void __launch_bounds__(256) convert_qk_kernel()
{
    const int idx = blockIdx.x * 256 + threadIdx.x;   // over MTOT*DIMV
    const int row = idx / DIMV;
    const int c   = idx - row * DIMV;
    const int h   = c / PH;
    const int d   = c - h * PH;
    const long base = (long)row * NQKV + h * (3 * PH) + d;

    float q = g_qkv[base] * SCALE;
    float k = g_qkv[base + PH];

    __nv_bfloat16 qh = __float2bfloat16(q);
    g_Qh[idx] = qh;
    g_Ql[idx] = __float2bfloat16(q - __bfloat162float(qh));
    __nv_bfloat16 kh = __float2bfloat16(k);
    g_Kh[idx] = kh;
    g_Kl[idx] = __float2bfloat16(k - __bfloat162float(kh));
}

// ---------------------------------------------------------------------------
// Convert B: V -> transposed bf16 hi/lo: g_Vt*[bh][d][t]
// grid (TSEQ/64, 64), block 256
// ---------------------------------------------------------------------------
__global__ void __launch_bounds__(256) convert_v_kernel()
{
    __shared__ float sv[PH][65];

    const int tb = blockIdx.x;
    const int bh = blockIdx.y;
    const int b = bh >> 4;
    const int h = bh & 15;
    const int tid = threadIdx.x;

    // read 64 t-rows x 48 dims (coalesced per row)
    const int tl = tid >> 2;           // 0..63
    const int dp = (tid & 3) * 12;     // 0,12,24,36
    const long rbase = (long)(b * TSEQ + tb * 64 + tl) * NQKV + h * (3 * PH) + 2 * PH + dp;
    #pragma unroll
    for (int j = 0; j < 12; j++)
        sv[dp + j][tl] = g_qkv[rbase + j];
    __syncthreads();

    // write transposed, packed pairs of keys
    uint32_t* Vh32 = (uint32_t*)g_Vth;
    uint32_t* Vl32 = (uint32_t*)g_Vtl;
    const long obase = ((long)bh * PH * TSEQ) / 2;     // in u32 units
    #pragma unroll
    for (int i = 0; i < 6; i++) {
        int tau = tid + 256 * i;       // < 1536
        int d = tau >> 5;
        int j = tau & 31;
        float x0 = sv[d][2 * j];
        float x1 = sv[d][2 * j + 1];
        uint32_t whi = cvt2(x0, x1);
        float r0 = x0 - lo16f(whi);
        float r1 = x1 - hi16f(whi);
        uint32_t wlo = cvt2(r0, r1);
        long o = obase + (long)d * (TSEQ / 2) + tb * 32 + j;
        Vh32[o] = whi;
        Vl32[o] = wlo;
    }
}

// ---------------------------------------------------------------------------
// Flash attention with mma.sync bf16 x3-split.
// grid (TSEQ/128, 64), block 256 (8 warps, 16 query rows each).
// ---------------------------------------------------------------------------
__global__ void __launch_bounds__(256, 2) attn_mma_kernel()
{
    __shared__ __align__(16) __nv_bfloat16 sK[2][64][56];  // [hi/lo][key][dim]
    __shared__ __align__(16) __nv_bfloat16 sV[2][48][72];  // [hi/lo][dim][key]

    const int tid = threadIdx.x;
    const int wid = tid >> 5;
    const int lane = tid & 31;
    const int g = lane >> 2;          // 0..7
    const int t4 = lane & 3;          // 0..3

    const int bh = blockIdx.y;
    const int b = bh >> 4;
    const int h = bh & 15;
    const int qr0 = blockIdx.x * 128 + wid * 16;
    const long rowg  = (long)b * TSEQ + qr0 + g;
    const long rowg8 = rowg + 8;

    // ---- load Q fragments (held all kernel) ----
    const uint32_t* Qh32 = (const uint32_t*)g_Qh;
    const uint32_t* Ql32 = (const uint32_t*)g_Ql;
    uint32_t qh[3][4], ql[3][4];
    #pragma unroll
    for (int kk = 0; kk < 3; kk++) {
        long o0 = rowg  * 384 + h * 24 + kk * 8 + t4;
        long o1 = rowg8 * 384 + h * 24 + kk * 8 + t4;
        qh[kk][0] = Qh32[o0];     qh[kk][1] = Qh32[o1];
        qh[kk][2] = Qh32[o0 + 4]; qh[kk][3] = Qh32[o1 + 4];
        ql[kk][0] = Ql32[o0];     ql[kk][1] = Ql32[o1];
        ql[kk][2] = Ql32[o0 + 4]; ql[kk][3] = Ql32[o1 + 4];
    }

    float O[6][4];
    #pragma unroll
    for (int i = 0; i < 6; i++)
        #pragma unroll
        for (int j = 0; j < 4; j++) O[i][j] = 0.f;
    float m0 = -1e30f, m1 = -1e30f, l0 = 0.f, l1 = 0.f;

    for (int kb = 0; kb < TSEQ; kb += 64) {
        // ---- cooperative tile loads ----
        #pragma unroll
        for (int i = 0; i < 3; i++) {
            int tau = tid + 256 * i;       // < 768
            int arr = tau / 384;
            int rem = tau - arr * 384;
            int key = rem / 6;
            int c = rem - key * 6;
            const __nv_bfloat16* src = arr ? g_Kl : g_Kh;
            float4 v = *(const float4*)&src[(long)(b * TSEQ + kb + key) * DIMV + h * PH + c * 8];
            *(float4*)&sK[arr][key][c * 8] = v;
        }
        #pragma unroll
        for (int i = 0; i < 3; i++) {
            int tau = tid + 256 * i;
            int arr = tau / 384;
            int rem = tau - arr * 384;
            int d = rem >> 3;
            int c = rem & 7;
            const __nv_bfloat16* src = arr ? g_Vtl : g_Vth;
            float4 v = *(const float4*)&src[(long)bh * (PH * TSEQ) + d * TSEQ + kb + c * 8];
            *(float4*)&sV[arr][d][c * 8] = v;
        }
        __syncthreads();

        // ---- S = Q K^T (x3 split passes into same accumulators) ----
        float S[8][4];
        #pragma unroll
        for (int n = 0; n < 8; n++)
            #pragma unroll
            for (int j = 0; j < 4; j++) S[n][j] = 0.f;

        #pragma unroll
        for (int kk = 0; kk < 3; kk++) {
            #pragma unroll
            for (int n = 0; n < 8; n++) {
                const uint32_t* kh = (const uint32_t*)&sK[0][n * 8 + g][kk * 16 + 2 * t4];
                const uint32_t* kl = (const uint32_t*)&sK[1][n * 8 + g][kk * 16 + 2 * t4];
                uint32_t bh0 = kh[0], bh1 = kh[4];
                mma16816(S[n], qh[kk][0], qh[kk][1], qh[kk][2], qh[kk][3], bh0, bh1);
                mma16816(S[n], ql[kk][0], ql[kk][1], ql[kk][2], ql[kk][3], bh0, bh1);
                mma16816(S[n], qh[kk][0], qh[kk][1], qh[kk][2], qh[kk][3], kl[0], kl[4]);
            }
        }

        // ---- online softmax (tile-batched) ----
        float rmax0 = -1e30f, rmax1 = -1e30f;
        #pragma unroll
        for (int n = 0; n < 8; n++) {
            rmax0 = fmaxf(rmax0, fmaxf(S[n][0], S[n][1]));
            rmax1 = fmaxf(rmax1, fmaxf(S[n][2], S[n][3]));
        }
        rmax0 = fmaxf(rmax0, __shfl_xor_sync(0xffffffffu, rmax0, 1));
        rmax0 = fmaxf(rmax0, __shfl_xor_sync(0xffffffffu, rmax0, 2));
        rmax1 = fmaxf(rmax1, __shfl_xor_sync(0xffffffffu, rmax1, 1));
        rmax1 = fmaxf(rmax1, __shfl_xor_sync(0xffffffffu, rmax1, 2));

        float mn0 = fmaxf(m0, rmax0);
        float mn1 = fmaxf(m1, rmax1);
        float corr0 = __expf(m0 - mn0);
        float corr1 = __expf(m1 - mn1);
        m0 = mn0; m1 = mn1;
        l0 *= corr0; l1 *= corr1;
        #pragma unroll
        for (int nd = 0; nd < 6; nd++) {
            O[nd][0] *= corr0; O[nd][1] *= corr0;
            O[nd][2] *= corr1; O[nd][3] *= corr1;
        }

        float ps0 = 0.f, ps1 = 0.f;
        #pragma unroll
        for (int n = 0; n < 8; n++) {
            S[n][0] = __expf(S[n][0] - m0);
            S[n][1] = __expf(S[n][1] - m0);
            S[n][2] = __expf(S[n][2] - m1);
            S[n][3] = __expf(S[n][3] - m1);
            ps0 += S[n][0] + S[n][1];
            ps1 += S[n][2] + S[n][3];
        }
        ps0 += __shfl_xor_sync(0xffffffffu, ps0, 1);
        ps0 += __shfl_xor_sync(0xffffffffu, ps0, 2);
        ps1 += __shfl_xor_sync(0xffffffffu, ps1, 1);
        ps1 += __shfl_xor_sync(0xffffffffu, ps1, 2);
        l0 += ps0; l1 += ps1;

        // ---- O += P V (x3 split), P built per 16-key step ----
        #pragma unroll
        for (int kk = 0; kk < 4; kk++) {
            uint32_t ph[4], pl[4];
            #pragma unroll
            for (int half = 0; half < 2; half++) {     // C tiles 2kk, 2kk+1
                const float* Sc = S[2 * kk + half];
                uint32_t w0 = cvt2(Sc[0], Sc[1]);
                uint32_t w1 = cvt2(Sc[2], Sc[3]);
                ph[2 * half + 0] = w0;
                ph[2 * half + 1] = w1;
                pl[2 * half + 0] = cvt2(Sc[0] - lo16f(w0), Sc[1] - hi16f(w0));
                pl[2 * half + 1] = cvt2(Sc[2] - lo16f(w1), Sc[3] - hi16f(w1));
            }
            // reorder: a-regs are [r g lo16, r g+8, r g hi-cols, r g+8 hi-cols]
            // ph[0]=tile2kk rows g; ph[1]=tile2kk rows g+8; ph[2]/ph[3]=tile2kk+1
            #pragma unroll
            for (int nd = 0; nd < 6; nd++) {
                const uint32_t* vh = (const uint32_t*)&sV[0][nd * 8 + g][kk * 16 + 2 * t4];
                const uint32_t* vl = (const uint32_t*)&sV[1][nd * 8 + g][kk * 16 + 2 * t4];
                uint32_t bh0 = vh[0], bh1 = vh[4];
                mma16816(O[nd], ph[0], ph[1], ph[2], ph[3], bh0, bh1);
                mma16816(O[nd], pl[0], pl[1], pl[2], pl[3], bh0, bh1);
                mma16816(O[nd], ph[0], ph[1], ph[2], ph[3], vl[0], vl[4]);
            }
        }
        __syncthreads();
    }

    // ---- epilogue ----
    const float invl0 = 1.0f / l0;
    const float invl1 = 1.0f / l1;
    #pragma unroll
    for (int nd = 0; nd < 6; nd++) {
        long c = h * PH + nd * 8 + 2 * t4;
        float2 v0 = make_float2(O[nd][0] * invl0, O[nd][1] * invl0);
        float2 v1 = make_float2(O[nd][2] * invl1, O[nd][3] * invl1);
        *(float2*)&g_att[rowg  * DIMV + c] = v0;
        *(float2*)&g_att[rowg8 * DIMV + c] = v1;
    }
}

// ---------------------------------------------------------------------------
extern "C" void kernel_launch(void* const* d_in, const int* in_sizes, int n_in,
                              void* d_out, int out_size)
{
    const float* x     = (const float*)d_in[0];
    const float* w_in  = (const float*)d_in[1];
    const float* b_in  = (const float*)d_in[2];
    const float* w_out = (const float*)d_in[3];
    const float* b_out = (const float*)d_in[4];
    float* out = (float*)d_out;

    float* qkv = nullptr;
    float* att = nullptr;
    cudaGetSymbolAddress((void**)&qkv, g_qkv);
    cudaGetSymbolAddress((void**)&att, g_att);

    // 1) QKV projection
    {
        dim3 grid(NQKV / 128, MTOT / 128);
        gemm_bias_kernel<<<grid, 256>>>(x, w_in, b_in, qkv, MTOT, NQKV, DIMV);
    }
    // 2) bf16 hi/lo conversions
    convert_qk_kernel<<<(MTOT * DIMV) / 256, 256>>>();
    {
        dim3 grid(TSEQ / 64, 64);
        convert_v_kernel<<<grid, 256>>>();
    }
    // 3) Attention (tensor-core)
    {
        dim3 grid(TSEQ / 128, 64);
        attn_mma_kernel<<<grid, 256>>>();
    }
    // 4) Output projection
    {
        dim3 grid(DIMV / 128, MTOT / 128);
        gemm_bias_kernel<<<grid, 256>>>(att, w_out, b_out, out, MTOT, DIMV, DIMV);
    }
}

// round 7
// speedup vs baseline: 2.8192x; 1.3852x over previous
#include <cuda_runtime.h>
#include <cuda_bf16.h>
#include <cstdint>

#define DIMV 768
#define NHEAD 16
#define PH 48
#define BATCH 4
#define TSEQ 2048
#define MTOT (BATCH * TSEQ)   // 8192
#define NQKV (3 * DIMV)       // 2304
#define SCALE 0.14433756729740643f   // 1/sqrt(48)

// Scratch (allocation-free rule: __device__ globals)
__device__ float g_qkv[MTOT * NQKV];            // (8192, 2304) fp32 qkv
__device__ uint32_t g_Xh[MTOT * DIMV / 2];      // x split hi (bf16x2)
__device__ uint32_t g_Xl[MTOT * DIMV / 2];
__device__ uint32_t g_WinTh[NQKV * DIMV / 2];   // w_in^T split: [n][k]
__device__ uint32_t g_WinTl[NQKV * DIMV / 2];
__device__ uint32_t g_WoutTh[DIMV * DIMV / 2];  // w_out^T split
__device__ uint32_t g_WoutTl[DIMV * DIMV / 2];
__device__ uint32_t g_AttH[MTOT * DIMV / 2];    // attention out split
__device__ uint32_t g_AttL[MTOT * DIMV / 2];
__device__ __nv_bfloat16 g_Qh[MTOT * DIMV];     // q*scale hi
__device__ __nv_bfloat16 g_Ql[MTOT * DIMV];
__device__ __nv_bfloat16 g_Kh[MTOT * DIMV];
__device__ __nv_bfloat16 g_Kl[MTOT * DIMV];
__device__ __nv_bfloat16 g_Vth[64 * PH * TSEQ]; // V transposed: [bh][d][t]
__device__ __nv_bfloat16 g_Vtl[64 * PH * TSEQ];

// ---- bf16 pack/unpack ----
// cvt2: pack (lo,hi) floats -> bf16x2 reg with first arg in low half
__device__ __forceinline__ uint32_t cvt2(float lo, float hi) {
    uint32_t r;
    asm("cvt.rn.bf16x2.f32 %0, %1, %2;" : "=r"(r) : "f"(hi), "f"(lo));
    return r;
}
__device__ __forceinline__ float lo16f(uint32_t v) { return __uint_as_float(v << 16); }
__device__ __forceinline__ float hi16f(uint32_t v) { return __uint_as_float(v & 0xffff0000u); }

// ---- bf16 m16n8k16 mma ----
__device__ __forceinline__ void mma16816(float* c, uint32_t a0, uint32_t a1,
                                         uint32_t a2, uint32_t a3,
                                         uint32_t b0, uint32_t b1) {
    asm volatile(
        "mma.sync.aligned.m16n8k16.row.col.f32.bf16.bf16.f32 "
        "{%0,%1,%2,%3},{%4,%5,%6,%7},{%8,%9},{%0,%1,%2,%3};"
        : "+f"(c[0]), "+f"(c[1]), "+f"(c[2]), "+f"(c[3])
        : "r"(a0), "r"(a1), "r"(a2), "r"(a3), "r"(b0), "r"(b1));
}

// ---------------------------------------------------------------------------
// Split x (fp32) -> bf16 hi/lo packed pairs
// ---------------------------------------------------------------------------
__global__ void __launch_bounds__(256) convert_x_kernel(const float* __restrict__ x)
{
    const long i = (long)blockIdx.x * 256 + threadIdx.x;   // over MTOT*DIMV/2
    float2 v = ((const float2*)x)[i];
    uint32_t hi = cvt2(v.x, v.y);
    g_Xh[i] = hi;
    g_Xl[i] = cvt2(v.x - lo16f(hi), v.y - hi16f(hi));
}

// ---------------------------------------------------------------------------
// Transpose + split weights: W[K][N] fp32 -> Wt[N][K] bf16 hi/lo (u32 pairs)
// grid (N/32, K/32), block 256
// ---------------------------------------------------------------------------
__global__ void __launch_bounds__(256) convert_w_kernel(
    const float* __restrict__ W, uint32_t* __restrict__ WtH,
    uint32_t* __restrict__ WtL, int K, int N)
{
    __shared__ float sT[32][33];
    const int k0 = blockIdx.y * 32, n0 = blockIdx.x * 32;
    const int tid = threadIdx.x;
    const int tx = tid & 31, ty = tid >> 5;   // ty 0..7
    #pragma unroll
    for (int i = 0; i < 4; i++)
        sT[ty + i * 8][tx] = W[(long)(k0 + ty + i * 8) * N + n0 + tx];
    __syncthreads();

    const int nr = tid >> 3;   // 0..31
    const int kc = tid & 7;    // 0..7
    #pragma unroll
    for (int i = 0; i < 2; i++) {
        int kk = kc + i * 8;   // u32 index within 16 (k = 2kk, 2kk+1)
        float x0 = sT[2 * kk][nr], x1 = sT[2 * kk + 1][nr];
        uint32_t whi = cvt2(x0, x1);
        uint32_t wlo = cvt2(x0 - lo16f(whi), x1 - hi16f(whi));
        long o = (long)(n0 + nr) * (K / 2) + k0 / 2 + kk;
        WtH[o] = whi;
        WtL[o] = wlo;
    }
}

// ---------------------------------------------------------------------------
// Tensor-core GEMM, bf16 x3-split: C[M,N] = A[M,K] B[K,N] + bias
// A given as row-major hi/lo u32-pairs; B given transposed [N][K] hi/lo.
// BM=BN=128, BK=16, 256 threads (8 warps, 2x4), warp tile 64x32.
// ---------------------------------------------------------------------------
__global__ void __launch_bounds__(256) gemm_tc_kernel(
    const uint4* __restrict__ Ah, const uint4* __restrict__ Al,
    const uint4* __restrict__ Bh, const uint4* __restrict__ Bl,
    const float* __restrict__ bias, float* __restrict__ C,
    int M, int N, int K)
{
    __shared__ __align__(16) __nv_bfloat16 sA[2][128][24];  // [hi/lo][m][k]
    __shared__ __align__(16) __nv_bfloat16 sB[2][128][24];  // [hi/lo][n][k]

    const int tid = threadIdx.x;
    const int wid = tid >> 5;
    const int lane = tid & 31;
    const int g = lane >> 2;            // 0..7
    const int t4 = lane & 3;            // 0..3
    const int wr = wid >> 2;            // 0..1 -> m offset wr*64
    const int wc = wid & 3;             // 0..3 -> n offset wc*32

    const int m0 = blockIdx.y * 128;
    const int n0 = blockIdx.x * 128;
    const int row = tid >> 1;           // 0..127
    const int half = tid & 1;
    const int Ku4 = K >> 3;             // uint4 per row

    const uint4* pAh = Ah + (long)(m0 + row) * Ku4 + half;
    const uint4* pAl = Al + (long)(m0 + row) * Ku4 + half;
    const uint4* pBh = Bh + (long)(n0 + row) * Ku4 + half;
    const uint4* pBl = Bl + (long)(n0 + row) * Ku4 + half;

    float acc[4][4][4];
    #pragma unroll
    for (int mt = 0; mt < 4; mt++)
        #pragma unroll
        for (int nt = 0; nt < 4; nt++)
            #pragma unroll
            for (int j = 0; j < 4; j++) acc[mt][nt][j] = 0.f;

    uint4 ra0 = pAh[0], ra1 = pAl[0], rb0 = pBh[0], rb1 = pBl[0];

    const int NIT = K / 16;
    for (int it = 0; it < NIT; it++) {
        *(uint4*)&sA[0][row][half * 8] = ra0;
        *(uint4*)&sA[1][row][half * 8] = ra1;
        *(uint4*)&sB[0][row][half * 8] = rb0;
        *(uint4*)&sB[1][row][half * 8] = rb1;
        __syncthreads();

        if (it + 1 < NIT) {
            ra0 = pAh[(it + 1) * 2];
            ra1 = pAl[(it + 1) * 2];
            rb0 = pBh[(it + 1) * 2];
            rb1 = pBl[(it + 1) * 2];
        }

        const uint32_t* sA0 = (const uint32_t*)sA[0];  // stride 12 u32/row
        const uint32_t* sA1 = (const uint32_t*)sA[1];
        const uint32_t* sB0 = (const uint32_t*)sB[0];
        const uint32_t* sB1 = (const uint32_t*)sB[1];

        uint32_t bfh[4][2], bfl[4][2];
        #pragma unroll
        for (int nt = 0; nt < 4; nt++) {
            int n = wc * 32 + nt * 8 + g;
            bfh[nt][0] = sB0[n * 12 + t4];
            bfh[nt][1] = sB0[n * 12 + t4 + 4];
            bfl[nt][0] = sB1[n * 12 + t4];
            bfl[nt][1] = sB1[n * 12 + t4 + 4];
        }
        #pragma unroll
        for (int mt = 0; mt < 4; mt++) {
            int r0 = (wr * 64 + mt * 16 + g) * 12;
            int r1 = r0 + 8 * 12;
            uint32_t ah0 = sA0[r0 + t4],     ah1 = sA0[r1 + t4];
            uint32_t ah2 = sA0[r0 + t4 + 4], ah3 = sA0[r1 + t4 + 4];
            uint32_t al0 = sA1[r0 + t4],     al1 = sA1[r1 + t4];
            uint32_t al2 = sA1[r0 + t4 + 4], al3 = sA1[r1 + t4 + 4];
            #pragma unroll
            for (int nt = 0; nt < 4; nt++) {
                mma16816(acc[mt][nt], ah0, ah1, ah2, ah3, bfh[nt][0], bfh[nt][1]);
                mma16816(acc[mt][nt], al0, al1, al2, al3, bfh[nt][0], bfh[nt][1]);
                mma16816(acc[mt][nt], ah0, ah1, ah2, ah3, bfl[nt][0], bfl[nt][1]);
            }
        }
        __syncthreads();
    }

    // epilogue
    #pragma unroll
    for (int mt = 0; mt < 4; mt++) {
        int r = m0 + wr * 64 + mt * 16 + g;
        #pragma unroll
        for (int nt = 0; nt < 4; nt++) {
            int c = n0 + wc * 32 + nt * 8 + 2 * t4;
            float b0 = bias[c], b1 = bias[c + 1];
            *(float2*)&C[(long)r * N + c] =
                make_float2(acc[mt][nt][0] + b0, acc[mt][nt][1] + b1);
            *(float2*)&C[(long)(r + 8) * N + c] =
                make_float2(acc[mt][nt][2] + b0, acc[mt][nt][3] + b1);
        }
    }
}

// ---------------------------------------------------------------------------
// Split Q (pre-scaled) and K into bf16 hi/lo, layout [row][h*48+d]
// ---------------------------------------------------------------------------
__global__ void __launch_bounds__(256) convert_qk_kernel()
{
    const int idx = blockIdx.x * 256 + threadIdx.x;   // over MTOT*DIMV
    const int row = idx / DIMV;
    const int c   = idx - row * DIMV;
    const int h   = c / PH;
    const int d   = c - h * PH;
    const long base = (long)row * NQKV + h * (3 * PH) + d;

    float q = g_qkv[base] * SCALE;
    float k = g_qkv[base + PH];

    __nv_bfloat16 qh = __float2bfloat16(q);
    g_Qh[idx] = qh;
    g_Ql[idx] = __float2bfloat16(q - __bfloat162float(qh));
    __nv_bfloat16 kh = __float2bfloat16(k);
    g_Kh[idx] = kh;
    g_Kl[idx] = __float2bfloat16(k - __bfloat162float(kh));
}

// ---------------------------------------------------------------------------
// V -> transposed bf16 hi/lo: g_Vt*[bh][d][t].  grid (TSEQ/64, 64), block 256
// ---------------------------------------------------------------------------
__global__ void __launch_bounds__(256) convert_v_kernel()
{
    __shared__ float sv[PH][65];

    const int tb = blockIdx.x;
    const int bh = blockIdx.y;
    const int b = bh >> 4;
    const int h = bh & 15;
    const int tid = threadIdx.x;

    const int tl = tid >> 2;
    const int dp = (tid & 3) * 12;
    const long rbase = (long)(b * TSEQ + tb * 64 + tl) * NQKV + h * (3 * PH) + 2 * PH + dp;
    #pragma unroll
    for (int j = 0; j < 12; j++)
        sv[dp + j][tl] = g_qkv[rbase + j];
    __syncthreads();

    uint32_t* Vh32 = (uint32_t*)g_Vth;
    uint32_t* Vl32 = (uint32_t*)g_Vtl;
    const long obase = ((long)bh * PH * TSEQ) / 2;
    #pragma unroll
    for (int i = 0; i < 6; i++) {
        int tau = tid + 256 * i;
        int d = tau >> 5;
        int j = tau & 31;
        float x0 = sv[d][2 * j];
        float x1 = sv[d][2 * j + 1];
        uint32_t whi = cvt2(x0, x1);
        uint32_t wlo = cvt2(x0 - lo16f(whi), x1 - hi16f(whi));
        long o = obase + (long)d * (TSEQ / 2) + tb * 32 + j;
        Vh32[o] = whi;
        Vl32[o] = wlo;
    }
}

// ---------------------------------------------------------------------------
// Flash attention with mma.sync bf16 x3-split.
// grid (TSEQ/128, 64), block 256 (8 warps, 16 query rows each).
// Epilogue writes bf16 hi/lo (g_AttH/g_AttL) for the tc out-projection.
// ---------------------------------------------------------------------------
__global__ void __launch_bounds__(256, 2) attn_mma_kernel()
{
    __shared__ __align__(16) __nv_bfloat16 sK[2][64][56];  // [hi/lo][key][dim]
    __shared__ __align__(16) __nv_bfloat16 sV[2][48][72];  // [hi/lo][dim][key]

    const int tid = threadIdx.x;
    const int wid = tid >> 5;
    const int lane = tid & 31;
    const int g = lane >> 2;
    const int t4 = lane & 3;

    const int bh = blockIdx.y;
    const int b = bh >> 4;
    const int h = bh & 15;
    const int qr0 = blockIdx.x * 128 + wid * 16;
    const long rowg  = (long)b * TSEQ + qr0 + g;
    const long rowg8 = rowg + 8;

    const uint32_t* Qh32 = (const uint32_t*)g_Qh;
    const uint32_t* Ql32 = (const uint32_t*)g_Ql;
    uint32_t qh[3][4], ql[3][4];
    #pragma unroll
    for (int kk = 0; kk < 3; kk++) {
        long o0 = rowg  * 384 + h * 24 + kk * 8 + t4;
        long o1 = rowg8 * 384 + h * 24 + kk * 8 + t4;
        qh[kk][0] = Qh32[o0];     qh[kk][1] = Qh32[o1];
        qh[kk][2] = Qh32[o0 + 4]; qh[kk][3] = Qh32[o1 + 4];
        ql[kk][0] = Ql32[o0];     ql[kk][1] = Ql32[o1];
        ql[kk][2] = Ql32[o0 + 4]; ql[kk][3] = Ql32[o1 + 4];
    }

    float O[6][4];
    #pragma unroll
    for (int i = 0; i < 6; i++)
        #pragma unroll
        for (int j = 0; j < 4; j++) O[i][j] = 0.f;
    float m0 = -1e30f, m1 = -1e30f, l0 = 0.f, l1 = 0.f;

    for (int kb = 0; kb < TSEQ; kb += 64) {
        #pragma unroll
        for (int i = 0; i < 3; i++) {
            int tau = tid + 256 * i;
            int arr = tau / 384;
            int rem = tau - arr * 384;
            int key = rem / 6;
            int c = rem - key * 6;
            const __nv_bfloat16* src = arr ? g_Kl : g_Kh;
            float4 v = *(const float4*)&src[(long)(b * TSEQ + kb + key) * DIMV + h * PH + c * 8];
            *(float4*)&sK[arr][key][c * 8] = v;
        }
        #pragma unroll
        for (int i = 0; i < 3; i++) {
            int tau = tid + 256 * i;
            int arr = tau / 384;
            int rem = tau - arr * 384;
            int d = rem >> 3;
            int c = rem & 7;
            const __nv_bfloat16* src = arr ? g_Vtl : g_Vth;
            float4 v = *(const float4*)&src[(long)bh * (PH * TSEQ) + d * TSEQ + kb + c * 8];
            *(float4*)&sV[arr][d][c * 8] = v;
        }
        __syncthreads();

        float S[8][4];
        #pragma unroll
        for (int n = 0; n < 8; n++)
            #pragma unroll
            for (int j = 0; j < 4; j++) S[n][j] = 0.f;

        #pragma unroll
        for (int kk = 0; kk < 3; kk++) {
            #pragma unroll
            for (int n = 0; n < 8; n++) {
                const uint32_t* kh = (const uint32_t*)&sK[0][n * 8 + g][kk * 16 + 2 * t4];
                const uint32_t* kl = (const uint32_t*)&sK[1][n * 8 + g][kk * 16 + 2 * t4];
                uint32_t bh0 = kh[0], bh1 = kh[4];
                mma16816(S[n], qh[kk][0], qh[kk][1], qh[kk][2], qh[kk][3], bh0, bh1);
                mma16816(S[n], ql[kk][0], ql[kk][1], ql[kk][2], ql[kk][3], bh0, bh1);
                mma16816(S[n], qh[kk][0], qh[kk][1], qh[kk][2], qh[kk][3], kl[0], kl[4]);
            }
        }

        float rmax0 = -1e30f, rmax1 = -1e30f;
        #pragma unroll
        for (int n = 0; n < 8; n++) {
            rmax0 = fmaxf(rmax0, fmaxf(S[n][0], S[n][1]));
            rmax1 = fmaxf(rmax1, fmaxf(S[n][2], S[n][3]));
        }
        rmax0 = fmaxf(rmax0, __shfl_xor_sync(0xffffffffu, rmax0, 1));
        rmax0 = fmaxf(rmax0, __shfl_xor_sync(0xffffffffu, rmax0, 2));
        rmax1 = fmaxf(rmax1, __shfl_xor_sync(0xffffffffu, rmax1, 1));
        rmax1 = fmaxf(rmax1, __shfl_xor_sync(0xffffffffu, rmax1, 2));

        float mn0 = fmaxf(m0, rmax0);
        float mn1 = fmaxf(m1, rmax1);
        float corr0 = __expf(m0 - mn0);
        float corr1 = __expf(m1 - mn1);
        m0 = mn0; m1 = mn1;
        l0 *= corr0; l1 *= corr1;
        #pragma unroll
        for (int nd = 0; nd < 6; nd++) {
            O[nd][0] *= corr0; O[nd][1] *= corr0;
            O[nd][2] *= corr1; O[nd][3] *= corr1;
        }

        float ps0 = 0.f, ps1 = 0.f;
        #pragma unroll
        for (int n = 0; n < 8; n++) {
            S[n][0] = __expf(S[n][0] - m0);
            S[n][1] = __expf(S[n][1] - m0);
            S[n][2] = __expf(S[n][2] - m1);
            S[n][3] = __expf(S[n][3] - m1);
            ps0 += S[n][0] + S[n][1];
            ps1 += S[n][2] + S[n][3];
        }
        ps0 += __shfl_xor_sync(0xffffffffu, ps0, 1);
        ps0 += __shfl_xor_sync(0xffffffffu, ps0, 2);
        ps1 += __shfl_xor_sync(0xffffffffu, ps1, 1);
        ps1 += __shfl_xor_sync(0xffffffffu, ps1, 2);
        l0 += ps0; l1 += ps1;

        #pragma unroll
        for (int kk = 0; kk < 4; kk++) {
            uint32_t ph[4], pl[4];
            #pragma unroll
            for (int half = 0; half < 2; half++) {
                const float* Sc = S[2 * kk + half];
                uint32_t w0 = cvt2(Sc[0], Sc[1]);
                uint32_t w1 = cvt2(Sc[2], Sc[3]);
                ph[2 * half + 0] = w0;
                ph[2 * half + 1] = w1;
                pl[2 * half + 0] = cvt2(Sc[0] - lo16f(w0), Sc[1] - hi16f(w0));
                pl[2 * half + 1] = cvt2(Sc[2] - lo16f(w1), Sc[3] - hi16f(w1));
            }
            #pragma unroll
            for (int nd = 0; nd < 6; nd++) {
                const uint32_t* vh = (const uint32_t*)&sV[0][nd * 8 + g][kk * 16 + 2 * t4];
                const uint32_t* vl = (const uint32_t*)&sV[1][nd * 8 + g][kk * 16 + 2 * t4];
                uint32_t bh0 = vh[0], bh1 = vh[4];
                mma16816(O[nd], ph[0], ph[1], ph[2], ph[3], bh0, bh1);
                mma16816(O[nd], pl[0], pl[1], pl[2], pl[3], bh0, bh1);
                mma16816(O[nd], ph[0], ph[1], ph[2], ph[3], vl[0], vl[4]);
            }
        }
        __syncthreads();
    }

    // epilogue: write split bf16 directly (feeds tc out-projection)
    const float invl0 = 1.0f / l0;
    const float invl1 = 1.0f / l1;
    #pragma unroll
    for (int nd = 0; nd < 6; nd++) {
        long c = h * PH + nd * 8 + 2 * t4;
        float v0x = O[nd][0] * invl0, v0y = O[nd][1] * invl0;
        float v1x = O[nd][2] * invl1, v1y = O[nd][3] * invl1;
        uint32_t h0 = cvt2(v0x, v0y);
        uint32_t h1 = cvt2(v1x, v1y);
        long i0 = (rowg  * DIMV + c) >> 1;
        long i1 = (rowg8 * DIMV + c) >> 1;
        g_AttH[i0] = h0;
        g_AttL[i0] = cvt2(v0x - lo16f(h0), v0y - hi16f(h0));
        g_AttH[i1] = h1;
        g_AttL[i1] = cvt2(v1x - lo16f(h1), v1y - hi16f(h1));
    }
}

// ---------------------------------------------------------------------------
extern "C" void kernel_launch(void* const* d_in, const int* in_sizes, int n_in,
                              void* d_out, int out_size)
{
    const float* x     = (const float*)d_in[0];
    const float* w_in  = (const float*)d_in[1];
    const float* b_in  = (const float*)d_in[2];
    const float* w_out = (const float*)d_in[3];
    const float* b_out = (const float*)d_in[4];
    float* out = (float*)d_out;

    float* qkv = nullptr;
    cudaGetSymbolAddress((void**)&qkv, g_qkv);
    uint32_t *Xh, *Xl, *WinTh, *WinTl, *WoutTh, *WoutTl, *AttH, *AttL;
    cudaGetSymbolAddress((void**)&Xh, g_Xh);
    cudaGetSymbolAddress((void**)&Xl, g_Xl);
    cudaGetSymbolAddress((void**)&WinTh, g_WinTh);
    cudaGetSymbolAddress((void**)&WinTl, g_WinTl);
    cudaGetSymbolAddress((void**)&WoutTh, g_WoutTh);
    cudaGetSymbolAddress((void**)&WoutTl, g_WoutTl);
    cudaGetSymbolAddress((void**)&AttH, g_AttH);
    cudaGetSymbolAddress((void**)&AttL, g_AttL);

    // 1) input splits
    convert_x_kernel<<<(MTOT * DIMV / 2) / 256, 256>>>(x);
    {
        dim3 grid(NQKV / 32, DIMV / 32);
        convert_w_kernel<<<grid, 256>>>(w_in, WinTh, WinTl, DIMV, NQKV);
    }
    {
        dim3 grid(DIMV / 32, DIMV / 32);
        convert_w_kernel<<<grid, 256>>>(w_out, WoutTh, WoutTl, DIMV, DIMV);
    }

    // 2) QKV projection (tensor core)
    {
        dim3 grid(NQKV / 128, MTOT / 128);
        gemm_tc_kernel<<<grid, 256>>>((const uint4*)Xh, (const uint4*)Xl,
                                      (const uint4*)WinTh, (const uint4*)WinTl,
                                      b_in, qkv, MTOT, NQKV, DIMV);
    }

    // 3) attention-side conversions
    convert_qk_kernel<<<(MTOT * DIMV) / 256, 256>>>();
    {
        dim3 grid(TSEQ / 64, 64);
        convert_v_kernel<<<grid, 256>>>();
    }

    // 4) attention (tensor core), writes split bf16 output
    {
        dim3 grid(TSEQ / 128, 64);
        attn_mma_kernel<<<grid, 256>>>();
    }

    // 5) output projection (tensor core) -> d_out
    {
        dim3 grid(DIMV / 128, MTOT / 128);
        gemm_tc_kernel<<<grid, 256>>>((const uint4*)AttH, (const uint4*)AttL,
                                      (const uint4*)WoutTh, (const uint4*)WoutTl,
                                      b_out, out, MTOT, DIMV, DIMV);
    }
}

// round 8
// speedup vs baseline: 3.0114x; 1.0682x over previous
#include <cuda_runtime.h>
#include <cuda_bf16.h>
#include <cstdint>

#define DIMV 768
#define NHEAD 16
#define PH 48
#define BATCH 4
#define TSEQ 2048
#define MTOT (BATCH * TSEQ)   // 8192
#define NQKV (3 * DIMV)       // 2304
#define SCALE 0.14433756729740643f   // 1/sqrt(48)

// Scratch (allocation-free rule: __device__ globals)
__device__ float g_qkv[MTOT * NQKV];
__device__ uint32_t g_Xh[MTOT * DIMV / 2];
__device__ uint32_t g_Xl[MTOT * DIMV / 2];
__device__ uint32_t g_WinTh[NQKV * DIMV / 2];
__device__ uint32_t g_WinTl[NQKV * DIMV / 2];
__device__ uint32_t g_WoutTh[DIMV * DIMV / 2];
__device__ uint32_t g_WoutTl[DIMV * DIMV / 2];
__device__ uint32_t g_AttH[MTOT * DIMV / 2];
__device__ uint32_t g_AttL[MTOT * DIMV / 2];
__device__ __nv_bfloat16 g_Qh[MTOT * DIMV];
__device__ __nv_bfloat16 g_Ql[MTOT * DIMV];
__device__ __nv_bfloat16 g_Kh[MTOT * DIMV];
__device__ __nv_bfloat16 g_Kl[MTOT * DIMV];
__device__ __nv_bfloat16 g_Vth[64 * PH * TSEQ];
__device__ __nv_bfloat16 g_Vtl[64 * PH * TSEQ];

// ---- helpers ----
__device__ __forceinline__ uint32_t cvt2(float lo, float hi) {
    uint32_t r;
    asm("cvt.rn.bf16x2.f32 %0, %1, %2;" : "=r"(r) : "f"(hi), "f"(lo));
    return r;
}
__device__ __forceinline__ float lo16f(uint32_t v) { return __uint_as_float(v << 16); }
__device__ __forceinline__ float hi16f(uint32_t v) { return __uint_as_float(v & 0xffff0000u); }

__device__ __forceinline__ void mma16816(float* c, uint32_t a0, uint32_t a1,
                                         uint32_t a2, uint32_t a3,
                                         uint32_t b0, uint32_t b1) {
    asm volatile(
        "mma.sync.aligned.m16n8k16.row.col.f32.bf16.bf16.f32 "
        "{%0,%1,%2,%3},{%4,%5,%6,%7},{%8,%9},{%0,%1,%2,%3};"
        : "+f"(c[0]), "+f"(c[1]), "+f"(c[2]), "+f"(c[3])
        : "r"(a0), "r"(a1), "r"(a2), "r"(a3), "r"(b0), "r"(b1));
}

// ---- cp.async ----
__device__ __forceinline__ void cpa16(uint32_t dst_smem, const void* src) {
    asm volatile("cp.async.cg.shared.global [%0], [%1], 16;"
                 :: "r"(dst_smem), "l"(src));
}
__device__ __forceinline__ void cpa_commit() {
    asm volatile("cp.async.commit_group;");
}
__device__ __forceinline__ void cpa_wait1() {
    asm volatile("cp.async.wait_group 1;");
}
__device__ __forceinline__ void cpa_wait0() {
    asm volatile("cp.async.wait_group 0;");
}
__device__ __forceinline__ uint32_t smem_u32(const void* p) {
    return (uint32_t)__cvta_generic_to_shared(p);
}

// ---------------------------------------------------------------------------
// Split x -> bf16 hi/lo pairs
// ---------------------------------------------------------------------------
__global__ void __launch_bounds__(256) convert_x_kernel(const float* __restrict__ x)
{
    const long i = (long)blockIdx.x * 256 + threadIdx.x;
    float2 v = ((const float2*)x)[i];
    uint32_t hi = cvt2(v.x, v.y);
    g_Xh[i] = hi;
    g_Xl[i] = cvt2(v.x - lo16f(hi), v.y - hi16f(hi));
}

// ---------------------------------------------------------------------------
// Transpose + split weights: W[K][N] -> Wt[N][K] hi/lo
// ---------------------------------------------------------------------------
__global__ void __launch_bounds__(256) convert_w_kernel(
    const float* __restrict__ W, uint32_t* __restrict__ WtH,
    uint32_t* __restrict__ WtL, int K, int N)
{
    __shared__ float sT[32][33];
    const int k0 = blockIdx.y * 32, n0 = blockIdx.x * 32;
    const int tid = threadIdx.x;
    const int tx = tid & 31, ty = tid >> 5;
    #pragma unroll
    for (int i = 0; i < 4; i++)
        sT[ty + i * 8][tx] = W[(long)(k0 + ty + i * 8) * N + n0 + tx];
    __syncthreads();

    const int nr = tid >> 3;
    const int kc = tid & 7;
    #pragma unroll
    for (int i = 0; i < 2; i++) {
        int kk = kc + i * 8;
        float x0 = sT[2 * kk][nr], x1 = sT[2 * kk + 1][nr];
        uint32_t whi = cvt2(x0, x1);
        uint32_t wlo = cvt2(x0 - lo16f(whi), x1 - hi16f(whi));
        long o = (long)(n0 + nr) * (K / 2) + k0 / 2 + kk;
        WtH[o] = whi;
        WtL[o] = wlo;
    }
}

// ---------------------------------------------------------------------------
// Tensor-core GEMM, bf16 x3-split, cp.async double-buffered.
// BM=BN=128, BK=16, 256 threads, warp tile 64x32. smem = 48KB (2 stages).
// ---------------------------------------------------------------------------
__global__ void __launch_bounds__(256) gemm_tc_kernel(
    const uint4* __restrict__ Ah, const uint4* __restrict__ Al,
    const uint4* __restrict__ Bh, const uint4* __restrict__ Bl,
    const float* __restrict__ bias, float* __restrict__ C,
    int M, int N, int K)
{
    // [stage][hi/lo][row][24]
    __shared__ __align__(16) __nv_bfloat16 sA[2][2][128][24];
    __shared__ __align__(16) __nv_bfloat16 sB[2][2][128][24];

    const int tid = threadIdx.x;
    const int wid = tid >> 5;
    const int lane = tid & 31;
    const int g = lane >> 2;
    const int t4 = lane & 3;
    const int wr = wid >> 2;
    const int wc = wid & 3;

    const int m0 = blockIdx.y * 128;
    const int n0 = blockIdx.x * 128;
    const int row = tid >> 1;
    const int half = tid & 1;
    const int Ku4 = K >> 3;

    const uint4* pAh = Ah + (long)(m0 + row) * Ku4 + half;
    const uint4* pAl = Al + (long)(m0 + row) * Ku4 + half;
    const uint4* pBh = Bh + (long)(n0 + row) * Ku4 + half;
    const uint4* pBl = Bl + (long)(n0 + row) * Ku4 + half;

    const uint32_t dAh0 = smem_u32(&sA[0][0][row][half * 8]);
    const uint32_t dAl0 = smem_u32(&sA[0][1][row][half * 8]);
    const uint32_t dBh0 = smem_u32(&sB[0][0][row][half * 8]);
    const uint32_t dBl0 = smem_u32(&sB[0][1][row][half * 8]);
    const uint32_t stB = 2 * 2 * 128 * 24;   // bytes per stage

    float acc[4][4][4];
    #pragma unroll
    for (int mt = 0; mt < 4; mt++)
        #pragma unroll
        for (int nt = 0; nt < 4; nt++)
            #pragma unroll
            for (int j = 0; j < 4; j++) acc[mt][nt][j] = 0.f;

    const int NIT = K / 16;
    // prologue: stage 0 <- tile 0
    cpa16(dAh0, pAh); cpa16(dAl0, pAl);
    cpa16(dBh0, pBh); cpa16(dBl0, pBl);
    cpa_commit();

    for (int it = 0; it < NIT; it++) {
        if (it + 1 < NIT) {
            uint32_t so = ((it + 1) & 1) * stB;
            cpa16(dAh0 + so, pAh + (it + 1) * 2);
            cpa16(dAl0 + so, pAl + (it + 1) * 2);
            cpa16(dBh0 + so, pBh + (it + 1) * 2);
            cpa16(dBl0 + so, pBl + (it + 1) * 2);
            cpa_commit();
            cpa_wait1();
        } else {
            cpa_wait0();
        }
        __syncthreads();

        const int st = it & 1;
        const uint32_t* sA0 = (const uint32_t*)sA[st][0];
        const uint32_t* sA1 = (const uint32_t*)sA[st][1];
        const uint32_t* sB0 = (const uint32_t*)sB[st][0];
        const uint32_t* sB1 = (const uint32_t*)sB[st][1];

        uint32_t bfh[4][2], bfl[4][2];
        #pragma unroll
        for (int nt = 0; nt < 4; nt++) {
            int n = wc * 32 + nt * 8 + g;
            bfh[nt][0] = sB0[n * 12 + t4];
            bfh[nt][1] = sB0[n * 12 + t4 + 4];
            bfl[nt][0] = sB1[n * 12 + t4];
            bfl[nt][1] = sB1[n * 12 + t4 + 4];
        }
        #pragma unroll
        for (int mt = 0; mt < 4; mt++) {
            int r0 = (wr * 64 + mt * 16 + g) * 12;
            int r1 = r0 + 8 * 12;
            uint32_t ah0 = sA0[r0 + t4],     ah1 = sA0[r1 + t4];
            uint32_t ah2 = sA0[r0 + t4 + 4], ah3 = sA0[r1 + t4 + 4];
            uint32_t al0 = sA1[r0 + t4],     al1 = sA1[r1 + t4];
            uint32_t al2 = sA1[r0 + t4 + 4], al3 = sA1[r1 + t4 + 4];
            #pragma unroll
            for (int nt = 0; nt < 4; nt++) {
                mma16816(acc[mt][nt], ah0, ah1, ah2, ah3, bfh[nt][0], bfh[nt][1]);
                mma16816(acc[mt][nt], al0, al1, al2, al3, bfh[nt][0], bfh[nt][1]);
                mma16816(acc[mt][nt], ah0, ah1, ah2, ah3, bfl[nt][0], bfl[nt][1]);
            }
        }
        __syncthreads();
    }

    #pragma unroll
    for (int mt = 0; mt < 4; mt++) {
        int r = m0 + wr * 64 + mt * 16 + g;
        #pragma unroll
        for (int nt = 0; nt < 4; nt++) {
            int c = n0 + wc * 32 + nt * 8 + 2 * t4;
            float b0 = bias[c], b1 = bias[c + 1];
            *(float2*)&C[(long)r * N + c] =
                make_float2(acc[mt][nt][0] + b0, acc[mt][nt][1] + b1);
            *(float2*)&C[(long)(r + 8) * N + c] =
                make_float2(acc[mt][nt][2] + b0, acc[mt][nt][3] + b1);
        }
    }
}

// ---------------------------------------------------------------------------
// Split Q (pre-scaled) and K into bf16 hi/lo
// ---------------------------------------------------------------------------
__global__ void __launch_bounds__(256) convert_qk_kernel()
{
    const int idx = blockIdx.x * 256 + threadIdx.x;
    const int row = idx / DIMV;
    const int c   = idx - row * DIMV;
    const int h   = c / PH;
    const int d   = c - h * PH;
    const long base = (long)row * NQKV + h * (3 * PH) + d;

    float q = g_qkv[base] * SCALE;
    float k = g_qkv[base + PH];

    __nv_bfloat16 qh = __float2bfloat16(q);
    g_Qh[idx] = qh;
    g_Ql[idx] = __float2bfloat16(q - __bfloat162float(qh));
    __nv_bfloat16 kh = __float2bfloat16(k);
    g_Kh[idx] = kh;
    g_Kl[idx] = __float2bfloat16(k - __bfloat162float(kh));
}

// ---------------------------------------------------------------------------
// V -> transposed bf16 hi/lo
// ---------------------------------------------------------------------------
__global__ void __launch_bounds__(256) convert_v_kernel()
{
    __shared__ float sv[PH][65];

    const int tb = blockIdx.x;
    const int bh = blockIdx.y;
    const int b = bh >> 4;
    const int h = bh & 15;
    const int tid = threadIdx.x;

    const int tl = tid >> 2;
    const int dp = (tid & 3) * 12;
    const long rbase = (long)(b * TSEQ + tb * 64 + tl) * NQKV + h * (3 * PH) + 2 * PH + dp;
    #pragma unroll
    for (int j = 0; j < 12; j++)
        sv[dp + j][tl] = g_qkv[rbase + j];
    __syncthreads();

    uint32_t* Vh32 = (uint32_t*)g_Vth;
    uint32_t* Vl32 = (uint32_t*)g_Vtl;
    const long obase = ((long)bh * PH * TSEQ) / 2;
    #pragma unroll
    for (int i = 0; i < 6; i++) {
        int tau = tid + 256 * i;
        int d = tau >> 5;
        int j = tau & 31;
        float x0 = sv[d][2 * j];
        float x1 = sv[d][2 * j + 1];
        uint32_t whi = cvt2(x0, x1);
        uint32_t wlo = cvt2(x0 - lo16f(whi), x1 - hi16f(whi));
        long o = obase + (long)d * (TSEQ / 2) + tb * 32 + j;
        Vh32[o] = whi;
        Vl32[o] = wlo;
    }
}

// ---------------------------------------------------------------------------
// Flash attention, mma.sync bf16 x3, cp.async double-buffered K/V tiles.
// grid (TSEQ/128, 64), block 256. Dynamic smem: 2 stages.
//   sK stage: [2][64][56], sV stage: [2][48][72]
// ---------------------------------------------------------------------------
#define SK_STAGE (2 * 64 * 56)                 // elems per stage
#define SV_STAGE (2 * 48 * 72)
#define ATTN_SMEM ((2 * SK_STAGE + 2 * SV_STAGE) * 2)   // bytes = 56320

__global__ void __launch_bounds__(256, 2) attn_mma_kernel()
{
    extern __shared__ __align__(16) __nv_bfloat16 dyn[];
    __nv_bfloat16* sKb = dyn;                       // [2][2][64][56]
    __nv_bfloat16* sVb = dyn + 2 * SK_STAGE;        // [2][2][48][72]

    const int tid = threadIdx.x;
    const int wid = tid >> 5;
    const int lane = tid & 31;
    const int g = lane >> 2;
    const int t4 = lane & 3;

    const int bh = blockIdx.y;
    const int b = bh >> 4;
    const int h = bh & 15;
    const int qr0 = blockIdx.x * 128 + wid * 16;
    const long rowg  = (long)b * TSEQ + qr0 + g;
    const long rowg8 = rowg + 8;

    // per-thread cp.async slots (3 K chunks + 3 V chunks of 16B per tile)
    int kArr[3], kKey[3], kC[3], vArr[3], vD[3], vC[3];
    #pragma unroll
    for (int i = 0; i < 3; i++) {
        int tau = tid + 256 * i;
        kArr[i] = tau / 384;
        int rem = tau - kArr[i] * 384;
        kKey[i] = rem / 6;
        kC[i] = rem - kKey[i] * 6;
        vArr[i] = tau / 384;
        vD[i] = rem >> 3;
        vC[i] = rem & 7;
    }

    auto load_tile = [&](int kb, int st) {
        #pragma unroll
        for (int i = 0; i < 3; i++) {
            const __nv_bfloat16* src = (kArr[i] ? g_Kl : g_Kh)
                + (long)(b * TSEQ + kb + kKey[i]) * DIMV + h * PH + kC[i] * 8;
            uint32_t dst = smem_u32(sKb + (st * 2 + kArr[i]) * (64 * 56)
                                    + kKey[i] * 56 + kC[i] * 8);
            cpa16(dst, src);
        }
        #pragma unroll
        for (int i = 0; i < 3; i++) {
            const __nv_bfloat16* src = (vArr[i] ? g_Vtl : g_Vth)
                + (long)bh * (PH * TSEQ) + vD[i] * TSEQ + kb + vC[i] * 8;
            uint32_t dst = smem_u32(sVb + (st * 2 + vArr[i]) * (48 * 72)
                                    + vD[i] * 72 + vC[i] * 8);
            cpa16(dst, src);
        }
        cpa_commit();
    };

    const uint32_t* Qh32 = (const uint32_t*)g_Qh;
    const uint32_t* Ql32 = (const uint32_t*)g_Ql;
    uint32_t qh[3][4], ql[3][4];
    #pragma unroll
    for (int kk = 0; kk < 3; kk++) {
        long o0 = rowg  * 384 + h * 24 + kk * 8 + t4;
        long o1 = rowg8 * 384 + h * 24 + kk * 8 + t4;
        qh[kk][0] = Qh32[o0];     qh[kk][1] = Qh32[o1];
        qh[kk][2] = Qh32[o0 + 4]; qh[kk][3] = Qh32[o1 + 4];
        ql[kk][0] = Ql32[o0];     ql[kk][1] = Ql32[o1];
        ql[kk][2] = Ql32[o0 + 4]; ql[kk][3] = Ql32[o1 + 4];
    }

    float O[6][4];
    #pragma unroll
    for (int i = 0; i < 6; i++)
        #pragma unroll
        for (int j = 0; j < 4; j++) O[i][j] = 0.f;
    float m0 = -1e30f, m1 = -1e30f, l0 = 0.f, l1 = 0.f;

    load_tile(0, 0);   // prologue

    const int NT = TSEQ / 64;
    for (int t = 0; t < NT; t++) {
        if (t + 1 < NT) {
            load_tile((t + 1) * 64, (t + 1) & 1);
            cpa_wait1();
        } else {
            cpa_wait0();
        }
        __syncthreads();

        const int st = t & 1;
        const __nv_bfloat16* sK0 = sKb + (st * 2 + 0) * (64 * 56);
        const __nv_bfloat16* sK1 = sKb + (st * 2 + 1) * (64 * 56);
        const __nv_bfloat16* sV0 = sVb + (st * 2 + 0) * (48 * 72);
        const __nv_bfloat16* sV1 = sVb + (st * 2 + 1) * (48 * 72);

        float S[8][4];
        #pragma unroll
        for (int n = 0; n < 8; n++)
            #pragma unroll
            for (int j = 0; j < 4; j++) S[n][j] = 0.f;

        #pragma unroll
        for (int kk = 0; kk < 3; kk++) {
            #pragma unroll
            for (int n = 0; n < 8; n++) {
                const uint32_t* kh = (const uint32_t*)(sK0 + (n * 8 + g) * 56 + kk * 16 + 2 * t4);
                const uint32_t* kl = (const uint32_t*)(sK1 + (n * 8 + g) * 56 + kk * 16 + 2 * t4);
                uint32_t bh0 = kh[0], bh1 = kh[4];
                mma16816(S[n], qh[kk][0], qh[kk][1], qh[kk][2], qh[kk][3], bh0, bh1);
                mma16816(S[n], ql[kk][0], ql[kk][1], ql[kk][2], ql[kk][3], bh0, bh1);
                mma16816(S[n], qh[kk][0], qh[kk][1], qh[kk][2], qh[kk][3], kl[0], kl[4]);
            }
        }

        float rmax0 = -1e30f, rmax1 = -1e30f;
        #pragma unroll
        for (int n = 0; n < 8; n++) {
            rmax0 = fmaxf(rmax0, fmaxf(S[n][0], S[n][1]));
            rmax1 = fmaxf(rmax1, fmaxf(S[n][2], S[n][3]));
        }
        rmax0 = fmaxf(rmax0, __shfl_xor_sync(0xffffffffu, rmax0, 1));
        rmax0 = fmaxf(rmax0, __shfl_xor_sync(0xffffffffu, rmax0, 2));
        rmax1 = fmaxf(rmax1, __shfl_xor_sync(0xffffffffu, rmax1, 1));
        rmax1 = fmaxf(rmax1, __shfl_xor_sync(0xffffffffu, rmax1, 2));

        float mn0 = fmaxf(m0, rmax0);
        float mn1 = fmaxf(m1, rmax1);
        float corr0 = __expf(m0 - mn0);
        float corr1 = __expf(m1 - mn1);
        m0 = mn0; m1 = mn1;
        l0 *= corr0; l1 *= corr1;
        #pragma unroll
        for (int nd = 0; nd < 6; nd++) {
            O[nd][0] *= corr0; O[nd][1] *= corr0;
            O[nd][2] *= corr1; O[nd][3] *= corr1;
        }

        float ps0 = 0.f, ps1 = 0.f;
        #pragma unroll
        for (int n = 0; n < 8; n++) {
            S[n][0] = __expf(S[n][0] - m0);
            S[n][1] = __expf(S[n][1] - m0);
            S[n][2] = __expf(S[n][2] - m1);
            S[n][3] = __expf(S[n][3] - m1);
            ps0 += S[n][0] + S[n][1];
            ps1 += S[n][2] + S[n][3];
        }
        ps0 += __shfl_xor_sync(0xffffffffu, ps0, 1);
        ps0 += __shfl_xor_sync(0xffffffffu, ps0, 2);
        ps1 += __shfl_xor_sync(0xffffffffu, ps1, 1);
        ps1 += __shfl_xor_sync(0xffffffffu, ps1, 2);
        l0 += ps0; l1 += ps1;

        #pragma unroll
        for (int kk = 0; kk < 4; kk++) {
            uint32_t ph[4], pl[4];
            #pragma unroll
            for (int half = 0; half < 2; half++) {
                const float* Sc = S[2 * kk + half];
                uint32_t w0 = cvt2(Sc[0], Sc[1]);
                uint32_t w1 = cvt2(Sc[2], Sc[3]);
                ph[2 * half + 0] = w0;
                ph[2 * half + 1] = w1;
                pl[2 * half + 0] = cvt2(Sc[0] - lo16f(w0), Sc[1] - hi16f(w0));
                pl[2 * half + 1] = cvt2(Sc[2] - lo16f(w1), Sc[3] - hi16f(w1));
            }
            #pragma unroll
            for (int nd = 0; nd < 6; nd++) {
                const uint32_t* vh = (const uint32_t*)(sV0 + (nd * 8 + g) * 72 + kk * 16 + 2 * t4);
                const uint32_t* vl = (const uint32_t*)(sV1 + (nd * 8 + g) * 72 + kk * 16 + 2 * t4);
                uint32_t bh0 = vh[0], bh1 = vh[4];
                mma16816(O[nd], ph[0], ph[1], ph[2], ph[3], bh0, bh1);
                mma16816(O[nd], pl[0], pl[1], pl[2], pl[3], bh0, bh1);
                mma16816(O[nd], ph[0], ph[1], ph[2], ph[3], vl[0], vl[4]);
            }
        }
        __syncthreads();
    }

    const float invl0 = 1.0f / l0;
    const float invl1 = 1.0f / l1;
    #pragma unroll
    for (int nd = 0; nd < 6; nd++) {
        long c = h * PH + nd * 8 + 2 * t4;
        float v0x = O[nd][0] * invl0, v0y = O[nd][1] * invl0;
        float v1x = O[nd][2] * invl1, v1y = O[nd][3] * invl1;
        uint32_t h0 = cvt2(v0x, v0y);
        uint32_t h1 = cvt2(v1x, v1y);
        long i0 = (rowg  * DIMV + c) >> 1;
        long i1 = (rowg8 * DIMV + c) >> 1;
        g_AttH[i0] = h0;
        g_AttL[i0] = cvt2(v0x - lo16f(h0), v0y - hi16f(h0));
        g_AttH[i1] = h1;
        g_AttL[i1] = cvt2(v1x - lo16f(h1), v1y - hi16f(h1));
    }
}

// ---------------------------------------------------------------------------
extern "C" void kernel_launch(void* const* d_in, const int* in_sizes, int n_in,
                              void* d_out, int out_size)
{
    const float* x     = (const float*)d_in[0];
    const float* w_in  = (const float*)d_in[1];
    const float* b_in  = (const float*)d_in[2];
    const float* w_out = (const float*)d_in[3];
    const float* b_out = (const float*)d_in[4];
    float* out = (float*)d_out;

    static bool attr_set = false;
    if (!attr_set) {
        cudaFuncSetAttribute(attn_mma_kernel,
                             cudaFuncAttributeMaxDynamicSharedMemorySize, ATTN_SMEM);
        attr_set = true;
    }

    float* qkv = nullptr;
    cudaGetSymbolAddress((void**)&qkv, g_qkv);
    uint32_t *Xh, *Xl, *WinTh, *WinTl, *WoutTh, *WoutTl, *AttH, *AttL;
    cudaGetSymbolAddress((void**)&Xh, g_Xh);
    cudaGetSymbolAddress((void**)&Xl, g_Xl);
    cudaGetSymbolAddress((void**)&WinTh, g_WinTh);
    cudaGetSymbolAddress((void**)&WinTl, g_WinTl);
    cudaGetSymbolAddress((void**)&WoutTh, g_WoutTh);
    cudaGetSymbolAddress((void**)&WoutTl, g_WoutTl);
    cudaGetSymbolAddress((void**)&AttH, g_AttH);
    cudaGetSymbolAddress((void**)&AttL, g_AttL);

    convert_x_kernel<<<(MTOT * DIMV / 2) / 256, 256>>>(x);
    {
        dim3 grid(NQKV / 32, DIMV / 32);
        convert_w_kernel<<<grid, 256>>>(w_in, WinTh, WinTl, DIMV, NQKV);
    }
    {
        dim3 grid(DIMV / 32, DIMV / 32);
        convert_w_kernel<<<grid, 256>>>(w_out, WoutTh, WoutTl, DIMV, DIMV);
    }

    {
        dim3 grid(NQKV / 128, MTOT / 128);
        gemm_tc_kernel<<<grid, 256>>>((const uint4*)Xh, (const uint4*)Xl,
                                      (const uint4*)WinTh, (const uint4*)WinTl,
                                      b_in, qkv, MTOT, NQKV, DIMV);
    }

    convert_qk_kernel<<<(MTOT * DIMV) / 256, 256>>>();
    {
        dim3 grid(TSEQ / 64, 64);
        convert_v_kernel<<<grid, 256>>>();
    }

    {
        dim3 grid(TSEQ / 128, 64);
        attn_mma_kernel<<<grid, 256, ATTN_SMEM>>>();
    }

    {
        dim3 grid(DIMV / 128, MTOT / 128);
        gemm_tc_kernel<<<grid, 256>>>((const uint4*)AttH, (const uint4*)AttL,
                                      (const uint4*)WoutTh, (const uint4*)WoutTl,
                                      b_out, out, MTOT, DIMV, DIMV);
    }
}

// round 9
// speedup vs baseline: 3.0780x; 1.0221x over previous
#include <cuda_runtime.h>
#include <cuda_bf16.h>
#include <cstdint>

#define DIMV 768
#define NHEAD 16
#define PH 48
#define BATCH 4
#define TSEQ 2048
#define MTOT (BATCH * TSEQ)   // 8192
#define NQKV (3 * DIMV)       // 2304
#define SCALE 0.14433756729740643f   // 1/sqrt(48)

// Scratch (allocation-free rule: __device__ globals)
__device__ float g_qkv[MTOT * NQKV];
__device__ uint32_t g_Xh[MTOT * DIMV / 2];
__device__ uint32_t g_Xl[MTOT * DIMV / 2];
__device__ uint32_t g_WinTh[NQKV * DIMV / 2];
__device__ uint32_t g_WinTl[NQKV * DIMV / 2];
__device__ uint32_t g_WoutTh[DIMV * DIMV / 2];
__device__ uint32_t g_WoutTl[DIMV * DIMV / 2];
__device__ uint32_t g_AttH[MTOT * DIMV / 2];
__device__ uint32_t g_AttL[MTOT * DIMV / 2];
__device__ __nv_bfloat16 g_Qh[MTOT * DIMV];
__device__ __nv_bfloat16 g_Ql[MTOT * DIMV];
__device__ __nv_bfloat16 g_Kh[MTOT * DIMV];
__device__ __nv_bfloat16 g_Kl[MTOT * DIMV];
__device__ __nv_bfloat16 g_Vth[64 * PH * TSEQ];
__device__ __nv_bfloat16 g_Vtl[64 * PH * TSEQ];

// ---- helpers ----
__device__ __forceinline__ uint32_t cvt2(float lo, float hi) {
    uint32_t r;
    asm("cvt.rn.bf16x2.f32 %0, %1, %2;" : "=r"(r) : "f"(hi), "f"(lo));
    return r;
}
__device__ __forceinline__ float lo16f(uint32_t v) { return __uint_as_float(v << 16); }
__device__ __forceinline__ float hi16f(uint32_t v) { return __uint_as_float(v & 0xffff0000u); }

__device__ __forceinline__ void mma16816(float* c, uint32_t a0, uint32_t a1,
                                         uint32_t a2, uint32_t a3,
                                         uint32_t b0, uint32_t b1) {
    asm volatile(
        "mma.sync.aligned.m16n8k16.row.col.f32.bf16.bf16.f32 "
        "{%0,%1,%2,%3},{%4,%5,%6,%7},{%8,%9},{%0,%1,%2,%3};"
        : "+f"(c[0]), "+f"(c[1]), "+f"(c[2]), "+f"(c[3])
        : "r"(a0), "r"(a1), "r"(a2), "r"(a3), "r"(b0), "r"(b1));
}

// ---- cp.async ----
__device__ __forceinline__ void cpa16(uint32_t dst_smem, const void* src) {
    asm volatile("cp.async.cg.shared.global [%0], [%1], 16;"
                 :: "r"(dst_smem), "l"(src));
}
__device__ __forceinline__ void cpa_commit() {
    asm volatile("cp.async.commit_group;");
}
__device__ __forceinline__ void cpa_wait1() {
    asm volatile("cp.async.wait_group 1;");
}
__device__ __forceinline__ void cpa_wait0() {
    asm volatile("cp.async.wait_group 0;");
}
__device__ __forceinline__ uint32_t smem_u32(const void* p) {
    return (uint32_t)__cvta_generic_to_shared(p);
}

// ---------------------------------------------------------------------------
// Split x -> bf16 hi/lo pairs
// ---------------------------------------------------------------------------
__global__ void __launch_bounds__(256) convert_x_kernel(const float* __restrict__ x)
{
    const long i = (long)blockIdx.x * 256 + threadIdx.x;
    float2 v = ((const float2*)x)[i];
    uint32_t hi = cvt2(v.x, v.y);
    g_Xh[i] = hi;
    g_Xl[i] = cvt2(v.x - lo16f(hi), v.y - hi16f(hi));
}

// ---------------------------------------------------------------------------
// Transpose + split weights: W[K][N] -> Wt[N][K] hi/lo
// ---------------------------------------------------------------------------
__global__ void __launch_bounds__(256) convert_w_kernel(
    const float* __restrict__ W, uint32_t* __restrict__ WtH,
    uint32_t* __restrict__ WtL, int K, int N)
{
    __shared__ float sT[32][33];
    const int k0 = blockIdx.y * 32, n0 = blockIdx.x * 32;
    const int tid = threadIdx.x;
    const int tx = tid & 31, ty = tid >> 5;
    #pragma unroll
    for (int i = 0; i < 4; i++)
        sT[ty + i * 8][tx] = W[(long)(k0 + ty + i * 8) * N + n0 + tx];
    __syncthreads();

    const int nr = tid >> 3;
    const int kc = tid & 7;
    #pragma unroll
    for (int i = 0; i < 2; i++) {
        int kk = kc + i * 8;
        float x0 = sT[2 * kk][nr], x1 = sT[2 * kk + 1][nr];
        uint32_t whi = cvt2(x0, x1);
        uint32_t wlo = cvt2(x0 - lo16f(whi), x1 - hi16f(whi));
        long o = (long)(n0 + nr) * (K / 2) + k0 / 2 + kk;
        WtH[o] = whi;
        WtL[o] = wlo;
    }
}

// ---------------------------------------------------------------------------
// Tensor-core GEMM, bf16 x3-split, cp.async double-buffered,
// PASS-MAJOR mma order: 16 independent accumulator chains per pass.
// ---------------------------------------------------------------------------
__global__ void __launch_bounds__(256, 2) gemm_tc_kernel(
    const uint4* __restrict__ Ah, const uint4* __restrict__ Al,
    const uint4* __restrict__ Bh, const uint4* __restrict__ Bl,
    const float* __restrict__ bias, float* __restrict__ C,
    int M, int N, int K)
{
    __shared__ __align__(16) __nv_bfloat16 sA[2][2][128][24];
    __shared__ __align__(16) __nv_bfloat16 sB[2][2][128][24];

    const int tid = threadIdx.x;
    const int wid = tid >> 5;
    const int lane = tid & 31;
    const int g = lane >> 2;
    const int t4 = lane & 3;
    const int wr = wid >> 2;
    const int wc = wid & 3;

    const int m0 = blockIdx.y * 128;
    const int n0 = blockIdx.x * 128;
    const int row = tid >> 1;
    const int half = tid & 1;
    const int Ku4 = K >> 3;

    const uint4* pAh = Ah + (long)(m0 + row) * Ku4 + half;
    const uint4* pAl = Al + (long)(m0 + row) * Ku4 + half;
    const uint4* pBh = Bh + (long)(n0 + row) * Ku4 + half;
    const uint4* pBl = Bl + (long)(n0 + row) * Ku4 + half;

    const uint32_t dAh0 = smem_u32(&sA[0][0][row][half * 8]);
    const uint32_t dAl0 = smem_u32(&sA[0][1][row][half * 8]);
    const uint32_t dBh0 = smem_u32(&sB[0][0][row][half * 8]);
    const uint32_t dBl0 = smem_u32(&sB[0][1][row][half * 8]);
    const uint32_t stB = 2 * 2 * 128 * 24;

    float acc[4][4][4];
    #pragma unroll
    for (int mt = 0; mt < 4; mt++)
        #pragma unroll
        for (int nt = 0; nt < 4; nt++)
            #pragma unroll
            for (int j = 0; j < 4; j++) acc[mt][nt][j] = 0.f;

    const int NIT = K / 16;
    cpa16(dAh0, pAh); cpa16(dAl0, pAl);
    cpa16(dBh0, pBh); cpa16(dBl0, pBl);
    cpa_commit();

    for (int it = 0; it < NIT; it++) {
        if (it + 1 < NIT) {
            uint32_t so = ((it + 1) & 1) * stB;
            cpa16(dAh0 + so, pAh + (it + 1) * 2);
            cpa16(dAl0 + so, pAl + (it + 1) * 2);
            cpa16(dBh0 + so, pBh + (it + 1) * 2);
            cpa16(dBl0 + so, pBl + (it + 1) * 2);
            cpa_commit();
            cpa_wait1();
        } else {
            cpa_wait0();
        }
        __syncthreads();

        const int st = it & 1;
        const uint32_t* sA0 = (const uint32_t*)sA[st][0];
        const uint32_t* sA1 = (const uint32_t*)sA[st][1];
        const uint32_t* sB0 = (const uint32_t*)sB[st][0];
        const uint32_t* sB1 = (const uint32_t*)sB[st][1];

        // B frags: hi and lo
        uint32_t bfh[4][2], bfl[4][2];
        #pragma unroll
        for (int nt = 0; nt < 4; nt++) {
            int n = wc * 32 + nt * 8 + g;
            bfh[nt][0] = sB0[n * 12 + t4];
            bfh[nt][1] = sB0[n * 12 + t4 + 4];
            bfl[nt][0] = sB1[n * 12 + t4];
            bfl[nt][1] = sB1[n * 12 + t4 + 4];
        }
        // A hi frags
        uint32_t af[4][4];
        #pragma unroll
        for (int mt = 0; mt < 4; mt++) {
            int r0 = (wr * 64 + mt * 16 + g) * 12;
            int r1 = r0 + 8 * 12;
            af[mt][0] = sA0[r0 + t4];     af[mt][1] = sA0[r1 + t4];
            af[mt][2] = sA0[r0 + t4 + 4]; af[mt][3] = sA0[r1 + t4 + 4];
        }
        // pass 0: hi*hi — 16 independent chains
        #pragma unroll
        for (int mt = 0; mt < 4; mt++)
            #pragma unroll
            for (int nt = 0; nt < 4; nt++)
                mma16816(acc[mt][nt], af[mt][0], af[mt][1], af[mt][2], af[mt][3],
                         bfh[nt][0], bfh[nt][1]);
        // pass 1: hi*lo
        #pragma unroll
        for (int mt = 0; mt < 4; mt++)
            #pragma unroll
            for (int nt = 0; nt < 4; nt++)
                mma16816(acc[mt][nt], af[mt][0], af[mt][1], af[mt][2], af[mt][3],
                         bfl[nt][0], bfl[nt][1]);
        // reload A frags with lo
        #pragma unroll
        for (int mt = 0; mt < 4; mt++) {
            int r0 = (wr * 64 + mt * 16 + g) * 12;
            int r1 = r0 + 8 * 12;
            af[mt][0] = sA1[r0 + t4];     af[mt][1] = sA1[r1 + t4];
            af[mt][2] = sA1[r0 + t4 + 4]; af[mt][3] = sA1[r1 + t4 + 4];
        }
        // pass 2: lo*hi
        #pragma unroll
        for (int mt = 0; mt < 4; mt++)
            #pragma unroll
            for (int nt = 0; nt < 4; nt++)
                mma16816(acc[mt][nt], af[mt][0], af[mt][1], af[mt][2], af[mt][3],
                         bfh[nt][0], bfh[nt][1]);
        __syncthreads();
    }

    #pragma unroll
    for (int mt = 0; mt < 4; mt++) {
        int r = m0 + wr * 64 + mt * 16 + g;
        #pragma unroll
        for (int nt = 0; nt < 4; nt++) {
            int c = n0 + wc * 32 + nt * 8 + 2 * t4;
            float b0 = bias[c], b1 = bias[c + 1];
            *(float2*)&C[(long)r * N + c] =
                make_float2(acc[mt][nt][0] + b0, acc[mt][nt][1] + b1);
            *(float2*)&C[(long)(r + 8) * N + c] =
                make_float2(acc[mt][nt][2] + b0, acc[mt][nt][3] + b1);
        }
    }
}

// ---------------------------------------------------------------------------
// Split Q (pre-scaled) and K into bf16 hi/lo
// ---------------------------------------------------------------------------
__global__ void __launch_bounds__(256) convert_qk_kernel()
{
    const int idx = blockIdx.x * 256 + threadIdx.x;
    const int row = idx / DIMV;
    const int c   = idx - row * DIMV;
    const int h   = c / PH;
    const int d   = c - h * PH;
    const long base = (long)row * NQKV + h * (3 * PH) + d;

    float q = g_qkv[base] * SCALE;
    float k = g_qkv[base + PH];

    __nv_bfloat16 qh = __float2bfloat16(q);
    g_Qh[idx] = qh;
    g_Ql[idx] = __float2bfloat16(q - __bfloat162float(qh));
    __nv_bfloat16 kh = __float2bfloat16(k);
    g_Kh[idx] = kh;
    g_Kl[idx] = __float2bfloat16(k - __bfloat162float(kh));
}

// ---------------------------------------------------------------------------
// V -> transposed bf16 hi/lo
// ---------------------------------------------------------------------------
__global__ void __launch_bounds__(256) convert_v_kernel()
{
    __shared__ float sv[PH][65];

    const int tb = blockIdx.x;
    const int bh = blockIdx.y;
    const int b = bh >> 4;
    const int h = bh & 15;
    const int tid = threadIdx.x;

    const int tl = tid >> 2;
    const int dp = (tid & 3) * 12;
    const long rbase = (long)(b * TSEQ + tb * 64 + tl) * NQKV + h * (3 * PH) + 2 * PH + dp;
    #pragma unroll
    for (int j = 0; j < 12; j++)
        sv[dp + j][tl] = g_qkv[rbase + j];
    __syncthreads();

    uint32_t* Vh32 = (uint32_t*)g_Vth;
    uint32_t* Vl32 = (uint32_t*)g_Vtl;
    const long obase = ((long)bh * PH * TSEQ) / 2;
    #pragma unroll
    for (int i = 0; i < 6; i++) {
        int tau = tid + 256 * i;
        int d = tau >> 5;
        int j = tau & 31;
        float x0 = sv[d][2 * j];
        float x1 = sv[d][2 * j + 1];
        uint32_t whi = cvt2(x0, x1);
        uint32_t wlo = cvt2(x0 - lo16f(whi), x1 - hi16f(whi));
        long o = obase + (long)d * (TSEQ / 2) + tb * 32 + j;
        Vh32[o] = whi;
        Vl32[o] = wlo;
    }
}

// ---------------------------------------------------------------------------
// Flash attention, mma.sync bf16 x3, cp.async double-buffered, pass-major mma.
// ---------------------------------------------------------------------------
#define SK_STAGE (2 * 64 * 56)
#define SV_STAGE (2 * 48 * 72)
#define ATTN_SMEM ((2 * SK_STAGE + 2 * SV_STAGE) * 2)   // bytes = 56320

__global__ void __launch_bounds__(256, 2) attn_mma_kernel()
{
    extern __shared__ __align__(16) __nv_bfloat16 dyn[];
    __nv_bfloat16* sKb = dyn;
    __nv_bfloat16* sVb = dyn + 2 * SK_STAGE;

    const int tid = threadIdx.x;
    const int wid = tid >> 5;
    const int lane = tid & 31;
    const int g = lane >> 2;
    const int t4 = lane & 3;

    const int bh = blockIdx.y;
    const int b = bh >> 4;
    const int h = bh & 15;
    const int qr0 = blockIdx.x * 128 + wid * 16;
    const long rowg  = (long)b * TSEQ + qr0 + g;
    const long rowg8 = rowg + 8;

    int kArr[3], kKey[3], kC[3], vArr[3], vD[3], vC[3];
    #pragma unroll
    for (int i = 0; i < 3; i++) {
        int tau = tid + 256 * i;
        kArr[i] = tau / 384;
        int rem = tau - kArr[i] * 384;
        kKey[i] = rem / 6;
        kC[i] = rem - kKey[i] * 6;
        vArr[i] = tau / 384;
        vD[i] = rem >> 3;
        vC[i] = rem & 7;
    }

    auto load_tile = [&](int kb, int st) {
        #pragma unroll
        for (int i = 0; i < 3; i++) {
            const __nv_bfloat16* src = (kArr[i] ? g_Kl : g_Kh)
                + (long)(b * TSEQ + kb + kKey[i]) * DIMV + h * PH + kC[i] * 8;
            uint32_t dst = smem_u32(sKb + (st * 2 + kArr[i]) * (64 * 56)
                                    + kKey[i] * 56 + kC[i] * 8);
            cpa16(dst, src);
        }
        #pragma unroll
        for (int i = 0; i < 3; i++) {
            const __nv_bfloat16* src = (vArr[i] ? g_Vtl : g_Vth)
                + (long)bh * (PH * TSEQ) + vD[i] * TSEQ + kb + vC[i] * 8;
            uint32_t dst = smem_u32(sVb + (st * 2 + vArr[i]) * (48 * 72)
                                    + vD[i] * 72 + vC[i] * 8);
            cpa16(dst, src);
        }
        cpa_commit();
    };

    const uint32_t* Qh32 = (const uint32_t*)g_Qh;
    const uint32_t* Ql32 = (const uint32_t*)g_Ql;
    uint32_t qh[3][4], ql[3][4];
    #pragma unroll
    for (int kk = 0; kk < 3; kk++) {
        long o0 = rowg  * 384 + h * 24 + kk * 8 + t4;
        long o1 = rowg8 * 384 + h * 24 + kk * 8 + t4;
        qh[kk][0] = Qh32[o0];     qh[kk][1] = Qh32[o1];
        qh[kk][2] = Qh32[o0 + 4]; qh[kk][3] = Qh32[o1 + 4];
        ql[kk][0] = Ql32[o0];     ql[kk][1] = Ql32[o1];
        ql[kk][2] = Ql32[o0 + 4]; ql[kk][3] = Ql32[o1 + 4];
    }

    float O[6][4];
    #pragma unroll
    for (int i = 0; i < 6; i++)
        #pragma unroll
        for (int j = 0; j < 4; j++) O[i][j] = 0.f;
    float m0 = -1e30f, m1 = -1e30f, l0 = 0.f, l1 = 0.f;

    load_tile(0, 0);

    const int NT = TSEQ / 64;
    for (int t = 0; t < NT; t++) {
        if (t + 1 < NT) {
            load_tile((t + 1) * 64, (t + 1) & 1);
            cpa_wait1();
        } else {
            cpa_wait0();
        }
        __syncthreads();

        const int st = t & 1;
        const __nv_bfloat16* sK0 = sKb + (st * 2 + 0) * (64 * 56);
        const __nv_bfloat16* sK1 = sKb + (st * 2 + 1) * (64 * 56);
        const __nv_bfloat16* sV0 = sVb + (st * 2 + 0) * (48 * 72);
        const __nv_bfloat16* sV1 = sVb + (st * 2 + 1) * (48 * 72);

        float S[8][4];
        #pragma unroll
        for (int n = 0; n < 8; n++)
            #pragma unroll
            for (int j = 0; j < 4; j++) S[n][j] = 0.f;

        // QK^T, pass-major: 8 independent chains per pass
        #pragma unroll
        for (int kk = 0; kk < 3; kk++) {
            uint32_t kf[8][2];
            #pragma unroll
            for (int n = 0; n < 8; n++) {
                const uint32_t* kh = (const uint32_t*)(sK0 + (n * 8 + g) * 56 + kk * 16 + 2 * t4);
                kf[n][0] = kh[0]; kf[n][1] = kh[4];
            }
            #pragma unroll
            for (int n = 0; n < 8; n++)
                mma16816(S[n], qh[kk][0], qh[kk][1], qh[kk][2], qh[kk][3], kf[n][0], kf[n][1]);
            #pragma unroll
            for (int n = 0; n < 8; n++)
                mma16816(S[n], ql[kk][0], ql[kk][1], ql[kk][2], ql[kk][3], kf[n][0], kf[n][1]);
            #pragma unroll
            for (int n = 0; n < 8; n++) {
                const uint32_t* kl = (const uint32_t*)(sK1 + (n * 8 + g) * 56 + kk * 16 + 2 * t4);
                kf[n][0] = kl[0]; kf[n][1] = kl[4];
            }
            #pragma unroll
            for (int n = 0; n < 8; n++)
                mma16816(S[n], qh[kk][0], qh[kk][1], qh[kk][2], qh[kk][3], kf[n][0], kf[n][1]);
        }

        float rmax0 = -1e30f, rmax1 = -1e30f;
        #pragma unroll
        for (int n = 0; n < 8; n++) {
            rmax0 = fmaxf(rmax0, fmaxf(S[n][0], S[n][1]));
            rmax1 = fmaxf(rmax1, fmaxf(S[n][2], S[n][3]));
        }
        rmax0 = fmaxf(rmax0, __shfl_xor_sync(0xffffffffu, rmax0, 1));
        rmax0 = fmaxf(rmax0, __shfl_xor_sync(0xffffffffu, rmax0, 2));
        rmax1 = fmaxf(rmax1, __shfl_xor_sync(0xffffffffu, rmax1, 1));
        rmax1 = fmaxf(rmax1, __shfl_xor_sync(0xffffffffu, rmax1, 2));

        float mn0 = fmaxf(m0, rmax0);
        float mn1 = fmaxf(m1, rmax1);
        float corr0 = __expf(m0 - mn0);
        float corr1 = __expf(m1 - mn1);
        m0 = mn0; m1 = mn1;
        l0 *= corr0; l1 *= corr1;
        #pragma unroll
        for (int nd = 0; nd < 6; nd++) {
            O[nd][0] *= corr0; O[nd][1] *= corr0;
            O[nd][2] *= corr1; O[nd][3] *= corr1;
        }

        float ps0 = 0.f, ps1 = 0.f;
        #pragma unroll
        for (int n = 0; n < 8; n++) {
            S[n][0] = __expf(S[n][0] - m0);
            S[n][1] = __expf(S[n][1] - m0);
            S[n][2] = __expf(S[n][2] - m1);
            S[n][3] = __expf(S[n][3] - m1);
            ps0 += S[n][0] + S[n][1];
            ps1 += S[n][2] + S[n][3];
        }
        ps0 += __shfl_xor_sync(0xffffffffu, ps0, 1);
        ps0 += __shfl_xor_sync(0xffffffffu, ps0, 2);
        ps1 += __shfl_xor_sync(0xffffffffu, ps1, 1);
        ps1 += __shfl_xor_sync(0xffffffffu, ps1, 2);
        l0 += ps0; l1 += ps1;

        // PV, pass-major: 6 independent chains per pass
        #pragma unroll
        for (int kk = 0; kk < 4; kk++) {
            uint32_t ph[4], pl[4];
            #pragma unroll
            for (int half = 0; half < 2; half++) {
                const float* Sc = S[2 * kk + half];
                uint32_t w0 = cvt2(Sc[0], Sc[1]);
                uint32_t w1 = cvt2(Sc[2], Sc[3]);
                ph[2 * half + 0] = w0;
                ph[2 * half + 1] = w1;
                pl[2 * half + 0] = cvt2(Sc[0] - lo16f(w0), Sc[1] - hi16f(w0));
                pl[2 * half + 1] = cvt2(Sc[2] - lo16f(w1), Sc[3] - hi16f(w1));
            }
            uint32_t vf[6][2];
            #pragma unroll
            for (int nd = 0; nd < 6; nd++) {
                const uint32_t* vh = (const uint32_t*)(sV0 + (nd * 8 + g) * 72 + kk * 16 + 2 * t4);
                vf[nd][0] = vh[0]; vf[nd][1] = vh[4];
            }
            #pragma unroll
            for (int nd = 0; nd < 6; nd++)
                mma16816(O[nd], ph[0], ph[1], ph[2], ph[3], vf[nd][0], vf[nd][1]);
            #pragma unroll
            for (int nd = 0; nd < 6; nd++)
                mma16816(O[nd], pl[0], pl[1], pl[2], pl[3], vf[nd][0], vf[nd][1]);
            #pragma unroll
            for (int nd = 0; nd < 6; nd++) {
                const uint32_t* vl = (const uint32_t*)(sV1 + (nd * 8 + g) * 72 + kk * 16 + 2 * t4);
                vf[nd][0] = vl[0]; vf[nd][1] = vl[4];
            }
            #pragma unroll
            for (int nd = 0; nd < 6; nd++)
                mma16816(O[nd], ph[0], ph[1], ph[2], ph[3], vf[nd][0], vf[nd][1]);
        }
        __syncthreads();
    }

    const float invl0 = 1.0f / l0;
    const float invl1 = 1.0f / l1;
    #pragma unroll
    for (int nd = 0; nd < 6; nd++) {
        long c = h * PH + nd * 8 + 2 * t4;
        float v0x = O[nd][0] * invl0, v0y = O[nd][1] * invl0;
        float v1x = O[nd][2] * invl1, v1y = O[nd][3] * invl1;
        uint32_t h0 = cvt2(v0x, v0y);
        uint32_t h1 = cvt2(v1x, v1y);
        long i0 = (rowg  * DIMV + c) >> 1;
        long i1 = (rowg8 * DIMV + c) >> 1;
        g_AttH[i0] = h0;
        g_AttL[i0] = cvt2(v0x - lo16f(h0), v0y - hi16f(h0));
        g_AttH[i1] = h1;
        g_AttL[i1] = cvt2(v1x - lo16f(h1), v1y - hi16f(h1));
    }
}

// ---------------------------------------------------------------------------
extern "C" void kernel_launch(void* const* d_in, const int* in_sizes, int n_in,
                              void* d_out, int out_size)
{
    const float* x     = (const float*)d_in[0];
    const float* w_in  = (const float*)d_in[1];
    const float* b_in  = (const float*)d_in[2];
    const float* w_out = (const float*)d_in[3];
    const float* b_out = (const float*)d_in[4];
    float* out = (float*)d_out;

    static bool attr_set = false;
    if (!attr_set) {
        cudaFuncSetAttribute(attn_mma_kernel,
                             cudaFuncAttributeMaxDynamicSharedMemorySize, ATTN_SMEM);
        attr_set = true;
    }

    float* qkv = nullptr;
    cudaGetSymbolAddress((void**)&qkv, g_qkv);
    uint32_t *Xh, *Xl, *WinTh, *WinTl, *WoutTh, *WoutTl, *AttH, *AttL;
    cudaGetSymbolAddress((void**)&Xh, g_Xh);
    cudaGetSymbolAddress((void**)&Xl, g_Xl);
    cudaGetSymbolAddress((void**)&WinTh, g_WinTh);
    cudaGetSymbolAddress((void**)&WinTl, g_WinTl);
    cudaGetSymbolAddress((void**)&WoutTh, g_WoutTh);
    cudaGetSymbolAddress((void**)&WoutTl, g_WoutTl);
    cudaGetSymbolAddress((void**)&AttH, g_AttH);
    cudaGetSymbolAddress((void**)&AttL, g_AttL);

    convert_x_kernel<<<(MTOT * DIMV / 2) / 256, 256>>>(x);
    {
        dim3 grid(NQKV / 32, DIMV / 32);
        convert_w_kernel<<<grid, 256>>>(w_in, WinTh, WinTl, DIMV, NQKV);
    }
    {
        dim3 grid(DIMV / 32, DIMV / 32);
        convert_w_kernel<<<grid, 256>>>(w_out, WoutTh, WoutTl, DIMV, DIMV);
    }

    {
        dim3 grid(NQKV / 128, MTOT / 128);
        gemm_tc_kernel<<<grid, 256>>>((const uint4*)Xh, (const uint4*)Xl,
                                      (const uint4*)WinTh, (const uint4*)WinTl,
                                      b_in, qkv, MTOT, NQKV, DIMV);
    }

    convert_qk_kernel<<<(MTOT * DIMV) / 256, 256>>>();
    {
        dim3 grid(TSEQ / 64, 64);
        convert_v_kernel<<<grid, 256>>>();
    }

    {
        dim3 grid(TSEQ / 128, 64);
        attn_mma_kernel<<<grid, 256, ATTN_SMEM>>>();
    }

    {
        dim3 grid(DIMV / 128, MTOT / 128);
        gemm_tc_kernel<<<grid, 256>>>((const uint4*)AttH, (const uint4*)AttL,
                                      (const uint4*)WoutTh, (const uint4*)WoutTl,
                                      b_out, out, MTOT, DIMV, DIMV);
    }
}

// round 11
// speedup vs baseline: 4.2554x; 1.3825x over previous
#include <cuda_runtime.h>
#include <cuda_fp16.h>
#include <cstdint>

#define DIMV 768
#define NHEAD 16
#define PH 48
#define BATCH 4
#define TSEQ 2048
#define MTOT (BATCH * TSEQ)   // 8192
#define NQKV (3 * DIMV)       // 2304
#define SCALE 0.14433756729740643f   // 1/sqrt(48)

// Scratch (allocation-free rule: __device__ globals)
__device__ float g_qkv[MTOT * NQKV];
__device__ uint32_t g_Xh[MTOT * DIMV / 2];       // x rounded fp16 (packed pairs)
__device__ uint32_t g_WinTh[NQKV * DIMV / 2];    // w_in^T split hi/lo fp16
__device__ uint32_t g_WinTl[NQKV * DIMV / 2];
__device__ uint32_t g_WoutTh[DIMV * DIMV / 2];
__device__ uint32_t g_WoutTl[DIMV * DIMV / 2];
__device__ uint32_t g_AttH[MTOT * DIMV / 2];     // attn out rounded fp16
__device__ __half g_Qh[MTOT * DIMV];             // q*scale split hi/lo
__device__ __half g_Ql[MTOT * DIMV];
__device__ __half g_Kh[MTOT * DIMV];             // k rounded
__device__ __half g_Vth[64 * PH * TSEQ];         // v transposed rounded [bh][d][t]

// ---- fp16 helpers ----
// pack (lo,hi) floats -> fp16x2 with first arg in LOW half
__device__ __forceinline__ uint32_t pkh2(float lo, float hi) {
    uint32_t r;
    asm("cvt.rn.f16x2.f32 %0, %1, %2;" : "=r"(r) : "f"(hi), "f"(lo));
    return r;
}
__device__ __forceinline__ float lo16h(uint32_t v) {
    return __half2float(__ushort_as_half((unsigned short)(v & 0xffffu)));
}
__device__ __forceinline__ float hi16h(uint32_t v) {
    return __half2float(__ushort_as_half((unsigned short)(v >> 16)));
}

// ---- fp16 m16n8k16 mma, fp32 accum ----
__device__ __forceinline__ void mma16816h(float* c, uint32_t a0, uint32_t a1,
                                          uint32_t a2, uint32_t a3,
                                          uint32_t b0, uint32_t b1) {
    asm volatile(
        "mma.sync.aligned.m16n8k16.row.col.f32.f16.f16.f32 "
        "{%0,%1,%2,%3},{%4,%5,%6,%7},{%8,%9},{%0,%1,%2,%3};"
        : "+f"(c[0]), "+f"(c[1]), "+f"(c[2]), "+f"(c[3])
        : "r"(a0), "r"(a1), "r"(a2), "r"(a3), "r"(b0), "r"(b1));
}

// ---- cp.async ----
__device__ __forceinline__ void cpa16(uint32_t dst_smem, const void* src) {
    asm volatile("cp.async.cg.shared.global [%0], [%1], 16;"
                 :: "r"(dst_smem), "l"(src));
}
__device__ __forceinline__ void cpa_commit() {
    asm volatile("cp.async.commit_group;");
}
__device__ __forceinline__ void cpa_wait1() {
    asm volatile("cp.async.wait_group 1;");
}
__device__ __forceinline__ void cpa_wait0() {
    asm volatile("cp.async.wait_group 0;");
}
__device__ __forceinline__ uint32_t smem_u32(const void* p) {
    return (uint32_t)__cvta_generic_to_shared(p);
}

// ---------------------------------------------------------------------------
// x -> rounded fp16 pairs
// ---------------------------------------------------------------------------
__global__ void __launch_bounds__(256) convert_x_kernel(const float* __restrict__ x)
{
    const long i = (long)blockIdx.x * 256 + threadIdx.x;
    float2 v = ((const float2*)x)[i];
    g_Xh[i] = pkh2(v.x, v.y);
}

// ---------------------------------------------------------------------------
// Transpose + SPLIT weights: W[K][N] fp32 -> Wt[N][K] fp16 hi/lo pairs
// ---------------------------------------------------------------------------
__global__ void __launch_bounds__(256) convert_w_kernel(
    const float* __restrict__ W, uint32_t* __restrict__ WtH,
    uint32_t* __restrict__ WtL, int K, int N)
{
    __shared__ float sT[32][33];
    const int k0 = blockIdx.y * 32, n0 = blockIdx.x * 32;
    const int tid = threadIdx.x;
    const int tx = tid & 31, ty = tid >> 5;
    #pragma unroll
    for (int i = 0; i < 4; i++)
        sT[ty + i * 8][tx] = W[(long)(k0 + ty + i * 8) * N + n0 + tx];
    __syncthreads();

    const int nr = tid >> 3;
    const int kc = tid & 7;
    #pragma unroll
    for (int i = 0; i < 2; i++) {
        int kk = kc + i * 8;
        float x0 = sT[2 * kk][nr], x1 = sT[2 * kk + 1][nr];
        uint32_t whi = pkh2(x0, x1);
        uint32_t wlo = pkh2(x0 - lo16h(whi), x1 - hi16h(whi));
        long o = (long)(n0 + nr) * (K / 2) + k0 / 2 + kk;
        WtH[o] = whi;
        WtL[o] = wlo;
    }
}

// ---------------------------------------------------------------------------
// Tensor-core GEMM fp16 x2: C = A Bt^T + bias. A rounded fp16 (single),
// B split hi/lo fp16. cp.async double-buffered, pass-major issue.
// BM=BN=128, BK=16, 256 threads, warp tile 64x32.
// ---------------------------------------------------------------------------
__global__ void __launch_bounds__(256, 2) gemm_tc_kernel(
    const uint4* __restrict__ A,
    const uint4* __restrict__ Bh, const uint4* __restrict__ Bl,
    const float* __restrict__ bias, float* __restrict__ C,
    int M, int N, int K)
{
    __shared__ __align__(16) __half sA[2][128][24];       // [stage][m][k]
    __shared__ __align__(16) __half sB[2][2][128][24];    // [stage][hi/lo][n][k]

    const int tid = threadIdx.x;
    const int wid = tid >> 5;
    const int lane = tid & 31;
    const int g = lane >> 2;
    const int t4 = lane & 3;
    const int wr = wid >> 2;
    const int wc = wid & 3;

    const int m0 = blockIdx.y * 128;
    const int n0 = blockIdx.x * 128;
    const int row = tid >> 1;
    const int half = tid & 1;
    const int Ku4 = K >> 3;

    const uint4* pA  = A  + (long)(m0 + row) * Ku4 + half;
    const uint4* pBh = Bh + (long)(n0 + row) * Ku4 + half;
    const uint4* pBl = Bl + (long)(n0 + row) * Ku4 + half;

    const uint32_t dA0  = smem_u32(&sA[0][row][half * 8]);
    const uint32_t dBh0 = smem_u32(&sB[0][0][row][half * 8]);
    const uint32_t dBl0 = smem_u32(&sB[0][1][row][half * 8]);
    const uint32_t stA = 128 * 24 * 2;        // bytes per A stage
    const uint32_t stB = 2 * 128 * 24 * 2;    // bytes per B stage

    float acc[4][4][4];
    #pragma unroll
    for (int mt = 0; mt < 4; mt++)
        #pragma unroll
        for (int nt = 0; nt < 4; nt++)
            #pragma unroll
            for (int j = 0; j < 4; j++) acc[mt][nt][j] = 0.f;

    const int NIT = K / 16;
    cpa16(dA0, pA); cpa16(dBh0, pBh); cpa16(dBl0, pBl);
    cpa_commit();

    for (int it = 0; it < NIT; it++) {
        if (it + 1 < NIT) {
            uint32_t s = (it + 1) & 1;
            cpa16(dA0  + s * stA, pA  + (it + 1) * 2);
            cpa16(dBh0 + s * stB, pBh + (it + 1) * 2);
            cpa16(dBl0 + s * stB, pBl + (it + 1) * 2);
            cpa_commit();
            cpa_wait1();
        } else {
            cpa_wait0();
        }
        __syncthreads();

        const int st = it & 1;
        const uint32_t* sA0 = (const uint32_t*)sA[st];
        const uint32_t* sB0 = (const uint32_t*)sB[st][0];
        const uint32_t* sB1 = (const uint32_t*)sB[st][1];

        uint32_t bfh[4][2], bfl[4][2];
        #pragma unroll
        for (int nt = 0; nt < 4; nt++) {
            int n = wc * 32 + nt * 8 + g;
            bfh[nt][0] = sB0[n * 12 + t4];
            bfh[nt][1] = sB0[n * 12 + t4 + 4];
            bfl[nt][0] = sB1[n * 12 + t4];
            bfl[nt][1] = sB1[n * 12 + t4 + 4];
        }
        uint32_t af[4][4];
        #pragma unroll
        for (int mt = 0; mt < 4; mt++) {
            int r0 = (wr * 64 + mt * 16 + g) * 12;
            int r1 = r0 + 8 * 12;
            af[mt][0] = sA0[r0 + t4];     af[mt][1] = sA0[r1 + t4];
            af[mt][2] = sA0[r0 + t4 + 4]; af[mt][3] = sA0[r1 + t4 + 4];
        }
        // pass 0: a * b_hi (16 independent chains)
        #pragma unroll
        for (int mt = 0; mt < 4; mt++)
            #pragma unroll
            for (int nt = 0; nt < 4; nt++)
                mma16816h(acc[mt][nt], af[mt][0], af[mt][1], af[mt][2], af[mt][3],
                          bfh[nt][0], bfh[nt][1]);
        // pass 1: a * b_lo
        #pragma unroll
        for (int mt = 0; mt < 4; mt++)
            #pragma unroll
            for (int nt = 0; nt < 4; nt++)
                mma16816h(acc[mt][nt], af[mt][0], af[mt][1], af[mt][2], af[mt][3],
                          bfl[nt][0], bfl[nt][1]);
        __syncthreads();
    }

    #pragma unroll
    for (int mt = 0; mt < 4; mt++) {
        int r = m0 + wr * 64 + mt * 16 + g;
        #pragma unroll
        for (int nt = 0; nt < 4; nt++) {
            int c = n0 + wc * 32 + nt * 8 + 2 * t4;
            float b0 = bias[c], b1 = bias[c + 1];
            *(float2*)&C[(long)r * N + c] =
                make_float2(acc[mt][nt][0] + b0, acc[mt][nt][1] + b1);
            *(float2*)&C[(long)(r + 8) * N + c] =
                make_float2(acc[mt][nt][2] + b0, acc[mt][nt][3] + b1);
        }
    }
}

// ---------------------------------------------------------------------------
// Split Q (pre-scaled) into fp16 hi/lo; round K to fp16.
// ---------------------------------------------------------------------------
__global__ void __launch_bounds__(256) convert_qk_kernel()
{
    const int idx = blockIdx.x * 256 + threadIdx.x;
    const int row = idx / DIMV;
    const int c   = idx - row * DIMV;
    const int h   = c / PH;
    const int d   = c - h * PH;
    const long base = (long)row * NQKV + h * (3 * PH) + d;

    float q = g_qkv[base] * SCALE;
    __half qh = __float2half_rn(q);
    g_Qh[idx] = qh;
    g_Ql[idx] = __float2half_rn(q - __half2float(qh));
    g_Kh[idx] = __float2half_rn(g_qkv[base + PH]);
}

// ---------------------------------------------------------------------------
// V -> transposed rounded fp16: g_Vth[bh][d][t]
// ---------------------------------------------------------------------------
__global__ void __launch_bounds__(256) convert_v_kernel()
{
    __shared__ float sv[PH][65];

    const int tb = blockIdx.x;
    const int bh = blockIdx.y;
    const int b = bh >> 4;
    const int h = bh & 15;
    const int tid = threadIdx.x;

    const int tl = tid >> 2;
    const int dp = (tid & 3) * 12;
    const long rbase = (long)(b * TSEQ + tb * 64 + tl) * NQKV + h * (3 * PH) + 2 * PH + dp;
    #pragma unroll
    for (int j = 0; j < 12; j++)
        sv[dp + j][tl] = g_qkv[rbase + j];
    __syncthreads();

    uint32_t* Vh32 = (uint32_t*)g_Vth;
    const long obase = ((long)bh * PH * TSEQ) / 2;
    #pragma unroll
    for (int i = 0; i < 6; i++) {
        int tau = tid + 256 * i;
        int d = tau >> 5;
        int j = tau & 31;
        Vh32[obase + (long)d * (TSEQ / 2) + tb * 32 + j] =
            pkh2(sv[d][2 * j], sv[d][2 * j + 1]);
    }
}

// ---------------------------------------------------------------------------
// Flash attention, fp16 x2: Q split / K rounded, P split / V rounded.
// cp.async double-buffered; pass-major mma.
//   per stage: K [64][56] + V [48][72] fp16 = 7040 elems = 14080 B
// ---------------------------------------------------------------------------
#define SK_ELEMS (64 * 56)                 // 3584
#define STAGE_ELEMS (SK_ELEMS + 48 * 72)   // 7040
#define ATTN_SMEM (2 * STAGE_ELEMS * 2)    // 28160 bytes

__global__ void __launch_bounds__(256, 2) attn_mma_kernel()
{
    extern __shared__ __align__(16) __half dyn[];

    const int tid = threadIdx.x;
    const int wid = tid >> 5;
    const int lane = tid & 31;
    const int g = lane >> 2;
    const int t4 = lane & 3;

    const int bh = blockIdx.y;
    const int b = bh >> 4;
    const int h = bh & 15;
    const int qr0 = blockIdx.x * 128 + wid * 16;
    const long rowg  = (long)b * TSEQ + qr0 + g;
    const long rowg8 = rowg + 8;

    auto load_tile = [&](int kb, int st) {
        __half* base = dyn + st * STAGE_ELEMS;
        #pragma unroll
        for (int i = 0; i < 3; i++) {
            int idx = tid + 256 * i;
            if (idx < 384) {                     // K: 64 rows x 6 chunks
                int key = idx / 6, c = idx - key * 6;
                const __half* src = g_Kh
                    + (long)(b * TSEQ + kb + key) * DIMV + h * PH + c * 8;
                cpa16(smem_u32(base + key * 56 + c * 8), src);
            } else {                             // V: 48 dims x 8 chunks
                int v = idx - 384;
                int d = v >> 3, c = v & 7;
                const __half* src = g_Vth
                    + (long)bh * (PH * TSEQ) + d * TSEQ + kb + c * 8;
                cpa16(smem_u32(base + SK_ELEMS + d * 72 + c * 8), src);
            }
        }
        cpa_commit();
    };

    const uint32_t* Qh32 = (const uint32_t*)g_Qh;
    const uint32_t* Ql32 = (const uint32_t*)g_Ql;
    uint32_t qh[3][4], ql[3][4];
    #pragma unroll
    for (int kk = 0; kk < 3; kk++) {
        long o0 = rowg  * 384 + h * 24 + kk * 8 + t4;
        long o1 = rowg8 * 384 + h * 24 + kk * 8 + t4;
        qh[kk][0] = Qh32[o0];     qh[kk][1] = Qh32[o1];
        qh[kk][2] = Qh32[o0 + 4]; qh[kk][3] = Qh32[o1 + 4];
        ql[kk][0] = Ql32[o0];     ql[kk][1] = Ql32[o1];
        ql[kk][2] = Ql32[o0 + 4]; ql[kk][3] = Ql32[o1 + 4];
    }

    float O[6][4];
    #pragma unroll
    for (int i = 0; i < 6; i++)
        #pragma unroll
        for (int j = 0; j < 4; j++) O[i][j] = 0.f;
    float m0 = -1e30f, m1 = -1e30f, l0 = 0.f, l1 = 0.f;

    load_tile(0, 0);

    const int NT = TSEQ / 64;
    for (int t = 0; t < NT; t++) {
        if (t + 1 < NT) {
            load_tile((t + 1) * 64, (t + 1) & 1);
            cpa_wait1();
        } else {
            cpa_wait0();
        }
        __syncthreads();

        const int st = t & 1;
        const __half* sK0 = dyn + st * STAGE_ELEMS;
        const __half* sV0 = sK0 + SK_ELEMS;

        float S[8][4];
        #pragma unroll
        for (int n = 0; n < 8; n++)
            #pragma unroll
            for (int j = 0; j < 4; j++) S[n][j] = 0.f;

        // QK^T: 2 passes (q_hi, q_lo) x rounded K
        #pragma unroll
        for (int kk = 0; kk < 3; kk++) {
            uint32_t kf[8][2];
            #pragma unroll
            for (int n = 0; n < 8; n++) {
                const uint32_t* kp = (const uint32_t*)(sK0 + (n * 8 + g) * 56 + kk * 16 + 2 * t4);
                kf[n][0] = kp[0]; kf[n][1] = kp[4];
            }
            #pragma unroll
            for (int n = 0; n < 8; n++)
                mma16816h(S[n], qh[kk][0], qh[kk][1], qh[kk][2], qh[kk][3], kf[n][0], kf[n][1]);
            #pragma unroll
            for (int n = 0; n < 8; n++)
                mma16816h(S[n], ql[kk][0], ql[kk][1], ql[kk][2], ql[kk][3], kf[n][0], kf[n][1]);
        }

        float rmax0 = -1e30f, rmax1 = -1e30f;
        #pragma unroll
        for (int n = 0; n < 8; n++) {
            rmax0 = fmaxf(rmax0, fmaxf(S[n][0], S[n][1]));
            rmax1 = fmaxf(rmax1, fmaxf(S[n][2], S[n][3]));
        }
        rmax0 = fmaxf(rmax0, __shfl_xor_sync(0xffffffffu, rmax0, 1));
        rmax0 = fmaxf(rmax0, __shfl_xor_sync(0xffffffffu, rmax0, 2));
        rmax1 = fmaxf(rmax1, __shfl_xor_sync(0xffffffffu, rmax1, 1));
        rmax1 = fmaxf(rmax1, __shfl_xor_sync(0xffffffffu, rmax1, 2));

        float mn0 = fmaxf(m0, rmax0);
        float mn1 = fmaxf(m1, rmax1);
        float corr0 = __expf(m0 - mn0);
        float corr1 = __expf(m1 - mn1);
        m0 = mn0; m1 = mn1;
        l0 *= corr0; l1 *= corr1;
        #pragma unroll
        for (int nd = 0; nd < 6; nd++) {
            O[nd][0] *= corr0; O[nd][1] *= corr0;
            O[nd][2] *= corr1; O[nd][3] *= corr1;
        }

        float ps0 = 0.f, ps1 = 0.f;
        #pragma unroll
        for (int n = 0; n < 8; n++) {
            S[n][0] = __expf(S[n][0] - m0);
            S[n][1] = __expf(S[n][1] - m0);
            S[n][2] = __expf(S[n][2] - m1);
            S[n][3] = __expf(S[n][3] - m1);
            ps0 += S[n][0] + S[n][1];
            ps1 += S[n][2] + S[n][3];
        }
        ps0 += __shfl_xor_sync(0xffffffffu, ps0, 1);
        ps0 += __shfl_xor_sync(0xffffffffu, ps0, 2);
        ps1 += __shfl_xor_sync(0xffffffffu, ps1, 1);
        ps1 += __shfl_xor_sync(0xffffffffu, ps1, 2);
        l0 += ps0; l1 += ps1;

        // PV: 2 passes (p_hi, p_lo) x rounded V
        #pragma unroll
        for (int kk = 0; kk < 4; kk++) {
            uint32_t ph[4], pl[4];
            #pragma unroll
            for (int half = 0; half < 2; half++) {
                const float* Sc = S[2 * kk + half];
                uint32_t w0 = pkh2(Sc[0], Sc[1]);
                uint32_t w1 = pkh2(Sc[2], Sc[3]);
                ph[2 * half + 0] = w0;
                ph[2 * half + 1] = w1;
                pl[2 * half + 0] = pkh2(Sc[0] - lo16h(w0), Sc[1] - hi16h(w0));
                pl[2 * half + 1] = pkh2(Sc[2] - lo16h(w1), Sc[3] - hi16h(w1));
            }
            uint32_t vf[6][2];
            #pragma unroll
            for (int nd = 0; nd < 6; nd++) {
                const uint32_t* vp = (const uint32_t*)(sV0 + (nd * 8 + g) * 72 + kk * 16 + 2 * t4);
                vf[nd][0] = vp[0]; vf[nd][1] = vp[4];
            }
            #pragma unroll
            for (int nd = 0; nd < 6; nd++)
                mma16816h(O[nd], ph[0], ph[1], ph[2], ph[3], vf[nd][0], vf[nd][1]);
            #pragma unroll
            for (int nd = 0; nd < 6; nd++)
                mma16816h(O[nd], pl[0], pl[1], pl[2], pl[3], vf[nd][0], vf[nd][1]);
        }
        __syncthreads();
    }

    // epilogue: rounded fp16 output (feeds split-W out-projection)
    const float invl0 = 1.0f / l0;
    const float invl1 = 1.0f / l1;
    #pragma unroll
    for (int nd = 0; nd < 6; nd++) {
        long c = h * PH + nd * 8 + 2 * t4;
        g_AttH[(rowg  * DIMV + c) >> 1] =
            pkh2(O[nd][0] * invl0, O[nd][1] * invl0);
        g_AttH[(rowg8 * DIMV + c) >> 1] =
            pkh2(O[nd][2] * invl1, O[nd][3] * invl1);
    }
}

// ---------------------------------------------------------------------------
extern "C" void kernel_launch(void* const* d_in, const int* in_sizes, int n_in,
                              void* d_out, int out_size)
{
    const float* x     = (const float*)d_in[0];
    const float* w_in  = (const float*)d_in[1];
    const float* b_in  = (const float*)d_in[2];
    const float* w_out = (const float*)d_in[3];
    const float* b_out = (const float*)d_in[4];
    float* out = (float*)d_out;

    float* qkv = nullptr;
    cudaGetSymbolAddress((void**)&qkv, g_qkv);
    uint32_t *Xh, *WinTh, *WinTl, *WoutTh, *WoutTl, *AttH;
    cudaGetSymbolAddress((void**)&Xh, g_Xh);
    cudaGetSymbolAddress((void**)&WinTh, g_WinTh);
    cudaGetSymbolAddress((void**)&WinTl, g_WinTl);
    cudaGetSymbolAddress((void**)&WoutTh, g_WoutTh);
    cudaGetSymbolAddress((void**)&WoutTl, g_WoutTl);
    cudaGetSymbolAddress((void**)&AttH, g_AttH);

    convert_x_kernel<<<(MTOT * DIMV / 2) / 256, 256>>>(x);
    {
        dim3 grid(NQKV / 32, DIMV / 32);
        convert_w_kernel<<<grid, 256>>>(w_in, WinTh, WinTl, DIMV, NQKV);
    }
    {
        dim3 grid(DIMV / 32, DIMV / 32);
        convert_w_kernel<<<grid, 256>>>(w_out, WoutTh, WoutTl, DIMV, DIMV);
    }

    // QKV projection (fp16 x2)
    {
        dim3 grid(NQKV / 128, MTOT / 128);
        gemm_tc_kernel<<<grid, 256>>>((const uint4*)Xh,
                                      (const uint4*)WinTh, (const uint4*)WinTl,
                                      b_in, qkv, MTOT, NQKV, DIMV);
    }

    convert_qk_kernel<<<(MTOT * DIMV) / 256, 256>>>();
    {
        dim3 grid(TSEQ / 64, 64);
        convert_v_kernel<<<grid, 256>>>();
    }

    // Attention (fp16 x2)
    {
        dim3 grid(TSEQ / 128, 64);
        attn_mma_kernel<<<grid, 256, ATTN_SMEM>>>();
    }

    // Output projection (fp16 x2)
    {
        dim3 grid(DIMV / 128, MTOT / 128);
        gemm_tc_kernel<<<grid, 256>>>((const uint4*)AttH,
                                      (const uint4*)WoutTh, (const uint4*)WoutTl,
                                      b_out, out, MTOT, DIMV, DIMV);
    }
}

// round 12
// speedup vs baseline: 4.6444x; 1.0914x over previous
#include <cuda_runtime.h>
#include <cuda_fp16.h>
#include <cstdint>

#define DIMV 768
#define NHEAD 16
#define PH 48
#define BATCH 4
#define TSEQ 2048
#define MTOT (BATCH * TSEQ)   // 8192
#define NQKV (3 * DIMV)       // 2304
#define SCALE 0.14433756729740643f   // 1/sqrt(48)

// Scratch (allocation-free rule: __device__ globals)
__device__ float g_qkv[MTOT * NQKV];
__device__ uint32_t g_Xh[MTOT * DIMV / 2];       // x rounded fp16 (packed pairs)
__device__ uint32_t g_WinTh[NQKV * DIMV / 2];    // w_in^T split hi/lo fp16
__device__ uint32_t g_WinTl[NQKV * DIMV / 2];
__device__ uint32_t g_WoutTh[DIMV * DIMV / 2];
__device__ uint32_t g_WoutTl[DIMV * DIMV / 2];
__device__ uint32_t g_AttH[MTOT * DIMV / 2];     // attn out rounded fp16
__device__ __half g_Qh[MTOT * DIMV];             // q*scale split hi/lo
__device__ __half g_Ql[MTOT * DIMV];
__device__ __half g_Kh[MTOT * DIMV];             // k rounded
__device__ __half g_Vth[64 * PH * TSEQ];         // v transposed rounded [bh][d][t]

// ---- fp16 helpers ----
__device__ __forceinline__ uint32_t pkh2(float lo, float hi) {
    uint32_t r;
    asm("cvt.rn.f16x2.f32 %0, %1, %2;" : "=r"(r) : "f"(hi), "f"(lo));
    return r;
}
__device__ __forceinline__ float lo16h(uint32_t v) {
    return __half2float(__ushort_as_half((unsigned short)(v & 0xffffu)));
}
__device__ __forceinline__ float hi16h(uint32_t v) {
    return __half2float(__ushort_as_half((unsigned short)(v >> 16)));
}

// ---- fp16 m16n8k16 mma, fp32 accum ----
__device__ __forceinline__ void mma16816h(float* c, uint32_t a0, uint32_t a1,
                                          uint32_t a2, uint32_t a3,
                                          uint32_t b0, uint32_t b1) {
    asm volatile(
        "mma.sync.aligned.m16n8k16.row.col.f32.f16.f16.f32 "
        "{%0,%1,%2,%3},{%4,%5,%6,%7},{%8,%9},{%0,%1,%2,%3};"
        : "+f"(c[0]), "+f"(c[1]), "+f"(c[2]), "+f"(c[3])
        : "r"(a0), "r"(a1), "r"(a2), "r"(a3), "r"(b0), "r"(b1));
}

// ---- cp.async ----
__device__ __forceinline__ void cpa16(uint32_t dst_smem, const void* src) {
    asm volatile("cp.async.cg.shared.global [%0], [%1], 16;"
                 :: "r"(dst_smem), "l"(src));
}
__device__ __forceinline__ void cpa_commit() {
    asm volatile("cp.async.commit_group;");
}
__device__ __forceinline__ void cpa_wait1() {
    asm volatile("cp.async.wait_group 1;");
}
__device__ __forceinline__ void cpa_wait0() {
    asm volatile("cp.async.wait_group 0;");
}
__device__ __forceinline__ uint32_t smem_u32(const void* p) {
    return (uint32_t)__cvta_generic_to_shared(p);
}

// ---------------------------------------------------------------------------
// x -> rounded fp16 pairs
// ---------------------------------------------------------------------------
__global__ void __launch_bounds__(256) convert_x_kernel(const float* __restrict__ x)
{
    const long i = (long)blockIdx.x * 256 + threadIdx.x;
    float2 v = ((const float2*)x)[i];
    g_Xh[i] = pkh2(v.x, v.y);
}

// ---------------------------------------------------------------------------
// Transpose + SPLIT weights: W[K][N] fp32 -> Wt[N][K] fp16 hi/lo pairs
// ---------------------------------------------------------------------------
__global__ void __launch_bounds__(256) convert_w_kernel(
    const float* __restrict__ W, uint32_t* __restrict__ WtH,
    uint32_t* __restrict__ WtL, int K, int N)
{
    __shared__ float sT[32][33];
    const int k0 = blockIdx.y * 32, n0 = blockIdx.x * 32;
    const int tid = threadIdx.x;
    const int tx = tid & 31, ty = tid >> 5;
    #pragma unroll
    for (int i = 0; i < 4; i++)
        sT[ty + i * 8][tx] = W[(long)(k0 + ty + i * 8) * N + n0 + tx];
    __syncthreads();

    const int nr = tid >> 3;
    const int kc = tid & 7;
    #pragma unroll
    for (int i = 0; i < 2; i++) {
        int kk = kc + i * 8;
        float x0 = sT[2 * kk][nr], x1 = sT[2 * kk + 1][nr];
        uint32_t whi = pkh2(x0, x1);
        uint32_t wlo = pkh2(x0 - lo16h(whi), x1 - hi16h(whi));
        long o = (long)(n0 + nr) * (K / 2) + k0 / 2 + kk;
        WtH[o] = whi;
        WtL[o] = wlo;
    }
}

// ---------------------------------------------------------------------------
// Tensor-core GEMM fp16 x2: C = A Bt^T + bias. A rounded fp16 (single),
// B split hi/lo fp16. cp.async double-buffered, pass-major issue.
// ---------------------------------------------------------------------------
__global__ void __launch_bounds__(256, 2) gemm_tc_kernel(
    const uint4* __restrict__ A,
    const uint4* __restrict__ Bh, const uint4* __restrict__ Bl,
    const float* __restrict__ bias, float* __restrict__ C,
    int M, int N, int K)
{
    __shared__ __align__(16) __half sA[2][128][24];       // [stage][m][k]
    __shared__ __align__(16) __half sB[2][2][128][24];    // [stage][hi/lo][n][k]

    const int tid = threadIdx.x;
    const int wid = tid >> 5;
    const int lane = tid & 31;
    const int g = lane >> 2;
    const int t4 = lane & 3;
    const int wr = wid >> 2;
    const int wc = wid & 3;

    const int m0 = blockIdx.y * 128;
    const int n0 = blockIdx.x * 128;
    const int row = tid >> 1;
    const int half = tid & 1;
    const int Ku4 = K >> 3;

    const uint4* pA  = A  + (long)(m0 + row) * Ku4 + half;
    const uint4* pBh = Bh + (long)(n0 + row) * Ku4 + half;
    const uint4* pBl = Bl + (long)(n0 + row) * Ku4 + half;

    const uint32_t dA0  = smem_u32(&sA[0][row][half * 8]);
    const uint32_t dBh0 = smem_u32(&sB[0][0][row][half * 8]);
    const uint32_t dBl0 = smem_u32(&sB[0][1][row][half * 8]);
    const uint32_t stA = 128 * 24 * 2;
    const uint32_t stB = 2 * 128 * 24 * 2;

    float acc[4][4][4];
    #pragma unroll
    for (int mt = 0; mt < 4; mt++)
        #pragma unroll
        for (int nt = 0; nt < 4; nt++)
            #pragma unroll
            for (int j = 0; j < 4; j++) acc[mt][nt][j] = 0.f;

    const int NIT = K / 16;
    cpa16(dA0, pA); cpa16(dBh0, pBh); cpa16(dBl0, pBl);
    cpa_commit();

    for (int it = 0; it < NIT; it++) {
        if (it + 1 < NIT) {
            uint32_t s = (it + 1) & 1;
            cpa16(dA0  + s * stA, pA  + (it + 1) * 2);
            cpa16(dBh0 + s * stB, pBh + (it + 1) * 2);
            cpa16(dBl0 + s * stB, pBl + (it + 1) * 2);
            cpa_commit();
            cpa_wait1();
        } else {
            cpa_wait0();
        }
        __syncthreads();

        const int st = it & 1;
        const uint32_t* sA0 = (const uint32_t*)sA[st];
        const uint32_t* sB0 = (const uint32_t*)sB[st][0];
        const uint32_t* sB1 = (const uint32_t*)sB[st][1];

        uint32_t bfh[4][2], bfl[4][2];
        #pragma unroll
        for (int nt = 0; nt < 4; nt++) {
            int n = wc * 32 + nt * 8 + g;
            bfh[nt][0] = sB0[n * 12 + t4];
            bfh[nt][1] = sB0[n * 12 + t4 + 4];
            bfl[nt][0] = sB1[n * 12 + t4];
            bfl[nt][1] = sB1[n * 12 + t4 + 4];
        }
        uint32_t af[4][4];
        #pragma unroll
        for (int mt = 0; mt < 4; mt++) {
            int r0 = (wr * 64 + mt * 16 + g) * 12;
            int r1 = r0 + 8 * 12;
            af[mt][0] = sA0[r0 + t4];     af[mt][1] = sA0[r1 + t4];
            af[mt][2] = sA0[r0 + t4 + 4]; af[mt][3] = sA0[r1 + t4 + 4];
        }
        #pragma unroll
        for (int mt = 0; mt < 4; mt++)
            #pragma unroll
            for (int nt = 0; nt < 4; nt++)
                mma16816h(acc[mt][nt], af[mt][0], af[mt][1], af[mt][2], af[mt][3],
                          bfh[nt][0], bfh[nt][1]);
        #pragma unroll
        for (int mt = 0; mt < 4; mt++)
            #pragma unroll
            for (int nt = 0; nt < 4; nt++)
                mma16816h(acc[mt][nt], af[mt][0], af[mt][1], af[mt][2], af[mt][3],
                          bfl[nt][0], bfl[nt][1]);
        __syncthreads();
    }

    #pragma unroll
    for (int mt = 0; mt < 4; mt++) {
        int r = m0 + wr * 64 + mt * 16 + g;
        #pragma unroll
        for (int nt = 0; nt < 4; nt++) {
            int c = n0 + wc * 32 + nt * 8 + 2 * t4;
            float b0 = bias[c], b1 = bias[c + 1];
            *(float2*)&C[(long)r * N + c] =
                make_float2(acc[mt][nt][0] + b0, acc[mt][nt][1] + b1);
            *(float2*)&C[(long)(r + 8) * N + c] =
                make_float2(acc[mt][nt][2] + b0, acc[mt][nt][3] + b1);
        }
    }
}

// ---------------------------------------------------------------------------
// Split Q (pre-scaled) into fp16 hi/lo; round K to fp16.
// ---------------------------------------------------------------------------
__global__ void __launch_bounds__(256) convert_qk_kernel()
{
    const int idx = blockIdx.x * 256 + threadIdx.x;
    const int row = idx / DIMV;
    const int c   = idx - row * DIMV;
    const int h   = c / PH;
    const int d   = c - h * PH;
    const long base = (long)row * NQKV + h * (3 * PH) + d;

    float q = g_qkv[base] * SCALE;
    __half qh = __float2half_rn(q);
    g_Qh[idx] = qh;
    g_Ql[idx] = __float2half_rn(q - __half2float(qh));
    g_Kh[idx] = __float2half_rn(g_qkv[base + PH]);
}

// ---------------------------------------------------------------------------
// V -> transposed rounded fp16: g_Vth[bh][d][t]
// ---------------------------------------------------------------------------
__global__ void __launch_bounds__(256) convert_v_kernel()
{
    __shared__ float sv[PH][65];

    const int tb = blockIdx.x;
    const int bh = blockIdx.y;
    const int b = bh >> 4;
    const int h = bh & 15;
    const int tid = threadIdx.x;

    const int tl = tid >> 2;
    const int dp = (tid & 3) * 12;
    const long rbase = (long)(b * TSEQ + tb * 64 + tl) * NQKV + h * (3 * PH) + 2 * PH + dp;
    #pragma unroll
    for (int j = 0; j < 12; j++)
        sv[dp + j][tl] = g_qkv[rbase + j];
    __syncthreads();

    uint32_t* Vh32 = (uint32_t*)g_Vth;
    const long obase = ((long)bh * PH * TSEQ) / 2;
    #pragma unroll
    for (int i = 0; i < 6; i++) {
        int tau = tid + 256 * i;
        int d = tau >> 5;
        int j = tau & 31;
        Vh32[obase + (long)d * (TSEQ / 2) + tb * 32 + j] =
            pkh2(sv[d][2 * j], sv[d][2 * j + 1]);
    }
}

// ---------------------------------------------------------------------------
// Flash attention fp16: Q split x2 / K rounded; P rounded SINGLE-pass / V rounded.
// cp.async double-buffered; pass-major mma.
// ---------------------------------------------------------------------------
#define SK_ELEMS (64 * 56)                 // 3584
#define STAGE_ELEMS (SK_ELEMS + 48 * 72)   // 7040
#define ATTN_SMEM (2 * STAGE_ELEMS * 2)    // 28160 bytes

__global__ void __launch_bounds__(256, 2) attn_mma_kernel()
{
    extern __shared__ __align__(16) __half dyn[];

    const int tid = threadIdx.x;
    const int wid = tid >> 5;
    const int lane = tid & 31;
    const int g = lane >> 2;
    const int t4 = lane & 3;

    const int bh = blockIdx.y;
    const int b = bh >> 4;
    const int h = bh & 15;
    const int qr0 = blockIdx.x * 128 + wid * 16;
    const long rowg  = (long)b * TSEQ + qr0 + g;
    const long rowg8 = rowg + 8;

    auto load_tile = [&](int kb, int st) {
        __half* base = dyn + st * STAGE_ELEMS;
        #pragma unroll
        for (int i = 0; i < 3; i++) {
            int idx = tid + 256 * i;
            if (idx < 384) {                     // K: 64 rows x 6 chunks
                int key = idx / 6, c = idx - key * 6;
                const __half* src = g_Kh
                    + (long)(b * TSEQ + kb + key) * DIMV + h * PH + c * 8;
                cpa16(smem_u32(base + key * 56 + c * 8), src);
            } else {                             // V: 48 dims x 8 chunks
                int v = idx - 384;
                int d = v >> 3, c = v & 7;
                const __half* src = g_Vth
                    + (long)bh * (PH * TSEQ) + d * TSEQ + kb + c * 8;
                cpa16(smem_u32(base + SK_ELEMS + d * 72 + c * 8), src);
            }
        }
        cpa_commit();
    };

    const uint32_t* Qh32 = (const uint32_t*)g_Qh;
    const uint32_t* Ql32 = (const uint32_t*)g_Ql;
    uint32_t qh[3][4], ql[3][4];
    #pragma unroll
    for (int kk = 0; kk < 3; kk++) {
        long o0 = rowg  * 384 + h * 24 + kk * 8 + t4;
        long o1 = rowg8 * 384 + h * 24 + kk * 8 + t4;
        qh[kk][0] = Qh32[o0];     qh[kk][1] = Qh32[o1];
        qh[kk][2] = Qh32[o0 + 4]; qh[kk][3] = Qh32[o1 + 4];
        ql[kk][0] = Ql32[o0];     ql[kk][1] = Ql32[o1];
        ql[kk][2] = Ql32[o0 + 4]; ql[kk][3] = Ql32[o1 + 4];
    }

    float O[6][4];
    #pragma unroll
    for (int i = 0; i < 6; i++)
        #pragma unroll
        for (int j = 0; j < 4; j++) O[i][j] = 0.f;
    float m0 = -1e30f, m1 = -1e30f, l0 = 0.f, l1 = 0.f;

    load_tile(0, 0);

    const int NT = TSEQ / 64;
    for (int t = 0; t < NT; t++) {
        if (t + 1 < NT) {
            load_tile((t + 1) * 64, (t + 1) & 1);
            cpa_wait1();
        } else {
            cpa_wait0();
        }
        __syncthreads();

        const int st = t & 1;
        const __half* sK0 = dyn + st * STAGE_ELEMS;
        const __half* sV0 = sK0 + SK_ELEMS;

        float S[8][4];
        #pragma unroll
        for (int n = 0; n < 8; n++)
            #pragma unroll
            for (int j = 0; j < 4; j++) S[n][j] = 0.f;

        // QK^T: 2 passes (q_hi, q_lo) x rounded K
        #pragma unroll
        for (int kk = 0; kk < 3; kk++) {
            uint32_t kf[8][2];
            #pragma unroll
            for (int n = 0; n < 8; n++) {
                const uint32_t* kp = (const uint32_t*)(sK0 + (n * 8 + g) * 56 + kk * 16 + 2 * t4);
                kf[n][0] = kp[0]; kf[n][1] = kp[4];
            }
            #pragma unroll
            for (int n = 0; n < 8; n++)
                mma16816h(S[n], qh[kk][0], qh[kk][1], qh[kk][2], qh[kk][3], kf[n][0], kf[n][1]);
            #pragma unroll
            for (int n = 0; n < 8; n++)
                mma16816h(S[n], ql[kk][0], ql[kk][1], ql[kk][2], ql[kk][3], kf[n][0], kf[n][1]);
        }

        float rmax0 = -1e30f, rmax1 = -1e30f;
        #pragma unroll
        for (int n = 0; n < 8; n++) {
            rmax0 = fmaxf(rmax0, fmaxf(S[n][0], S[n][1]));
            rmax1 = fmaxf(rmax1, fmaxf(S[n][2], S[n][3]));
        }
        rmax0 = fmaxf(rmax0, __shfl_xor_sync(0xffffffffu, rmax0, 1));
        rmax0 = fmaxf(rmax0, __shfl_xor_sync(0xffffffffu, rmax0, 2));
        rmax1 = fmaxf(rmax1, __shfl_xor_sync(0xffffffffu, rmax1, 1));
        rmax1 = fmaxf(rmax1, __shfl_xor_sync(0xffffffffu, rmax1, 2));

        float mn0 = fmaxf(m0, rmax0);
        float mn1 = fmaxf(m1, rmax1);
        float corr0 = __expf(m0 - mn0);
        float corr1 = __expf(m1 - mn1);
        m0 = mn0; m1 = mn1;
        l0 *= corr0; l1 *= corr1;
        #pragma unroll
        for (int nd = 0; nd < 6; nd++) {
            O[nd][0] *= corr0; O[nd][1] *= corr0;
            O[nd][2] *= corr1; O[nd][3] *= corr1;
        }

        float ps0 = 0.f, ps1 = 0.f;
        #pragma unroll
        for (int n = 0; n < 8; n++) {
            S[n][0] = __expf(S[n][0] - m0);
            S[n][1] = __expf(S[n][1] - m0);
            S[n][2] = __expf(S[n][2] - m1);
            S[n][3] = __expf(S[n][3] - m1);
            ps0 += S[n][0] + S[n][1];
            ps1 += S[n][2] + S[n][3];
        }
        ps0 += __shfl_xor_sync(0xffffffffu, ps0, 1);
        ps0 += __shfl_xor_sync(0xffffffffu, ps0, 2);
        ps1 += __shfl_xor_sync(0xffffffffu, ps1, 1);
        ps1 += __shfl_xor_sync(0xffffffffu, ps1, 2);
        l0 += ps0; l1 += ps1;

        // PV: SINGLE pass (rounded P) x rounded V
        #pragma unroll
        for (int kk = 0; kk < 4; kk++) {
            uint32_t ph[4];
            #pragma unroll
            for (int half = 0; half < 2; half++) {
                const float* Sc = S[2 * kk + half];
                ph[2 * half + 0] = pkh2(Sc[0], Sc[1]);
                ph[2 * half + 1] = pkh2(Sc[2], Sc[3]);
            }
            uint32_t vf[6][2];
            #pragma unroll
            for (int nd = 0; nd < 6; nd++) {
                const uint32_t* vp = (const uint32_t*)(sV0 + (nd * 8 + g) * 72 + kk * 16 + 2 * t4);
                vf[nd][0] = vp[0]; vf[nd][1] = vp[4];
            }
            #pragma unroll
            for (int nd = 0; nd < 6; nd++)
                mma16816h(O[nd], ph[0], ph[1], ph[2], ph[3], vf[nd][0], vf[nd][1]);
        }
        __syncthreads();
    }

    const float invl0 = 1.0f / l0;
    const float invl1 = 1.0f / l1;
    #pragma unroll
    for (int nd = 0; nd < 6; nd++) {
        long c = h * PH + nd * 8 + 2 * t4;
        g_AttH[(rowg  * DIMV + c) >> 1] =
            pkh2(O[nd][0] * invl0, O[nd][1] * invl0);
        g_AttH[(rowg8 * DIMV + c) >> 1] =
            pkh2(O[nd][2] * invl1, O[nd][3] * invl1);
    }
}

// ---------------------------------------------------------------------------
extern "C" void kernel_launch(void* const* d_in, const int* in_sizes, int n_in,
                              void* d_out, int out_size)
{
    const float* x     = (const float*)d_in[0];
    const float* w_in  = (const float*)d_in[1];
    const float* b_in  = (const float*)d_in[2];
    const float* w_out = (const float*)d_in[3];
    const float* b_out = (const float*)d_in[4];
    float* out = (float*)d_out;

    float* qkv = nullptr;
    cudaGetSymbolAddress((void**)&qkv, g_qkv);
    uint32_t *Xh, *WinTh, *WinTl, *WoutTh, *WoutTl, *AttH;
    cudaGetSymbolAddress((void**)&Xh, g_Xh);
    cudaGetSymbolAddress((void**)&WinTh, g_WinTh);
    cudaGetSymbolAddress((void**)&WinTl, g_WinTl);
    cudaGetSymbolAddress((void**)&WoutTh, g_WoutTh);
    cudaGetSymbolAddress((void**)&WoutTl, g_WoutTl);
    cudaGetSymbolAddress((void**)&AttH, g_AttH);

    convert_x_kernel<<<(MTOT * DIMV / 2) / 256, 256>>>(x);
    {
        dim3 grid(NQKV / 32, DIMV / 32);
        convert_w_kernel<<<grid, 256>>>(w_in, WinTh, WinTl, DIMV, NQKV);
    }
    {
        dim3 grid(DIMV / 32, DIMV / 32);
        convert_w_kernel<<<grid, 256>>>(w_out, WoutTh, WoutTl, DIMV, DIMV);
    }

    // QKV projection (fp16 x2)
    {
        dim3 grid(NQKV / 128, MTOT / 128);
        gemm_tc_kernel<<<grid, 256>>>((const uint4*)Xh,
                                      (const uint4*)WinTh, (const uint4*)WinTl,
                                      b_in, qkv, MTOT, NQKV, DIMV);
    }

    convert_qk_kernel<<<(MTOT * DIMV) / 256, 256>>>();
    {
        dim3 grid(TSEQ / 64, 64);
        convert_v_kernel<<<grid, 256>>>();
    }

    // Attention (Q x2, PV x1)
    {
        dim3 grid(TSEQ / 128, 64);
        attn_mma_kernel<<<grid, 256, ATTN_SMEM>>>();
    }

    // Output projection (fp16 x2)
    {
        dim3 grid(DIMV / 128, MTOT / 128);
        gemm_tc_kernel<<<grid, 256>>>((const uint4*)AttH,
                                      (const uint4*)WoutTh, (const uint4*)WoutTl,
                                      b_out, out, MTOT, DIMV, DIMV);
    }
}

// round 13
// speedup vs baseline: 5.5718x; 1.1997x over previous
#include <cuda_runtime.h>
#include <cuda_fp16.h>
#include <cstdint>

#define DIMV 768
#define NHEAD 16
#define PH 48
#define BATCH 4
#define TSEQ 2048
#define MTOT (BATCH * TSEQ)   // 8192
#define NQKV (3 * DIMV)       // 2304
#define SCALE 0.14433756729740643f   // 1/sqrt(48)

// Scratch (allocation-free rule: __device__ globals)
__device__ float g_qkv[MTOT * NQKV];
__device__ uint32_t g_Xh[MTOT * DIMV / 2];       // x rounded fp16 (packed pairs)
__device__ uint32_t g_WinTh[NQKV * DIMV / 2];    // w_in^T rounded fp16
__device__ uint32_t g_WoutTh[DIMV * DIMV / 2];   // w_out^T rounded fp16
__device__ uint32_t g_AttH[MTOT * DIMV / 2];     // attn out rounded fp16
__device__ __half g_Qh[MTOT * DIMV];             // q*scale split hi/lo
__device__ __half g_Ql[MTOT * DIMV];
__device__ __half g_Kh[MTOT * DIMV];             // k rounded
__device__ __half g_Vth[64 * PH * TSEQ];         // v transposed rounded [bh][d][t]

// ---- fp16 helpers ----
__device__ __forceinline__ uint32_t pkh2(float lo, float hi) {
    uint32_t r;
    asm("cvt.rn.f16x2.f32 %0, %1, %2;" : "=r"(r) : "f"(hi), "f"(lo));
    return r;
}

// ---- fp16 m16n8k16 mma, fp32 accum ----
__device__ __forceinline__ void mma16816h(float* c, uint32_t a0, uint32_t a1,
                                          uint32_t a2, uint32_t a3,
                                          uint32_t b0, uint32_t b1) {
    asm volatile(
        "mma.sync.aligned.m16n8k16.row.col.f32.f16.f16.f32 "
        "{%0,%1,%2,%3},{%4,%5,%6,%7},{%8,%9},{%0,%1,%2,%3};"
        : "+f"(c[0]), "+f"(c[1]), "+f"(c[2]), "+f"(c[3])
        : "r"(a0), "r"(a1), "r"(a2), "r"(a3), "r"(b0), "r"(b1));
}

// ---- cp.async ----
__device__ __forceinline__ void cpa16(uint32_t dst_smem, const void* src) {
    asm volatile("cp.async.cg.shared.global [%0], [%1], 16;"
                 :: "r"(dst_smem), "l"(src));
}
__device__ __forceinline__ void cpa_commit() {
    asm volatile("cp.async.commit_group;");
}
__device__ __forceinline__ void cpa_wait1() {
    asm volatile("cp.async.wait_group 1;");
}
__device__ __forceinline__ void cpa_wait0() {
    asm volatile("cp.async.wait_group 0;");
}
__device__ __forceinline__ uint32_t smem_u32(const void* p) {
    return (uint32_t)__cvta_generic_to_shared(p);
}

// ---------------------------------------------------------------------------
// x -> rounded fp16 pairs
// ---------------------------------------------------------------------------
__global__ void __launch_bounds__(256) convert_x_kernel(const float* __restrict__ x)
{
    const long i = (long)blockIdx.x * 256 + threadIdx.x;
    float2 v = ((const float2*)x)[i];
    g_Xh[i] = pkh2(v.x, v.y);
}

// ---------------------------------------------------------------------------
// Transpose + ROUND weights: W[K][N] fp32 -> Wt[N][K] fp16 pairs
// ---------------------------------------------------------------------------
__global__ void __launch_bounds__(256) convert_w_kernel(
    const float* __restrict__ W, uint32_t* __restrict__ WtH, int K, int N)
{
    __shared__ float sT[32][33];
    const int k0 = blockIdx.y * 32, n0 = blockIdx.x * 32;
    const int tid = threadIdx.x;
    const int tx = tid & 31, ty = tid >> 5;
    #pragma unroll
    for (int i = 0; i < 4; i++)
        sT[ty + i * 8][tx] = W[(long)(k0 + ty + i * 8) * N + n0 + tx];
    __syncthreads();

    const int nr = tid >> 3;
    const int kc = tid & 7;
    #pragma unroll
    for (int i = 0; i < 2; i++) {
        int kk = kc + i * 8;
        long o = (long)(n0 + nr) * (K / 2) + k0 / 2 + kk;
        WtH[o] = pkh2(sT[2 * kk][nr], sT[2 * kk + 1][nr]);
    }
}

// ---------------------------------------------------------------------------
// Tensor-core GEMM pure fp16 (single pass): C = A Bt^T + bias.
// cp.async double-buffered, pass-major issue. BM=BN=128, BK=16, 256 threads.
// ---------------------------------------------------------------------------
__global__ void __launch_bounds__(256, 2) gemm_tc_kernel(
    const uint4* __restrict__ A, const uint4* __restrict__ B,
    const float* __restrict__ bias, float* __restrict__ C,
    int M, int N, int K)
{
    __shared__ __align__(16) __half sA[2][128][24];   // [stage][m][k]
    __shared__ __align__(16) __half sB[2][128][24];   // [stage][n][k]

    const int tid = threadIdx.x;
    const int wid = tid >> 5;
    const int lane = tid & 31;
    const int g = lane >> 2;
    const int t4 = lane & 3;
    const int wr = wid >> 2;
    const int wc = wid & 3;

    const int m0 = blockIdx.y * 128;
    const int n0 = blockIdx.x * 128;
    const int row = tid >> 1;
    const int half = tid & 1;
    const int Ku4 = K >> 3;

    const uint4* pA = A + (long)(m0 + row) * Ku4 + half;
    const uint4* pB = B + (long)(n0 + row) * Ku4 + half;

    const uint32_t dA0 = smem_u32(&sA[0][row][half * 8]);
    const uint32_t dB0 = smem_u32(&sB[0][row][half * 8]);
    const uint32_t stg = 128 * 24 * 2;   // bytes per stage

    float acc[4][4][4];
    #pragma unroll
    for (int mt = 0; mt < 4; mt++)
        #pragma unroll
        for (int nt = 0; nt < 4; nt++)
            #pragma unroll
            for (int j = 0; j < 4; j++) acc[mt][nt][j] = 0.f;

    const int NIT = K / 16;
    cpa16(dA0, pA); cpa16(dB0, pB);
    cpa_commit();

    for (int it = 0; it < NIT; it++) {
        if (it + 1 < NIT) {
            uint32_t s = (it + 1) & 1;
            cpa16(dA0 + s * stg, pA + (it + 1) * 2);
            cpa16(dB0 + s * stg, pB + (it + 1) * 2);
            cpa_commit();
            cpa_wait1();
        } else {
            cpa_wait0();
        }
        __syncthreads();

        const int st = it & 1;
        const uint32_t* sA0 = (const uint32_t*)sA[st];
        const uint32_t* sB0 = (const uint32_t*)sB[st];

        uint32_t bf[4][2];
        #pragma unroll
        for (int nt = 0; nt < 4; nt++) {
            int n = wc * 32 + nt * 8 + g;
            bf[nt][0] = sB0[n * 12 + t4];
            bf[nt][1] = sB0[n * 12 + t4 + 4];
        }
        uint32_t af[4][4];
        #pragma unroll
        for (int mt = 0; mt < 4; mt++) {
            int r0 = (wr * 64 + mt * 16 + g) * 12;
            int r1 = r0 + 8 * 12;
            af[mt][0] = sA0[r0 + t4];     af[mt][1] = sA0[r1 + t4];
            af[mt][2] = sA0[r0 + t4 + 4]; af[mt][3] = sA0[r1 + t4 + 4];
        }
        #pragma unroll
        for (int mt = 0; mt < 4; mt++)
            #pragma unroll
            for (int nt = 0; nt < 4; nt++)
                mma16816h(acc[mt][nt], af[mt][0], af[mt][1], af[mt][2], af[mt][3],
                          bf[nt][0], bf[nt][1]);
        __syncthreads();
    }

    #pragma unroll
    for (int mt = 0; mt < 4; mt++) {
        int r = m0 + wr * 64 + mt * 16 + g;
        #pragma unroll
        for (int nt = 0; nt < 4; nt++) {
            int c = n0 + wc * 32 + nt * 8 + 2 * t4;
            float b0 = bias[c], b1 = bias[c + 1];
            *(float2*)&C[(long)r * N + c] =
                make_float2(acc[mt][nt][0] + b0, acc[mt][nt][1] + b1);
            *(float2*)&C[(long)(r + 8) * N + c] =
                make_float2(acc[mt][nt][2] + b0, acc[mt][nt][3] + b1);
        }
    }
}

// ---------------------------------------------------------------------------
// Split Q (pre-scaled) into fp16 hi/lo; round K to fp16.
// ---------------------------------------------------------------------------
__global__ void __launch_bounds__(256) convert_qk_kernel()
{
    const int idx = blockIdx.x * 256 + threadIdx.x;
    const int row = idx / DIMV;
    const int c   = idx - row * DIMV;
    const int h   = c / PH;
    const int d   = c - h * PH;
    const long base = (long)row * NQKV + h * (3 * PH) + d;

    float q = g_qkv[base] * SCALE;
    __half qh = __float2half_rn(q);
    g_Qh[idx] = qh;
    g_Ql[idx] = __float2half_rn(q - __half2float(qh));
    g_Kh[idx] = __float2half_rn(g_qkv[base + PH]);
}

// ---------------------------------------------------------------------------
// V -> transposed rounded fp16: g_Vth[bh][d][t]
// ---------------------------------------------------------------------------
__global__ void __launch_bounds__(256) convert_v_kernel()
{
    __shared__ float sv[PH][65];

    const int tb = blockIdx.x;
    const int bh = blockIdx.y;
    const int b = bh >> 4;
    const int h = bh & 15;
    const int tid = threadIdx.x;

    const int tl = tid >> 2;
    const int dp = (tid & 3) * 12;
    const long rbase = (long)(b * TSEQ + tb * 64 + tl) * NQKV + h * (3 * PH) + 2 * PH + dp;
    #pragma unroll
    for (int j = 0; j < 12; j++)
        sv[dp + j][tl] = g_qkv[rbase + j];
    __syncthreads();

    uint32_t* Vh32 = (uint32_t*)g_Vth;
    const long obase = ((long)bh * PH * TSEQ) / 2;
    #pragma unroll
    for (int i = 0; i < 6; i++) {
        int tau = tid + 256 * i;
        int d = tau >> 5;
        int j = tau & 31;
        Vh32[obase + (long)d * (TSEQ / 2) + tb * 32 + j] =
            pkh2(sv[d][2 * j], sv[d][2 * j + 1]);
    }
}

// ---------------------------------------------------------------------------
// Flash attention fp16: Q split x2 / K rounded; P rounded single / V rounded.
// cp.async double-buffered; pass-major mma.
// ---------------------------------------------------------------------------
#define SK_ELEMS (64 * 56)                 // 3584
#define STAGE_ELEMS (SK_ELEMS + 48 * 72)   // 7040
#define ATTN_SMEM (2 * STAGE_ELEMS * 2)    // 28160 bytes

__global__ void __launch_bounds__(256, 2) attn_mma_kernel()
{
    extern __shared__ __align__(16) __half dyn[];

    const int tid = threadIdx.x;
    const int wid = tid >> 5;
    const int lane = tid & 31;
    const int g = lane >> 2;
    const int t4 = lane & 3;

    const int bh = blockIdx.y;
    const int b = bh >> 4;
    const int h = bh & 15;
    const int qr0 = blockIdx.x * 128 + wid * 16;
    const long rowg  = (long)b * TSEQ + qr0 + g;
    const long rowg8 = rowg + 8;

    auto load_tile = [&](int kb, int st) {
        __half* base = dyn + st * STAGE_ELEMS;
        #pragma unroll
        for (int i = 0; i < 3; i++) {
            int idx = tid + 256 * i;
            if (idx < 384) {                     // K: 64 rows x 6 chunks
                int key = idx / 6, c = idx - key * 6;
                const __half* src = g_Kh
                    + (long)(b * TSEQ + kb + key) * DIMV + h * PH + c * 8;
                cpa16(smem_u32(base + key * 56 + c * 8), src);
            } else {                             // V: 48 dims x 8 chunks
                int v = idx - 384;
                int d = v >> 3, c = v & 7;
                const __half* src = g_Vth
                    + (long)bh * (PH * TSEQ) + d * TSEQ + kb + c * 8;
                cpa16(smem_u32(base + SK_ELEMS + d * 72 + c * 8), src);
            }
        }
        cpa_commit();
    };

    const uint32_t* Qh32 = (const uint32_t*)g_Qh;
    const uint32_t* Ql32 = (const uint32_t*)g_Ql;
    uint32_t qh[3][4], ql[3][4];
    #pragma unroll
    for (int kk = 0; kk < 3; kk++) {
        long o0 = rowg  * 384 + h * 24 + kk * 8 + t4;
        long o1 = rowg8 * 384 + h * 24 + kk * 8 + t4;
        qh[kk][0] = Qh32[o0];     qh[kk][1] = Qh32[o1];
        qh[kk][2] = Qh32[o0 + 4]; qh[kk][3] = Qh32[o1 + 4];
        ql[kk][0] = Ql32[o0];     ql[kk][1] = Ql32[o1];
        ql[kk][2] = Ql32[o0 + 4]; ql[kk][3] = Ql32[o1 + 4];
    }

    float O[6][4];
    #pragma unroll
    for (int i = 0; i < 6; i++)
        #pragma unroll
        for (int j = 0; j < 4; j++) O[i][j] = 0.f;
    float m0 = -1e30f, m1 = -1e30f, l0 = 0.f, l1 = 0.f;

    load_tile(0, 0);

    const int NT = TSEQ / 64;
    for (int t = 0; t < NT; t++) {
        if (t + 1 < NT) {
            load_tile((t + 1) * 64, (t + 1) & 1);
            cpa_wait1();
        } else {
            cpa_wait0();
        }
        __syncthreads();

        const int st = t & 1;
        const __half* sK0 = dyn + st * STAGE_ELEMS;
        const __half* sV0 = sK0 + SK_ELEMS;

        float S[8][4];
        #pragma unroll
        for (int n = 0; n < 8; n++)
            #pragma unroll
            for (int j = 0; j < 4; j++) S[n][j] = 0.f;

        // QK^T: 2 passes (q_hi, q_lo) x rounded K
        #pragma unroll
        for (int kk = 0; kk < 3; kk++) {
            uint32_t kf[8][2];
            #pragma unroll
            for (int n = 0; n < 8; n++) {
                const uint32_t* kp = (const uint32_t*)(sK0 + (n * 8 + g) * 56 + kk * 16 + 2 * t4);
                kf[n][0] = kp[0]; kf[n][1] = kp[4];
            }
            #pragma unroll
            for (int n = 0; n < 8; n++)
                mma16816h(S[n], qh[kk][0], qh[kk][1], qh[kk][2], qh[kk][3], kf[n][0], kf[n][1]);
            #pragma unroll
            for (int n = 0; n < 8; n++)
                mma16816h(S[n], ql[kk][0], ql[kk][1], ql[kk][2], ql[kk][3], kf[n][0], kf[n][1]);
        }

        float rmax0 = -1e30f, rmax1 = -1e30f;
        #pragma unroll
        for (int n = 0; n < 8; n++) {
            rmax0 = fmaxf(rmax0, fmaxf(S[n][0], S[n][1]));
            rmax1 = fmaxf(rmax1, fmaxf(S[n][2], S[n][3]));
        }
        rmax0 = fmaxf(rmax0, __shfl_xor_sync(0xffffffffu, rmax0, 1));
        rmax0 = fmaxf(rmax0, __shfl_xor_sync(0xffffffffu, rmax0, 2));
        rmax1 = fmaxf(rmax1, __shfl_xor_sync(0xffffffffu, rmax1, 1));
        rmax1 = fmaxf(rmax1, __shfl_xor_sync(0xffffffffu, rmax1, 2));

        float mn0 = fmaxf(m0, rmax0);
        float mn1 = fmaxf(m1, rmax1);
        float corr0 = __expf(m0 - mn0);
        float corr1 = __expf(m1 - mn1);
        m0 = mn0; m1 = mn1;
        l0 *= corr0; l1 *= corr1;
        #pragma unroll
        for (int nd = 0; nd < 6; nd++) {
            O[nd][0] *= corr0; O[nd][1] *= corr0;
            O[nd][2] *= corr1; O[nd][3] *= corr1;
        }

        float ps0 = 0.f, ps1 = 0.f;
        #pragma unroll
        for (int n = 0; n < 8; n++) {
            S[n][0] = __expf(S[n][0] - m0);
            S[n][1] = __expf(S[n][1] - m0);
            S[n][2] = __expf(S[n][2] - m1);
            S[n][3] = __expf(S[n][3] - m1);
            ps0 += S[n][0] + S[n][1];
            ps1 += S[n][2] + S[n][3];
        }
        ps0 += __shfl_xor_sync(0xffffffffu, ps0, 1);
        ps0 += __shfl_xor_sync(0xffffffffu, ps0, 2);
        ps1 += __shfl_xor_sync(0xffffffffu, ps1, 1);
        ps1 += __shfl_xor_sync(0xffffffffu, ps1, 2);
        l0 += ps0; l1 += ps1;

        // PV: single pass (rounded P) x rounded V
        #pragma unroll
        for (int kk = 0; kk < 4; kk++) {
            uint32_t ph[4];
            #pragma unroll
            for (int half = 0; half < 2; half++) {
                const float* Sc = S[2 * kk + half];
                ph[2 * half + 0] = pkh2(Sc[0], Sc[1]);
                ph[2 * half + 1] = pkh2(Sc[2], Sc[3]);
            }
            uint32_t vf[6][2];
            #pragma unroll
            for (int nd = 0; nd < 6; nd++) {
                const uint32_t* vp = (const uint32_t*)(sV0 + (nd * 8 + g) * 72 + kk * 16 + 2 * t4);
                vf[nd][0] = vp[0]; vf[nd][1] = vp[4];
            }
            #pragma unroll
            for (int nd = 0; nd < 6; nd++)
                mma16816h(O[nd], ph[0], ph[1], ph[2], ph[3], vf[nd][0], vf[nd][1]);
        }
        __syncthreads();
    }

    const float invl0 = 1.0f / l0;
    const float invl1 = 1.0f / l1;
    #pragma unroll
    for (int nd = 0; nd < 6; nd++) {
        long c = h * PH + nd * 8 + 2 * t4;
        g_AttH[(rowg  * DIMV + c) >> 1] =
            pkh2(O[nd][0] * invl0, O[nd][1] * invl0);
        g_AttH[(rowg8 * DIMV + c) >> 1] =
            pkh2(O[nd][2] * invl1, O[nd][3] * invl1);
    }
}

// ---------------------------------------------------------------------------
extern "C" void kernel_launch(void* const* d_in, const int* in_sizes, int n_in,
                              void* d_out, int out_size)
{
    const float* x     = (const float*)d_in[0];
    const float* w_in  = (const float*)d_in[1];
    const float* b_in  = (const float*)d_in[2];
    const float* w_out = (const float*)d_in[3];
    const float* b_out = (const float*)d_in[4];
    float* out = (float*)d_out;

    float* qkv = nullptr;
    cudaGetSymbolAddress((void**)&qkv, g_qkv);
    uint32_t *Xh, *WinTh, *WoutTh, *AttH;
    cudaGetSymbolAddress((void**)&Xh, g_Xh);
    cudaGetSymbolAddress((void**)&WinTh, g_WinTh);
    cudaGetSymbolAddress((void**)&WoutTh, g_WoutTh);
    cudaGetSymbolAddress((void**)&AttH, g_AttH);

    convert_x_kernel<<<(MTOT * DIMV / 2) / 256, 256>>>(x);
    {
        dim3 grid(NQKV / 32, DIMV / 32);
        convert_w_kernel<<<grid, 256>>>(w_in, WinTh, DIMV, NQKV);
    }
    {
        dim3 grid(DIMV / 32, DIMV / 32);
        convert_w_kernel<<<grid, 256>>>(w_out, WoutTh, DIMV, DIMV);
    }

    // QKV projection (fp16 single-pass)
    {
        dim3 grid(NQKV / 128, MTOT / 128);
        gemm_tc_kernel<<<grid, 256>>>((const uint4*)Xh, (const uint4*)WinTh,
                                      b_in, qkv, MTOT, NQKV, DIMV);
    }

    convert_qk_kernel<<<(MTOT * DIMV) / 256, 256>>>();
    {
        dim3 grid(TSEQ / 64, 64);
        convert_v_kernel<<<grid, 256>>>();
    }

    // Attention (Q x2, PV x1)
    {
        dim3 grid(TSEQ / 128, 64);
        attn_mma_kernel<<<grid, 256, ATTN_SMEM>>>();
    }

    // Output projection (fp16 single-pass)
    {
        dim3 grid(DIMV / 128, MTOT / 128);
        gemm_tc_kernel<<<grid, 256>>>((const uint4*)AttH, (const uint4*)WoutTh,
                                      b_out, out, MTOT, DIMV, DIMV);
    }
}

// round 14
// speedup vs baseline: 6.3736x; 1.1439x over previous
#include <cuda_runtime.h>
#include <cuda_fp16.h>
#include <cstdint>

#define DIMV 768
#define NHEAD 16
#define PH 48
#define BATCH 4
#define TSEQ 2048
#define MTOT (BATCH * TSEQ)   // 8192
#define NQKV (3 * DIMV)       // 2304
#define SCALE 0.14433756729740643f   // 1/sqrt(48)

// Scratch (allocation-free rule: __device__ globals)
__device__ float g_qkv[MTOT * NQKV];
__device__ uint32_t g_Xh[MTOT * DIMV / 2];       // x rounded fp16 (packed pairs)
__device__ uint32_t g_WinTh[NQKV * DIMV / 2];    // w_in^T rounded fp16
__device__ uint32_t g_WoutTh[DIMV * DIMV / 2];   // w_out^T rounded fp16
__device__ uint32_t g_AttH[MTOT * DIMV / 2];     // attn out rounded fp16
__device__ __half g_Qh[MTOT * DIMV];             // q*scale rounded
__device__ __half g_Kh[MTOT * DIMV];             // k rounded
__device__ __half g_Vth[64 * PH * TSEQ];         // v transposed rounded [bh][d][t]

// ---- fp16 helpers ----
__device__ __forceinline__ uint32_t pkh2(float lo, float hi) {
    uint32_t r;
    asm("cvt.rn.f16x2.f32 %0, %1, %2;" : "=r"(r) : "f"(hi), "f"(lo));
    return r;
}

// ---- fp16 m16n8k16 mma, fp32 accum ----
__device__ __forceinline__ void mma16816h(float* c, uint32_t a0, uint32_t a1,
                                          uint32_t a2, uint32_t a3,
                                          uint32_t b0, uint32_t b1) {
    asm volatile(
        "mma.sync.aligned.m16n8k16.row.col.f32.f16.f16.f32 "
        "{%0,%1,%2,%3},{%4,%5,%6,%7},{%8,%9},{%0,%1,%2,%3};"
        : "+f"(c[0]), "+f"(c[1]), "+f"(c[2]), "+f"(c[3])
        : "r"(a0), "r"(a1), "r"(a2), "r"(a3), "r"(b0), "r"(b1));
}

// ---- cp.async ----
__device__ __forceinline__ void cpa16(uint32_t dst_smem, const void* src) {
    asm volatile("cp.async.cg.shared.global [%0], [%1], 16;"
                 :: "r"(dst_smem), "l"(src));
}
__device__ __forceinline__ void cpa_commit() {
    asm volatile("cp.async.commit_group;");
}
__device__ __forceinline__ void cpa_wait1() {
    asm volatile("cp.async.wait_group 1;");
}
__device__ __forceinline__ void cpa_wait0() {
    asm volatile("cp.async.wait_group 0;");
}
__device__ __forceinline__ uint32_t smem_u32(const void* p) {
    return (uint32_t)__cvta_generic_to_shared(p);
}

// ---------------------------------------------------------------------------
// x -> rounded fp16 pairs
// ---------------------------------------------------------------------------
__global__ void __launch_bounds__(256) convert_x_kernel(const float* __restrict__ x)
{
    const long i = (long)blockIdx.x * 256 + threadIdx.x;
    float2 v = ((const float2*)x)[i];
    g_Xh[i] = pkh2(v.x, v.y);
}

// ---------------------------------------------------------------------------
// Transpose + ROUND weights: W[K][N] fp32 -> Wt[N][K] fp16 pairs
// ---------------------------------------------------------------------------
__global__ void __launch_bounds__(256) convert_w_kernel(
    const float* __restrict__ W, uint32_t* __restrict__ WtH, int K, int N)
{
    __shared__ float sT[32][33];
    const int k0 = blockIdx.y * 32, n0 = blockIdx.x * 32;
    const int tid = threadIdx.x;
    const int tx = tid & 31, ty = tid >> 5;
    #pragma unroll
    for (int i = 0; i < 4; i++)
        sT[ty + i * 8][tx] = W[(long)(k0 + ty + i * 8) * N + n0 + tx];
    __syncthreads();

    const int nr = tid >> 3;
    const int kc = tid & 7;
    #pragma unroll
    for (int i = 0; i < 2; i++) {
        int kk = kc + i * 8;
        long o = (long)(n0 + nr) * (K / 2) + k0 / 2 + kk;
        WtH[o] = pkh2(sT[2 * kk][nr], sT[2 * kk + 1][nr]);
    }
}

// ---------------------------------------------------------------------------
// Tensor-core GEMM pure fp16: C = A Bt^T + bias.
// BK=32 (2 k16 steps per sync pair), cp.async double-buffered.
// BM=BN=128, 256 threads, warp tile 64x32.
// ---------------------------------------------------------------------------
__global__ void __launch_bounds__(256, 2) gemm_tc_kernel(
    const uint4* __restrict__ A, const uint4* __restrict__ B,
    const float* __restrict__ bias, float* __restrict__ C,
    int M, int N, int K)
{
    __shared__ __align__(16) __half sA[2][128][40];   // [stage][m][32k + 8 pad]
    __shared__ __align__(16) __half sB[2][128][40];   // [stage][n][...]

    const int tid = threadIdx.x;
    const int wid = tid >> 5;
    const int lane = tid & 31;
    const int g = lane >> 2;
    const int t4 = lane & 3;
    const int wr = wid >> 2;
    const int wc = wid & 3;

    const int m0 = blockIdx.y * 128;
    const int n0 = blockIdx.x * 128;
    const int row = tid >> 1;           // 0..127
    const int half = tid & 1;           // which 16-half chunk pair
    const int Ku4 = K >> 3;

    // each thread loads 2 x uint4 (16 halves) per operand per tile
    const uint4* pA = A + (long)(m0 + row) * Ku4 + half * 2;
    const uint4* pB = B + (long)(n0 + row) * Ku4 + half * 2;

    const uint32_t dA0 = smem_u32(&sA[0][row][half * 16]);
    const uint32_t dB0 = smem_u32(&sB[0][row][half * 16]);
    const uint32_t stg = 128 * 40 * 2;   // bytes per stage

    float acc[4][4][4];
    #pragma unroll
    for (int mt = 0; mt < 4; mt++)
        #pragma unroll
        for (int nt = 0; nt < 4; nt++)
            #pragma unroll
            for (int j = 0; j < 4; j++) acc[mt][nt][j] = 0.f;

    const int NIT = K / 32;
    cpa16(dA0, pA);      cpa16(dA0 + 16, pA + 1);
    cpa16(dB0, pB);      cpa16(dB0 + 16, pB + 1);
    cpa_commit();

    for (int it = 0; it < NIT; it++) {
        if (it + 1 < NIT) {
            uint32_t s = (it + 1) & 1;
            const uint4* nA = pA + (it + 1) * 4;
            const uint4* nB = pB + (it + 1) * 4;
            cpa16(dA0 + s * stg, nA);      cpa16(dA0 + s * stg + 16, nA + 1);
            cpa16(dB0 + s * stg, nB);      cpa16(dB0 + s * stg + 16, nB + 1);
            cpa_commit();
            cpa_wait1();
        } else {
            cpa_wait0();
        }
        __syncthreads();

        const int st = it & 1;
        const uint32_t* sA0 = (const uint32_t*)sA[st];   // row stride 20 u32
        const uint32_t* sB0 = (const uint32_t*)sB[st];

        #pragma unroll
        for (int kk = 0; kk < 2; kk++) {
            const int ko = kk * 8;
            uint32_t bf[4][2];
            #pragma unroll
            for (int nt = 0; nt < 4; nt++) {
                int n = wc * 32 + nt * 8 + g;
                bf[nt][0] = sB0[n * 20 + ko + t4];
                bf[nt][1] = sB0[n * 20 + ko + t4 + 4];
            }
            uint32_t af[4][4];
            #pragma unroll
            for (int mt = 0; mt < 4; mt++) {
                int r0 = (wr * 64 + mt * 16 + g) * 20 + ko;
                int r1 = r0 + 8 * 20;
                af[mt][0] = sA0[r0 + t4];     af[mt][1] = sA0[r1 + t4];
                af[mt][2] = sA0[r0 + t4 + 4]; af[mt][3] = sA0[r1 + t4 + 4];
            }
            #pragma unroll
            for (int mt = 0; mt < 4; mt++)
                #pragma unroll
                for (int nt = 0; nt < 4; nt++)
                    mma16816h(acc[mt][nt], af[mt][0], af[mt][1], af[mt][2], af[mt][3],
                              bf[nt][0], bf[nt][1]);
        }
        __syncthreads();
    }

    #pragma unroll
    for (int mt = 0; mt < 4; mt++) {
        int r = m0 + wr * 64 + mt * 16 + g;
        #pragma unroll
        for (int nt = 0; nt < 4; nt++) {
            int c = n0 + wc * 32 + nt * 8 + 2 * t4;
            float b0 = bias[c], b1 = bias[c + 1];
            *(float2*)&C[(long)r * N + c] =
                make_float2(acc[mt][nt][0] + b0, acc[mt][nt][1] + b1);
            *(float2*)&C[(long)(r + 8) * N + c] =
                make_float2(acc[mt][nt][2] + b0, acc[mt][nt][3] + b1);
        }
    }
}

// ---------------------------------------------------------------------------
// Round Q (pre-scaled) and K to fp16.
// ---------------------------------------------------------------------------
__global__ void __launch_bounds__(256) convert_qk_kernel()
{
    const int idx = blockIdx.x * 256 + threadIdx.x;
    const int row = idx / DIMV;
    const int c   = idx - row * DIMV;
    const int h   = c / PH;
    const int d   = c - h * PH;
    const long base = (long)row * NQKV + h * (3 * PH) + d;

    g_Qh[idx] = __float2half_rn(g_qkv[base] * SCALE);
    g_Kh[idx] = __float2half_rn(g_qkv[base + PH]);
}

// ---------------------------------------------------------------------------
// V -> transposed rounded fp16: g_Vth[bh][d][t]
// ---------------------------------------------------------------------------
__global__ void __launch_bounds__(256) convert_v_kernel()
{
    __shared__ float sv[PH][65];

    const int tb = blockIdx.x;
    const int bh = blockIdx.y;
    const int b = bh >> 4;
    const int h = bh & 15;
    const int tid = threadIdx.x;

    const int tl = tid >> 2;
    const int dp = (tid & 3) * 12;
    const long rbase = (long)(b * TSEQ + tb * 64 + tl) * NQKV + h * (3 * PH) + 2 * PH + dp;
    #pragma unroll
    for (int j = 0; j < 12; j++)
        sv[dp + j][tl] = g_qkv[rbase + j];
    __syncthreads();

    uint32_t* Vh32 = (uint32_t*)g_Vth;
    const long obase = ((long)bh * PH * TSEQ) / 2;
    #pragma unroll
    for (int i = 0; i < 6; i++) {
        int tau = tid + 256 * i;
        int d = tau >> 5;
        int j = tau & 31;
        Vh32[obase + (long)d * (TSEQ / 2) + tb * 32 + j] =
            pkh2(sv[d][2 * j], sv[d][2 * j + 1]);
    }
}

// ---------------------------------------------------------------------------
// Flash attention fp16: Q rounded single / K rounded; P rounded / V rounded.
// cp.async double-buffered; pass-major mma.
// ---------------------------------------------------------------------------
#define SK_ELEMS (64 * 56)                 // 3584
#define STAGE_ELEMS (SK_ELEMS + 48 * 72)   // 7040
#define ATTN_SMEM (2 * STAGE_ELEMS * 2)    // 28160 bytes

__global__ void __launch_bounds__(256, 2) attn_mma_kernel()
{
    extern __shared__ __align__(16) __half dyn[];

    const int tid = threadIdx.x;
    const int wid = tid >> 5;
    const int lane = tid & 31;
    const int g = lane >> 2;
    const int t4 = lane & 3;

    const int bh = blockIdx.y;
    const int b = bh >> 4;
    const int h = bh & 15;
    const int qr0 = blockIdx.x * 128 + wid * 16;
    const long rowg  = (long)b * TSEQ + qr0 + g;
    const long rowg8 = rowg + 8;

    auto load_tile = [&](int kb, int st) {
        __half* base = dyn + st * STAGE_ELEMS;
        #pragma unroll
        for (int i = 0; i < 3; i++) {
            int idx = tid + 256 * i;
            if (idx < 384) {                     // K: 64 rows x 6 chunks
                int key = idx / 6, c = idx - key * 6;
                const __half* src = g_Kh
                    + (long)(b * TSEQ + kb + key) * DIMV + h * PH + c * 8;
                cpa16(smem_u32(base + key * 56 + c * 8), src);
            } else {                             // V: 48 dims x 8 chunks
                int v = idx - 384;
                int d = v >> 3, c = v & 7;
                const __half* src = g_Vth
                    + (long)bh * (PH * TSEQ) + d * TSEQ + kb + c * 8;
                cpa16(smem_u32(base + SK_ELEMS + d * 72 + c * 8), src);
            }
        }
        cpa_commit();
    };

    const uint32_t* Qh32 = (const uint32_t*)g_Qh;
    uint32_t qh[3][4];
    #pragma unroll
    for (int kk = 0; kk < 3; kk++) {
        long o0 = rowg  * 384 + h * 24 + kk * 8 + t4;
        long o1 = rowg8 * 384 + h * 24 + kk * 8 + t4;
        qh[kk][0] = Qh32[o0];     qh[kk][1] = Qh32[o1];
        qh[kk][2] = Qh32[o0 + 4]; qh[kk][3] = Qh32[o1 + 4];
    }

    float O[6][4];
    #pragma unroll
    for (int i = 0; i < 6; i++)
        #pragma unroll
        for (int j = 0; j < 4; j++) O[i][j] = 0.f;
    float m0 = -1e30f, m1 = -1e30f, l0 = 0.f, l1 = 0.f;

    load_tile(0, 0);

    const int NT = TSEQ / 64;
    for (int t = 0; t < NT; t++) {
        if (t + 1 < NT) {
            load_tile((t + 1) * 64, (t + 1) & 1);
            cpa_wait1();
        } else {
            cpa_wait0();
        }
        __syncthreads();

        const int st = t & 1;
        const __half* sK0 = dyn + st * STAGE_ELEMS;
        const __half* sV0 = sK0 + SK_ELEMS;

        float S[8][4];
        #pragma unroll
        for (int n = 0; n < 8; n++)
            #pragma unroll
            for (int j = 0; j < 4; j++) S[n][j] = 0.f;

        // QK^T: single pass (rounded q) x rounded K
        #pragma unroll
        for (int kk = 0; kk < 3; kk++) {
            uint32_t kf[8][2];
            #pragma unroll
            for (int n = 0; n < 8; n++) {
                const uint32_t* kp = (const uint32_t*)(sK0 + (n * 8 + g) * 56 + kk * 16 + 2 * t4);
                kf[n][0] = kp[0]; kf[n][1] = kp[4];
            }
            #pragma unroll
            for (int n = 0; n < 8; n++)
                mma16816h(S[n], qh[kk][0], qh[kk][1], qh[kk][2], qh[kk][3], kf[n][0], kf[n][1]);
        }

        float rmax0 = -1e30f, rmax1 = -1e30f;
        #pragma unroll
        for (int n = 0; n < 8; n++) {
            rmax0 = fmaxf(rmax0, fmaxf(S[n][0], S[n][1]));
            rmax1 = fmaxf(rmax1, fmaxf(S[n][2], S[n][3]));
        }
        rmax0 = fmaxf(rmax0, __shfl_xor_sync(0xffffffffu, rmax0, 1));
        rmax0 = fmaxf(rmax0, __shfl_xor_sync(0xffffffffu, rmax0, 2));
        rmax1 = fmaxf(rmax1, __shfl_xor_sync(0xffffffffu, rmax1, 1));
        rmax1 = fmaxf(rmax1, __shfl_xor_sync(0xffffffffu, rmax1, 2));

        float mn0 = fmaxf(m0, rmax0);
        float mn1 = fmaxf(m1, rmax1);
        float corr0 = __expf(m0 - mn0);
        float corr1 = __expf(m1 - mn1);
        m0 = mn0; m1 = mn1;
        l0 *= corr0; l1 *= corr1;
        #pragma unroll
        for (int nd = 0; nd < 6; nd++) {
            O[nd][0] *= corr0; O[nd][1] *= corr0;
            O[nd][2] *= corr1; O[nd][3] *= corr1;
        }

        float ps0 = 0.f, ps1 = 0.f;
        #pragma unroll
        for (int n = 0; n < 8; n++) {
            S[n][0] = __expf(S[n][0] - m0);
            S[n][1] = __expf(S[n][1] - m0);
            S[n][2] = __expf(S[n][2] - m1);
            S[n][3] = __expf(S[n][3] - m1);
            ps0 += S[n][0] + S[n][1];
            ps1 += S[n][2] + S[n][3];
        }
        ps0 += __shfl_xor_sync(0xffffffffu, ps0, 1);
        ps0 += __shfl_xor_sync(0xffffffffu, ps0, 2);
        ps1 += __shfl_xor_sync(0xffffffffu, ps1, 1);
        ps1 += __shfl_xor_sync(0xffffffffu, ps1, 2);
        l0 += ps0; l1 += ps1;

        // PV: single pass (rounded P) x rounded V
        #pragma unroll
        for (int kk = 0; kk < 4; kk++) {
            uint32_t ph[4];
            #pragma unroll
            for (int half = 0; half < 2; half++) {
                const float* Sc = S[2 * kk + half];
                ph[2 * half + 0] = pkh2(Sc[0], Sc[1]);
                ph[2 * half + 1] = pkh2(Sc[2], Sc[3]);
            }
            uint32_t vf[6][2];
            #pragma unroll
            for (int nd = 0; nd < 6; nd++) {
                const uint32_t* vp = (const uint32_t*)(sV0 + (nd * 8 + g) * 72 + kk * 16 + 2 * t4);
                vf[nd][0] = vp[0]; vf[nd][1] = vp[4];
            }
            #pragma unroll
            for (int nd = 0; nd < 6; nd++)
                mma16816h(O[nd], ph[0], ph[1], ph[2], ph[3], vf[nd][0], vf[nd][1]);
        }
        __syncthreads();
    }

    const float invl0 = 1.0f / l0;
    const float invl1 = 1.0f / l1;
    #pragma unroll
    for (int nd = 0; nd < 6; nd++) {
        long c = h * PH + nd * 8 + 2 * t4;
        g_AttH[(rowg  * DIMV + c) >> 1] =
            pkh2(O[nd][0] * invl0, O[nd][1] * invl0);
        g_AttH[(rowg8 * DIMV + c) >> 1] =
            pkh2(O[nd][2] * invl1, O[nd][3] * invl1);
    }
}

// ---------------------------------------------------------------------------
extern "C" void kernel_launch(void* const* d_in, const int* in_sizes, int n_in,
                              void* d_out, int out_size)
{
    const float* x     = (const float*)d_in[0];
    const float* w_in  = (const float*)d_in[1];
    const float* b_in  = (const float*)d_in[2];
    const float* w_out = (const float*)d_in[3];
    const float* b_out = (const float*)d_in[4];
    float* out = (float*)d_out;

    float* qkv = nullptr;
    cudaGetSymbolAddress((void**)&qkv, g_qkv);
    uint32_t *Xh, *WinTh, *WoutTh, *AttH;
    cudaGetSymbolAddress((void**)&Xh, g_Xh);
    cudaGetSymbolAddress((void**)&WinTh, g_WinTh);
    cudaGetSymbolAddress((void**)&WoutTh, g_WoutTh);
    cudaGetSymbolAddress((void**)&AttH, g_AttH);

    convert_x_kernel<<<(MTOT * DIMV / 2) / 256, 256>>>(x);
    {
        dim3 grid(NQKV / 32, DIMV / 32);
        convert_w_kernel<<<grid, 256>>>(w_in, WinTh, DIMV, NQKV);
    }
    {
        dim3 grid(DIMV / 32, DIMV / 32);
        convert_w_kernel<<<grid, 256>>>(w_out, WoutTh, DIMV, DIMV);
    }

    // QKV projection (fp16, BK=32)
    {
        dim3 grid(NQKV / 128, MTOT / 128);
        gemm_tc_kernel<<<grid, 256>>>((const uint4*)Xh, (const uint4*)WinTh,
                                      b_in, qkv, MTOT, NQKV, DIMV);
    }

    convert_qk_kernel<<<(MTOT * DIMV) / 256, 256>>>();
    {
        dim3 grid(TSEQ / 64, 64);
        convert_v_kernel<<<grid, 256>>>();
    }

    // Attention (QK x1, PV x1)
    {
        dim3 grid(TSEQ / 128, 64);
        attn_mma_kernel<<<grid, 256, ATTN_SMEM>>>();
    }

    // Output projection (fp16, BK=32)
    {
        dim3 grid(DIMV / 128, MTOT / 128);
        gemm_tc_kernel<<<grid, 256>>>((const uint4*)AttH, (const uint4*)WoutTh,
                                      b_out, out, MTOT, DIMV, DIMV);
    }
}

// round 15
// speedup vs baseline: 6.9092x; 1.0840x over previous
#include <cuda_runtime.h>
#include <cuda_fp16.h>
#include <cstdint>

#define DIMV 768
#define NHEAD 16
#define PH 48
#define BATCH 4
#define TSEQ 2048
#define MTOT (BATCH * TSEQ)   // 8192
#define NQKV (3 * DIMV)       // 2304
#define SCALE 0.14433756729740643f   // 1/sqrt(48)

// Scratch (allocation-free rule: __device__ globals)
__device__ uint32_t g_Xh[MTOT * DIMV / 2];       // x rounded fp16 (packed pairs)
__device__ uint32_t g_WinTh[NQKV * DIMV / 2];    // w_in^T rounded fp16
__device__ uint32_t g_WoutTh[DIMV * DIMV / 2];   // w_out^T rounded fp16
__device__ uint32_t g_AttH[MTOT * DIMV / 2];     // attn out rounded fp16
__device__ __half g_Qh[MTOT * DIMV];             // q*scale rounded
__device__ __half g_Kh[MTOT * DIMV];             // k rounded
__device__ __half g_Vth[64 * PH * TSEQ];         // v transposed rounded [bh][d][t]

// ---- fp16 helpers ----
__device__ __forceinline__ uint32_t pkh2(float lo, float hi) {
    uint32_t r;
    asm("cvt.rn.f16x2.f32 %0, %1, %2;" : "=r"(r) : "f"(hi), "f"(lo));
    return r;
}

// ---- fp16 m16n8k16 mma, fp32 accum ----
__device__ __forceinline__ void mma16816h(float* c, uint32_t a0, uint32_t a1,
                                          uint32_t a2, uint32_t a3,
                                          uint32_t b0, uint32_t b1) {
    asm volatile(
        "mma.sync.aligned.m16n8k16.row.col.f32.f16.f16.f32 "
        "{%0,%1,%2,%3},{%4,%5,%6,%7},{%8,%9},{%0,%1,%2,%3};"
        : "+f"(c[0]), "+f"(c[1]), "+f"(c[2]), "+f"(c[3])
        : "r"(a0), "r"(a1), "r"(a2), "r"(a3), "r"(b0), "r"(b1));
}

// ---- cp.async ----
__device__ __forceinline__ void cpa16(uint32_t dst_smem, const void* src) {
    asm volatile("cp.async.cg.shared.global [%0], [%1], 16;"
                 :: "r"(dst_smem), "l"(src));
}
__device__ __forceinline__ void cpa_commit() {
    asm volatile("cp.async.commit_group;");
}
__device__ __forceinline__ void cpa_wait1() {
    asm volatile("cp.async.wait_group 1;");
}
__device__ __forceinline__ void cpa_wait0() {
    asm volatile("cp.async.wait_group 0;");
}
__device__ __forceinline__ uint32_t smem_u32(const void* p) {
    return (uint32_t)__cvta_generic_to_shared(p);
}

// ---------------------------------------------------------------------------
// x -> rounded fp16 pairs
// ---------------------------------------------------------------------------
__global__ void __launch_bounds__(256) convert_x_kernel(const float* __restrict__ x)
{
    const long i = (long)blockIdx.x * 256 + threadIdx.x;
    float2 v = ((const float2*)x)[i];
    g_Xh[i] = pkh2(v.x, v.y);
}

// ---------------------------------------------------------------------------
// Transpose + ROUND weights: W[K][N] fp32 -> Wt[N][K] fp16 pairs
// ---------------------------------------------------------------------------
__global__ void __launch_bounds__(256) convert_w_kernel(
    const float* __restrict__ W, uint32_t* __restrict__ WtH, int K, int N)
{
    __shared__ float sT[32][33];
    const int k0 = blockIdx.y * 32, n0 = blockIdx.x * 32;
    const int tid = threadIdx.x;
    const int tx = tid & 31, ty = tid >> 5;
    #pragma unroll
    for (int i = 0; i < 4; i++)
        sT[ty + i * 8][tx] = W[(long)(k0 + ty + i * 8) * N + n0 + tx];
    __syncthreads();

    const int nr = tid >> 3;
    const int kc = tid & 7;
    #pragma unroll
    for (int i = 0; i < 2; i++) {
        int kk = kc + i * 8;
        long o = (long)(n0 + nr) * (K / 2) + k0 / 2 + kk;
        WtH[o] = pkh2(sT[2 * kk][nr], sT[2 * kk + 1][nr]);
    }
}

// ===========================================================================
// Shared GEMM mainloop macro-structure (BK=32, cp.async double-buffered).
// Two kernels differ only in epilogue: fused-QKV vs plain fp32+bias.
// ===========================================================================

// ---------------------------------------------------------------------------
// QKV GEMM with FUSED epilogue: writes g_Qh (scaled), g_Kh, g_Vth (transposed)
// directly as rounded fp16. A = x fp16, B = w_in^T fp16, bias = b_in.
// M=8192, N=2304, K=768.
// ---------------------------------------------------------------------------
__global__ void __launch_bounds__(256, 2) gemm_qkv_fused_kernel(
    const uint4* __restrict__ A, const uint4* __restrict__ B,
    const float* __restrict__ bias)
{
    const int M = MTOT, N = NQKV, K = DIMV;
    __shared__ __align__(16) __half sA[2][128][40];
    __shared__ __align__(16) __half sB[2][128][40];

    const int tid = threadIdx.x;
    const int wid = tid >> 5;
    const int lane = tid & 31;
    const int g = lane >> 2;
    const int t4 = lane & 3;
    const int wr = wid >> 2;
    const int wc = wid & 3;

    const int m0 = blockIdx.y * 128;
    const int n0 = blockIdx.x * 128;
    const int row = tid >> 1;
    const int half = tid & 1;
    const int Ku4 = K >> 3;

    const uint4* pA = A + (long)(m0 + row) * Ku4 + half * 2;
    const uint4* pB = B + (long)(n0 + row) * Ku4 + half * 2;

    const uint32_t dA0 = smem_u32(&sA[0][row][half * 16]);
    const uint32_t dB0 = smem_u32(&sB[0][row][half * 16]);
    const uint32_t stg = 128 * 40 * 2;

    float acc[4][4][4];
    #pragma unroll
    for (int mt = 0; mt < 4; mt++)
        #pragma unroll
        for (int nt = 0; nt < 4; nt++)
            #pragma unroll
            for (int j = 0; j < 4; j++) acc[mt][nt][j] = 0.f;

    const int NIT = K / 32;
    cpa16(dA0, pA);      cpa16(dA0 + 16, pA + 1);
    cpa16(dB0, pB);      cpa16(dB0 + 16, pB + 1);
    cpa_commit();

    for (int it = 0; it < NIT; it++) {
        if (it + 1 < NIT) {
            uint32_t s = (it + 1) & 1;
            const uint4* nA = pA + (it + 1) * 4;
            const uint4* nB = pB + (it + 1) * 4;
            cpa16(dA0 + s * stg, nA);      cpa16(dA0 + s * stg + 16, nA + 1);
            cpa16(dB0 + s * stg, nB);      cpa16(dB0 + s * stg + 16, nB + 1);
            cpa_commit();
            cpa_wait1();
        } else {
            cpa_wait0();
        }
        __syncthreads();

        const int st = it & 1;
        const uint32_t* sA0 = (const uint32_t*)sA[st];
        const uint32_t* sB0 = (const uint32_t*)sB[st];

        #pragma unroll
        for (int kk = 0; kk < 2; kk++) {
            const int ko = kk * 8;
            uint32_t bf[4][2];
            #pragma unroll
            for (int nt = 0; nt < 4; nt++) {
                int n = wc * 32 + nt * 8 + g;
                bf[nt][0] = sB0[n * 20 + ko + t4];
                bf[nt][1] = sB0[n * 20 + ko + t4 + 4];
            }
            uint32_t af[4][4];
            #pragma unroll
            for (int mt = 0; mt < 4; mt++) {
                int r0 = (wr * 64 + mt * 16 + g) * 20 + ko;
                int r1 = r0 + 8 * 20;
                af[mt][0] = sA0[r0 + t4];     af[mt][1] = sA0[r1 + t4];
                af[mt][2] = sA0[r0 + t4 + 4]; af[mt][3] = sA0[r1 + t4 + 4];
            }
            #pragma unroll
            for (int mt = 0; mt < 4; mt++)
                #pragma unroll
                for (int nt = 0; nt < 4; nt++)
                    mma16816h(acc[mt][nt], af[mt][0], af[mt][1], af[mt][2], af[mt][3],
                              bf[nt][0], bf[nt][1]);
        }
        __syncthreads();
    }

    // Fused epilogue: route each column pair to Q / K / V-transposed fp16.
    uint32_t* Qh32 = (uint32_t*)g_Qh;
    uint32_t* Kh32 = (uint32_t*)g_Kh;
    #pragma unroll
    for (int mt = 0; mt < 4; mt++) {
        const int r = m0 + wr * 64 + mt * 16 + g;   // r+8 is the second row
        #pragma unroll
        for (int nt = 0; nt < 4; nt++) {
            const int c = n0 + wc * 32 + nt * 8 + 2 * t4;
            const float b0 = bias[c], b1 = bias[c + 1];
            const int h  = c / 144;
            const int rr = c - h * 144;
            float v00 = acc[mt][nt][0] + b0, v01 = acc[mt][nt][1] + b1;
            float v10 = acc[mt][nt][2] + b0, v11 = acc[mt][nt][3] + b1;
            if (rr < 48) {
                Qh32[((long)r * DIMV + h * PH + rr) >> 1] =
                    pkh2(v00 * SCALE, v01 * SCALE);
                Qh32[((long)(r + 8) * DIMV + h * PH + rr) >> 1] =
                    pkh2(v10 * SCALE, v11 * SCALE);
            } else if (rr < 96) {
                const int d = rr - 48;
                Kh32[((long)r * DIMV + h * PH + d) >> 1] = pkh2(v00, v01);
                Kh32[((long)(r + 8) * DIMV + h * PH + d) >> 1] = pkh2(v10, v11);
            } else {
                const int d = rr - 96;
                const int bb = r >> 11;           // batch (2048 rows each)
                const int t  = r & 2047;
                const long vb = ((long)(bb * NHEAD + h) * PH + d) * TSEQ + t;
                g_Vth[vb]            = __float2half_rn(v00);
                g_Vth[vb + TSEQ]     = __float2half_rn(v01);
                g_Vth[vb + 8]        = __float2half_rn(v10);
                g_Vth[vb + TSEQ + 8] = __float2half_rn(v11);
            }
        }
    }
}

// ---------------------------------------------------------------------------
// Generic tensor-core GEMM fp16 (BK=32): C = A Bt^T + bias (fp32 out).
// Used for the output projection only.
// ---------------------------------------------------------------------------
__global__ void __launch_bounds__(256, 2) gemm_tc_kernel(
    const uint4* __restrict__ A, const uint4* __restrict__ B,
    const float* __restrict__ bias, float* __restrict__ C,
    int M, int N, int K)
{
    __shared__ __align__(16) __half sA[2][128][40];
    __shared__ __align__(16) __half sB[2][128][40];

    const int tid = threadIdx.x;
    const int wid = tid >> 5;
    const int lane = tid & 31;
    const int g = lane >> 2;
    const int t4 = lane & 3;
    const int wr = wid >> 2;
    const int wc = wid & 3;

    const int m0 = blockIdx.y * 128;
    const int n0 = blockIdx.x * 128;
    const int row = tid >> 1;
    const int half = tid & 1;
    const int Ku4 = K >> 3;

    const uint4* pA = A + (long)(m0 + row) * Ku4 + half * 2;
    const uint4* pB = B + (long)(n0 + row) * Ku4 + half * 2;

    const uint32_t dA0 = smem_u32(&sA[0][row][half * 16]);
    const uint32_t dB0 = smem_u32(&sB[0][row][half * 16]);
    const uint32_t stg = 128 * 40 * 2;

    float acc[4][4][4];
    #pragma unroll
    for (int mt = 0; mt < 4; mt++)
        #pragma unroll
        for (int nt = 0; nt < 4; nt++)
            #pragma unroll
            for (int j = 0; j < 4; j++) acc[mt][nt][j] = 0.f;

    const int NIT = K / 32;
    cpa16(dA0, pA);      cpa16(dA0 + 16, pA + 1);
    cpa16(dB0, pB);      cpa16(dB0 + 16, pB + 1);
    cpa_commit();

    for (int it = 0; it < NIT; it++) {
        if (it + 1 < NIT) {
            uint32_t s = (it + 1) & 1;
            const uint4* nA = pA + (it + 1) * 4;
            const uint4* nB = pB + (it + 1) * 4;
            cpa16(dA0 + s * stg, nA);      cpa16(dA0 + s * stg + 16, nA + 1);
            cpa16(dB0 + s * stg, nB);      cpa16(dB0 + s * stg + 16, nB + 1);
            cpa_commit();
            cpa_wait1();
        } else {
            cpa_wait0();
        }
        __syncthreads();

        const int st = it & 1;
        const uint32_t* sA0 = (const uint32_t*)sA[st];
        const uint32_t* sB0 = (const uint32_t*)sB[st];

        #pragma unroll
        for (int kk = 0; kk < 2; kk++) {
            const int ko = kk * 8;
            uint32_t bf[4][2];
            #pragma unroll
            for (int nt = 0; nt < 4; nt++) {
                int n = wc * 32 + nt * 8 + g;
                bf[nt][0] = sB0[n * 20 + ko + t4];
                bf[nt][1] = sB0[n * 20 + ko + t4 + 4];
            }
            uint32_t af[4][4];
            #pragma unroll
            for (int mt = 0; mt < 4; mt++) {
                int r0 = (wr * 64 + mt * 16 + g) * 20 + ko;
                int r1 = r0 + 8 * 20;
                af[mt][0] = sA0[r0 + t4];     af[mt][1] = sA0[r1 + t4];
                af[mt][2] = sA0[r0 + t4 + 4]; af[mt][3] = sA0[r1 + t4 + 4];
            }
            #pragma unroll
            for (int mt = 0; mt < 4; mt++)
                #pragma unroll
                for (int nt = 0; nt < 4; nt++)
                    mma16816h(acc[mt][nt], af[mt][0], af[mt][1], af[mt][2], af[mt][3],
                              bf[nt][0], bf[nt][1]);
        }
        __syncthreads();
    }

    #pragma unroll
    for (int mt = 0; mt < 4; mt++) {
        int r = m0 + wr * 64 + mt * 16 + g;
        #pragma unroll
        for (int nt = 0; nt < 4; nt++) {
            int c = n0 + wc * 32 + nt * 8 + 2 * t4;
            float b0 = bias[c], b1 = bias[c + 1];
            *(float2*)&C[(long)r * N + c] =
                make_float2(acc[mt][nt][0] + b0, acc[mt][nt][1] + b1);
            *(float2*)&C[(long)(r + 8) * N + c] =
                make_float2(acc[mt][nt][2] + b0, acc[mt][nt][3] + b1);
        }
    }
}

// ---------------------------------------------------------------------------
// Flash attention fp16 (unchanged from R14): rounded Q/K/P/V single passes.
// ---------------------------------------------------------------------------
#define SK_ELEMS (64 * 56)                 // 3584
#define STAGE_ELEMS (SK_ELEMS + 48 * 72)   // 7040
#define ATTN_SMEM (2 * STAGE_ELEMS * 2)    // 28160 bytes

__global__ void __launch_bounds__(256, 2) attn_mma_kernel()
{
    extern __shared__ __align__(16) __half dyn[];

    const int tid = threadIdx.x;
    const int wid = tid >> 5;
    const int lane = tid & 31;
    const int g = lane >> 2;
    const int t4 = lane & 3;

    const int bh = blockIdx.y;
    const int b = bh >> 4;
    const int h = bh & 15;
    const int qr0 = blockIdx.x * 128 + wid * 16;
    const long rowg  = (long)b * TSEQ + qr0 + g;
    const long rowg8 = rowg + 8;

    auto load_tile = [&](int kb, int st) {
        __half* base = dyn + st * STAGE_ELEMS;
        #pragma unroll
        for (int i = 0; i < 3; i++) {
            int idx = tid + 256 * i;
            if (idx < 384) {                     // K: 64 rows x 6 chunks
                int key = idx / 6, c = idx - key * 6;
                const __half* src = g_Kh
                    + (long)(b * TSEQ + kb + key) * DIMV + h * PH + c * 8;
                cpa16(smem_u32(base + key * 56 + c * 8), src);
            } else {                             // V: 48 dims x 8 chunks
                int v = idx - 384;
                int d = v >> 3, c = v & 7;
                const __half* src = g_Vth
                    + (long)bh * (PH * TSEQ) + d * TSEQ + kb + c * 8;
                cpa16(smem_u32(base + SK_ELEMS + d * 72 + c * 8), src);
            }
        }
        cpa_commit();
    };

    const uint32_t* Qh32 = (const uint32_t*)g_Qh;
    uint32_t qh[3][4];
    #pragma unroll
    for (int kk = 0; kk < 3; kk++) {
        long o0 = rowg  * 384 + h * 24 + kk * 8 + t4;
        long o1 = rowg8 * 384 + h * 24 + kk * 8 + t4;
        qh[kk][0] = Qh32[o0];     qh[kk][1] = Qh32[o1];
        qh[kk][2] = Qh32[o0 + 4]; qh[kk][3] = Qh32[o1 + 4];
    }

    float O[6][4];
    #pragma unroll
    for (int i = 0; i < 6; i++)
        #pragma unroll
        for (int j = 0; j < 4; j++) O[i][j] = 0.f;
    float m0 = -1e30f, m1 = -1e30f, l0 = 0.f, l1 = 0.f;

    load_tile(0, 0);

    const int NT = TSEQ / 64;
    for (int t = 0; t < NT; t++) {
        if (t + 1 < NT) {
            load_tile((t + 1) * 64, (t + 1) & 1);
            cpa_wait1();
        } else {
            cpa_wait0();
        }
        __syncthreads();

        const int st = t & 1;
        const __half* sK0 = dyn + st * STAGE_ELEMS;
        const __half* sV0 = sK0 + SK_ELEMS;

        float S[8][4];
        #pragma unroll
        for (int n = 0; n < 8; n++)
            #pragma unroll
            for (int j = 0; j < 4; j++) S[n][j] = 0.f;

        #pragma unroll
        for (int kk = 0; kk < 3; kk++) {
            uint32_t kf[8][2];
            #pragma unroll
            for (int n = 0; n < 8; n++) {
                const uint32_t* kp = (const uint32_t*)(sK0 + (n * 8 + g) * 56 + kk * 16 + 2 * t4);
                kf[n][0] = kp[0]; kf[n][1] = kp[4];
            }
            #pragma unroll
            for (int n = 0; n < 8; n++)
                mma16816h(S[n], qh[kk][0], qh[kk][1], qh[kk][2], qh[kk][3], kf[n][0], kf[n][1]);
        }

        float rmax0 = -1e30f, rmax1 = -1e30f;
        #pragma unroll
        for (int n = 0; n < 8; n++) {
            rmax0 = fmaxf(rmax0, fmaxf(S[n][0], S[n][1]));
            rmax1 = fmaxf(rmax1, fmaxf(S[n][2], S[n][3]));
        }
        rmax0 = fmaxf(rmax0, __shfl_xor_sync(0xffffffffu, rmax0, 1));
        rmax0 = fmaxf(rmax0, __shfl_xor_sync(0xffffffffu, rmax0, 2));
        rmax1 = fmaxf(rmax1, __shfl_xor_sync(0xffffffffu, rmax1, 1));
        rmax1 = fmaxf(rmax1, __shfl_xor_sync(0xffffffffu, rmax1, 2));

        float mn0 = fmaxf(m0, rmax0);
        float mn1 = fmaxf(m1, rmax1);
        float corr0 = __expf(m0 - mn0);
        float corr1 = __expf(m1 - mn1);
        m0 = mn0; m1 = mn1;
        l0 *= corr0; l1 *= corr1;
        #pragma unroll
        for (int nd = 0; nd < 6; nd++) {
            O[nd][0] *= corr0; O[nd][1] *= corr0;
            O[nd][2] *= corr1; O[nd][3] *= corr1;
        }

        float ps0 = 0.f, ps1 = 0.f;
        #pragma unroll
        for (int n = 0; n < 8; n++) {
            S[n][0] = __expf(S[n][0] - m0);
            S[n][1] = __expf(S[n][1] - m0);
            S[n][2] = __expf(S[n][2] - m1);
            S[n][3] = __expf(S[n][3] - m1);
            ps0 += S[n][0] + S[n][1];
            ps1 += S[n][2] + S[n][3];
        }
        ps0 += __shfl_xor_sync(0xffffffffu, ps0, 1);
        ps0 += __shfl_xor_sync(0xffffffffu, ps0, 2);
        ps1 += __shfl_xor_sync(0xffffffffu, ps1, 1);
        ps1 += __shfl_xor_sync(0xffffffffu, ps1, 2);
        l0 += ps0; l1 += ps1;

        #pragma unroll
        for (int kk = 0; kk < 4; kk++) {
            uint32_t ph[4];
            #pragma unroll
            for (int half = 0; half < 2; half++) {
                const float* Sc = S[2 * kk + half];
                ph[2 * half + 0] = pkh2(Sc[0], Sc[1]);
                ph[2 * half + 1] = pkh2(Sc[2], Sc[3]);
            }
            uint32_t vf[6][2];
            #pragma unroll
            for (int nd = 0; nd < 6; nd++) {
                const uint32_t* vp = (const uint32_t*)(sV0 + (nd * 8 + g) * 72 + kk * 16 + 2 * t4);
                vf[nd][0] = vp[0]; vf[nd][1] = vp[4];
            }
            #pragma unroll
            for (int nd = 0; nd < 6; nd++)
                mma16816h(O[nd], ph[0], ph[1], ph[2], ph[3], vf[nd][0], vf[nd][1]);
        }
        __syncthreads();
    }

    const float invl0 = 1.0f / l0;
    const float invl1 = 1.0f / l1;
    #pragma unroll
    for (int nd = 0; nd < 6; nd++) {
        long c = h * PH + nd * 8 + 2 * t4;
        g_AttH[(rowg  * DIMV + c) >> 1] =
            pkh2(O[nd][0] * invl0, O[nd][1] * invl0);
        g_AttH[(rowg8 * DIMV + c) >> 1] =
            pkh2(O[nd][2] * invl1, O[nd][3] * invl1);
    }
}

// ---------------------------------------------------------------------------
extern "C" void kernel_launch(void* const* d_in, const int* in_sizes, int n_in,
                              void* d_out, int out_size)
{
    const float* x     = (const float*)d_in[0];
    const float* w_in  = (const float*)d_in[1];
    const float* b_in  = (const float*)d_in[2];
    const float* w_out = (const float*)d_in[3];
    const float* b_out = (const float*)d_in[4];
    float* out = (float*)d_out;

    uint32_t *Xh, *WinTh, *WoutTh, *AttH;
    cudaGetSymbolAddress((void**)&Xh, g_Xh);
    cudaGetSymbolAddress((void**)&WinTh, g_WinTh);
    cudaGetSymbolAddress((void**)&WoutTh, g_WoutTh);
    cudaGetSymbolAddress((void**)&AttH, g_AttH);

    convert_x_kernel<<<(MTOT * DIMV / 2) / 256, 256>>>(x);
    {
        dim3 grid(NQKV / 32, DIMV / 32);
        convert_w_kernel<<<grid, 256>>>(w_in, WinTh, DIMV, NQKV);
    }
    {
        dim3 grid(DIMV / 32, DIMV / 32);
        convert_w_kernel<<<grid, 256>>>(w_out, WoutTh, DIMV, DIMV);
    }

    // QKV projection with fused fp16 Q/K/V-transpose epilogue
    {
        dim3 grid(NQKV / 128, MTOT / 128);
        gemm_qkv_fused_kernel<<<grid, 256>>>((const uint4*)Xh,
                                             (const uint4*)WinTh, b_in);
    }

    // Attention (QK x1, PV x1)
    {
        dim3 grid(TSEQ / 128, 64);
        attn_mma_kernel<<<grid, 256, ATTN_SMEM>>>();
    }

    // Output projection (fp16, BK=32) -> fp32 d_out
    {
        dim3 grid(DIMV / 128, MTOT / 128);
        gemm_tc_kernel<<<grid, 256>>>((const uint4*)AttH, (const uint4*)WoutTh,
                                      b_out, out, MTOT, DIMV, DIMV);
    }
}